// round 1
// baseline (speedup 1.0000x reference)
#include <cuda_runtime.h>
#include <cuda_bf16.h>
#include <math.h>

// ---------------- problem constants ----------------
#define BATCH   8
#define SEQ     2048
#define D_IN    64
#define DM      1024          // d_model == P
#define NL      4
#define MROWS   (BATCH*SEQ)   // 16384

// ---------------- scratch (device globals; no allocation allowed) ------------
__device__ float g_h  [(size_t)MROWS * DM];       // 64 MB
__device__ float g_fx [(size_t)MROWS * DM];
__device__ float g_fy [(size_t)MROWS * DM];
__device__ float g_z  [(size_t)MROWS * DM];
__device__ float g_z2 [(size_t)MROWS * DM];
__device__ float g_gg [(size_t)MROWS * DM];
__device__ float g_bu [(size_t)MROWS * 2 * DM];   // 128 MB (interleaved re/im; scan in-place)
__device__ float g_u2 [(size_t)MROWS * 2 * DM];   // 128 MB
__device__ float g_W2 [(size_t)2 * DM * DM];      // [2P, H] interleaved B_bar rows
__device__ float g_Cw [(size_t)DM * 2 * DM];      // [H, 2P] interleaved C weight
__device__ float2 g_lamb[DM];
__device__ float2 g_coef[DM];
__device__ float g_pooled[BATCH * DM];

// ---------------- helpers ----------------
__device__ __forceinline__ float gelu_f(float x) {
    return 0.5f * x * (1.0f + erff(x * 0.70710678118654752f));
}

// ---------------- per-layer weight prep ----------------
__global__ void prep_lamb_k(const float* __restrict__ lam_re,
                            const float* __restrict__ lam_im,
                            const float* __restrict__ log_step) {
    int p = blockIdx.x * blockDim.x + threadIdx.x;
    if (p >= DM) return;
    float dt = expf(log_step[p]);
    float lr = lam_re[p], li = lam_im[p];
    float er = expf(lr * dt);
    float2 lb = make_float2(er * cosf(li * dt), er * sinf(li * dt));
    g_lamb[p] = lb;
    // coef = (lam_bar - 1) / lam
    float nr = lb.x - 1.0f, ni = lb.y;
    float den = lr * lr + li * li;
    g_coef[p] = make_float2((nr * lr + ni * li) / den, (ni * lr - nr * li) / den);
}

__global__ void prep_W2_k(const float* __restrict__ b_re,
                          const float* __restrict__ b_im) {
    size_t idx = (size_t)blockIdx.x * blockDim.x + threadIdx.x;   // P*H
    if (idx >= (size_t)DM * DM) return;
    int p = (int)(idx / DM), h = (int)(idx % DM);
    float2 c = g_coef[p];
    float br = b_re[idx], bi = b_im[idx];
    g_W2[(size_t)(2 * p)     * DM + h] = c.x * br - c.y * bi;   // re row
    g_W2[(size_t)(2 * p + 1) * DM + h] = c.x * bi + c.y * br;   // im row
}

__global__ void prep_Cw_k(const float* __restrict__ c_re,
                          const float* __restrict__ c_im) {
    size_t idx = (size_t)blockIdx.x * blockDim.x + threadIdx.x;   // H*P
    if (idx >= (size_t)DM * DM) return;
    int h = (int)(idx / DM), p = (int)(idx % DM);
    g_Cw[(size_t)h * (2 * DM) + 2 * p]     =  c_re[idx];
    g_Cw[(size_t)h * (2 * DM) + 2 * p + 1] = -c_im[idx];
}

// ---------------- SGEMM 128x128x8, fused epilogues ----------------
// EPI 0: plain, 1: +bias(e0[n]), 2: gelu(acc + e1[c]*e0[m,c]) + e0[m,c], 3: acc + e0[m,c]
#define TBM 128
#define TBN 128
#define TBK 8

template <bool TRANSB, int EPI>
__global__ void __launch_bounds__(256)
sgemm_k(const float* __restrict__ A, const float* __restrict__ B,
        float* __restrict__ C, int M, int N, int K,
        const float* __restrict__ e0, const float* __restrict__ e1) {
    __shared__ float As[TBK][TBM + 4];
    __shared__ float Bs[TBK][TBN + 4];
    const int tid = threadIdx.x;
    const int bm = blockIdx.y * TBM;
    const int bn = blockIdx.x * TBN;

    const int arow = tid >> 1;
    const int akc  = (tid & 1) * 4;
    const float* Aptr = A + (size_t)(bm + arow) * K + akc;

    const float* Bptr;
    int br0, bc0;
    if (!TRANSB) {                     // B is [K, N]
        br0 = tid >> 5;                // k row in tile
        bc0 = (tid & 31) * 4;          // n col in tile
        Bptr = B + (size_t)br0 * N + bn + bc0;
    } else {                           // B is [N, K]
        br0 = (tid & 1) * 4;           // k in tile
        bc0 = tid >> 1;                // n in tile
        Bptr = B + (size_t)(bn + bc0) * K + br0;
    }

    float acc[8][8];
#pragma unroll
    for (int i = 0; i < 8; i++)
#pragma unroll
        for (int j = 0; j < 8; j++) acc[i][j] = 0.0f;

    float4 aR = *reinterpret_cast<const float4*>(Aptr);
    float4 bR = *reinterpret_cast<const float4*>(Bptr);

    const int tm = tid >> 4;
    const int tn = tid & 15;

    for (int k0 = 0;;) {
        As[akc + 0][arow] = aR.x;
        As[akc + 1][arow] = aR.y;
        As[akc + 2][arow] = aR.z;
        As[akc + 3][arow] = aR.w;
        if (!TRANSB) {
            Bs[br0][bc0 + 0] = bR.x;
            Bs[br0][bc0 + 1] = bR.y;
            Bs[br0][bc0 + 2] = bR.z;
            Bs[br0][bc0 + 3] = bR.w;
        } else {
            Bs[br0 + 0][bc0] = bR.x;
            Bs[br0 + 1][bc0] = bR.y;
            Bs[br0 + 2][bc0] = bR.z;
            Bs[br0 + 3][bc0] = bR.w;
        }
        __syncthreads();
        k0 += TBK;
        bool more = (k0 < K);
        if (more) {
            aR = *reinterpret_cast<const float4*>(Aptr + k0);
            if (!TRANSB)
                bR = *reinterpret_cast<const float4*>(Bptr + (size_t)k0 * N);
            else
                bR = *reinterpret_cast<const float4*>(Bptr + k0);
        }
#pragma unroll
        for (int kk = 0; kk < TBK; kk++) {
            float4 a0 = *reinterpret_cast<const float4*>(&As[kk][tm * 4]);
            float4 a1 = *reinterpret_cast<const float4*>(&As[kk][64 + tm * 4]);
            float4 b0 = *reinterpret_cast<const float4*>(&Bs[kk][tn * 4]);
            float4 b1 = *reinterpret_cast<const float4*>(&Bs[kk][64 + tn * 4]);
            float av[8] = {a0.x, a0.y, a0.z, a0.w, a1.x, a1.y, a1.z, a1.w};
            float bv[8] = {b0.x, b0.y, b0.z, b0.w, b1.x, b1.y, b1.z, b1.w};
#pragma unroll
            for (int i = 0; i < 8; i++)
#pragma unroll
                for (int j = 0; j < 8; j++)
                    acc[i][j] = fmaf(av[i], bv[j], acc[i][j]);
        }
        __syncthreads();
        if (!more) break;
    }

#pragma unroll
    for (int i = 0; i < 8; i++) {
        int r = bm + ((i < 4) ? (tm * 4 + i) : (64 + tm * 4 + i - 4));
        size_t rowoff = (size_t)r * N;
#pragma unroll
        for (int j = 0; j < 8; j++) {
            int c = bn + ((j < 4) ? (tn * 4 + j) : (64 + tn * 4 + j - 4));
            float val = acc[i][j];
            if (EPI == 1) {
                val += e0[c];
            } else if (EPI == 2) {
                float f = e0[rowoff + c];
                val = gelu_f(val + e1[c] * f) + f;
            } else if (EPI == 3) {
                val += e0[rowoff + c];
            }
            C[rowoff + c] = val;
        }
    }
}

// ---------------- sequential complex scan (in-place, prefetched) -------------
__global__ void scan_k(float2* __restrict__ bu) {
    int idx = blockIdx.x * blockDim.x + threadIdx.x;   // 8192 channels
    if (idx >= BATCH * DM) return;
    int b = idx >> 10, p = idx & (DM - 1);
    float2 a = g_lamb[p];
    float2* ptr = bu + (size_t)b * SEQ * DM + p;
    float xr = 0.0f, xi = 0.0f;
    const int U = 8;
    float2 cur[U], nxt[U];
#pragma unroll
    for (int i = 0; i < U; i++) cur[i] = ptr[(size_t)i * DM];
#pragma unroll
    for (int i = 0; i < U; i++) nxt[i] = make_float2(0.f, 0.f);
    for (int l0 = 0; l0 < SEQ; l0 += U) {
        if (l0 + U < SEQ) {
#pragma unroll
            for (int i = 0; i < U; i++) nxt[i] = ptr[(size_t)(l0 + U + i) * DM];
        }
#pragma unroll
        for (int i = 0; i < U; i++) {
            float ur = cur[i].x, ui = cur[i].y;
            float nr = fmaf(a.x, xr, fmaf(-a.y, xi, ur));
            float ni = fmaf(a.x, xi, fmaf(a.y, xr, ui));
            xr = nr; xi = ni;
            ptr[(size_t)(l0 + i) * DM] = make_float2(xr, xi);
        }
#pragma unroll
        for (int i = 0; i < U; i++) cur[i] = nxt[i];
    }
}

// ---------------- LayerNorm (optionally fused residual add) ------------------
__global__ void __launch_bounds__(128)
ln_k(const float* __restrict__ in, const float* __restrict__ add,
     float* __restrict__ out, const float* __restrict__ g,
     const float* __restrict__ bb) {
    __shared__ float red[8];
    size_t base = (size_t)blockIdx.x * DM;
    int t = threadIdx.x;
    float v[8];
    float s = 0.0f;
#pragma unroll
    for (int i = 0; i < 8; i++) {
        float xv = in[base + t + i * 128];
        if (add) xv += add[base + t + i * 128];
        v[i] = xv;
        s += xv;
    }
#pragma unroll
    for (int o = 16; o > 0; o >>= 1) s += __shfl_xor_sync(0xffffffffu, s, o);
    if ((t & 31) == 0) red[t >> 5] = s;
    __syncthreads();
    float mean = (red[0] + red[1] + red[2] + red[3]) * (1.0f / DM);
    float s2 = 0.0f;
#pragma unroll
    for (int i = 0; i < 8; i++) { float d = v[i] - mean; s2 += d * d; }
#pragma unroll
    for (int o = 16; o > 0; o >>= 1) s2 += __shfl_xor_sync(0xffffffffu, s2, o);
    if ((t & 31) == 0) red[4 + (t >> 5)] = s2;
    __syncthreads();
    float var = (red[4] + red[5] + red[6] + red[7]) * (1.0f / DM);
    float inv = rsqrtf(var + 1e-5f);
#pragma unroll
    for (int i = 0; i < 8; i++) {
        int c = t + i * 128;
        out[base + c] = (v[i] - mean) * inv * g[c] + bb[c];
    }
}

// ---------------- GEGLU ----------------
__global__ void geglu_k(const float* __restrict__ u2, float* __restrict__ out) {
    size_t i = (size_t)blockIdx.x * blockDim.x + threadIdx.x;
    if (i >= (size_t)MROWS * DM) return;
    size_t m = i >> 10;
    int c = (int)(i & (DM - 1));
    float a = u2[m * (2 * DM) + c];
    float gg = u2[m * (2 * DM) + DM + c];
    out[i] = a * gelu_f(gg);
}

// ---------------- mean pool + decode ----------------
__global__ void pool_k(const float* __restrict__ h, float* __restrict__ pooled) {
    int idx = blockIdx.x * blockDim.x + threadIdx.x;   // BATCH*DM
    if (idx >= BATCH * DM) return;
    int b = idx >> 10, d = idx & (DM - 1);
    const float* p = h + (size_t)b * SEQ * DM + d;
    float s = 0.0f;
#pragma unroll 8
    for (int l = 0; l < SEQ; l++) s += p[(size_t)l * DM];
    pooled[idx] = s * (1.0f / SEQ);
}

__global__ void dec_k(const float* __restrict__ pooled,
                      const float* __restrict__ w,
                      const float* __restrict__ b,
                      float* __restrict__ out) {
    __shared__ float red[8];
    int bi = blockIdx.x;      // 8
    int t = threadIdx.x;      // 256
    float s = 0.0f;
    for (int d = t; d < DM; d += 256) s += pooled[bi * DM + d] * w[d];
#pragma unroll
    for (int o = 16; o > 0; o >>= 1) s += __shfl_xor_sync(0xffffffffu, s, o);
    if ((t & 31) == 0) red[t >> 5] = s;
    __syncthreads();
    if (t == 0) {
        float tot = 0.0f;
#pragma unroll
        for (int i = 0; i < 8; i++) tot += red[i];
        out[bi] = tot + b[0];
    }
}

// ---------------- driver ----------------
extern "C" void kernel_launch(void* const* d_in, const int* in_sizes, int n_in,
                              void* d_out, int out_size) {
    const float* x        = (const float*)d_in[0];
    const float* enc_w    = (const float*)d_in[1];
    const float* enc_b    = (const float*)d_in[2];
    const float* ln1_g    = (const float*)d_in[3];
    const float* ln1_b    = (const float*)d_in[4];
    const float* lam_re   = (const float*)d_in[5];
    const float* lam_im   = (const float*)d_in[6];
    const float* b_re     = (const float*)d_in[7];
    const float* b_im     = (const float*)d_in[8];
    const float* c_re     = (const float*)d_in[9];
    const float* c_im     = (const float*)d_in[10];
    const float* d_skip   = (const float*)d_in[11];
    const float* log_step = (const float*)d_in[12];
    const float* ffn_g    = (const float*)d_in[13];
    const float* ffn_b    = (const float*)d_in[14];
    const float* ff_enc_w = (const float*)d_in[15];
    const float* ff_dec_w = (const float*)d_in[16];
    const float* norm_g   = (const float*)d_in[17];
    const float* norm_b   = (const float*)d_in[18];
    const float* dec_w    = (const float*)d_in[19];
    const float* dec_b    = (const float*)d_in[20];
    float* out = (float*)d_out;

    // resolve device-global addresses (host side)
    float *p_h, *p_fx, *p_fy, *p_z, *p_z2, *p_gg, *p_bu, *p_u2, *p_W2, *p_Cw, *p_pooled;
    cudaGetSymbolAddress((void**)&p_h, g_h);
    cudaGetSymbolAddress((void**)&p_fx, g_fx);
    cudaGetSymbolAddress((void**)&p_fy, g_fy);
    cudaGetSymbolAddress((void**)&p_z, g_z);
    cudaGetSymbolAddress((void**)&p_z2, g_z2);
    cudaGetSymbolAddress((void**)&p_gg, g_gg);
    cudaGetSymbolAddress((void**)&p_bu, g_bu);
    cudaGetSymbolAddress((void**)&p_u2, g_u2);
    cudaGetSymbolAddress((void**)&p_W2, g_W2);
    cudaGetSymbolAddress((void**)&p_Cw, g_Cw);
    cudaGetSymbolAddress((void**)&p_pooled, g_pooled);

    const int M = MROWS;
    // encoder: h = x @ enc_w + enc_b
    sgemm_k<false, 1><<<dim3(DM / TBN, M / TBM), 256>>>(
        x, enc_w, p_h, M, DM, D_IN, enc_b, nullptr);

    for (int i = 0; i < NL; i++) {
        const size_t w1 = (size_t)i * DM;
        const size_t w2 = (size_t)i * DM * DM;
        const size_t w3 = (size_t)i * DM * 2 * DM;

        prep_lamb_k<<<(DM + 127) / 128, 128>>>(lam_re + w1, lam_im + w1, log_step + w1);
        prep_W2_k<<<(DM * DM + 255) / 256, 256>>>(b_re + w2, b_im + w2);
        prep_Cw_k<<<(DM * DM + 255) / 256, 256>>>(c_re + w2, c_im + w2);

        // fx = LN(h)
        ln_k<<<M, 128>>>(p_h, nullptr, p_fx, ln1_g + w1, ln1_b + w1);
        // Bu = fx @ W2^T  (interleaved complex output, [M, 2P])
        sgemm_k<true, 0><<<dim3(2 * DM / TBN, M / TBM), 256>>>(
            p_fx, p_W2, p_bu, M, 2 * DM, DM, nullptr, nullptr);
        // in-place complex scan over time
        scan_k<<<(BATCH * DM) / 128, 128>>>((float2*)p_bu);
        // z = gelu(xs @ Cw^T + d*fx) + fx
        sgemm_k<true, 2><<<dim3(DM / TBN, M / TBM), 256>>>(
            p_bu, p_Cw, p_z, M, DM, 2 * DM, p_fx, d_skip + w1);
        // fy = LN(z)
        ln_k<<<M, 128>>>(p_z, nullptr, p_fy, ffn_g + w1, ffn_b + w1);
        // u2 = fy @ ff_enc_w
        sgemm_k<false, 0><<<dim3(2 * DM / TBN, M / TBM), 256>>>(
            p_fy, ff_enc_w + w3, p_u2, M, 2 * DM, DM, nullptr, nullptr);
        // geglu
        geglu_k<<<(int)(((size_t)M * DM + 255) / 256), 256>>>(p_u2, p_gg);
        // z2 = geglu @ ff_dec_w + fy
        sgemm_k<false, 3><<<dim3(DM / TBN, M / TBM), 256>>>(
            p_gg, ff_dec_w + w2, p_z2, M, DM, DM, p_fy, nullptr);
        // h = LN(z2 + h)
        ln_k<<<M, 128>>>(p_z2, p_h, p_h, norm_g + w1, norm_b + w1);
    }

    pool_k<<<(BATCH * DM) / 128, 128>>>(p_h, p_pooled);
    dec_k<<<BATCH, 256>>>(p_pooled, dec_w, dec_b, out);
}

// round 3
// speedup vs baseline: 1.9414x; 1.9414x over previous
#include <cuda_runtime.h>
#include <cuda_bf16.h>
#include <math.h>
#include <stdint.h>

// ---------------- problem constants ----------------
#define BATCH   8
#define SEQ     2048
#define D_IN    64
#define DM      1024
#define NL      4
#define MROWS   (BATCH*SEQ)   // 16384

typedef __nv_bfloat16 bf16;
typedef __nv_bfloat162 bf162;

// ---------------- scratch (device globals) ----------------
__device__ float g_h  [(size_t)MROWS * DM];
__device__ float g_fx [(size_t)MROWS * DM];
__device__ float g_fy [(size_t)MROWS * DM];
__device__ float g_z  [(size_t)MROWS * DM];
__device__ float g_big[(size_t)MROWS * 2 * DM];    // bu (pre-scan) then u2

__device__ __align__(16) bf16 g_fxh[(size_t)MROWS * DM];
__device__ __align__(16) bf16 g_fxl[(size_t)MROWS * DM];
__device__ __align__(16) bf16 g_xsh[(size_t)MROWS * 2 * DM];
__device__ __align__(16) bf16 g_xsl[(size_t)MROWS * 2 * DM];
__device__ __align__(16) bf16 g_fyh[(size_t)MROWS * DM];
__device__ __align__(16) bf16 g_fyl[(size_t)MROWS * DM];
__device__ __align__(16) bf16 g_ggh[(size_t)MROWS * DM];
__device__ __align__(16) bf16 g_ggl[(size_t)MROWS * DM];

__device__ __align__(16) bf16 g_W2h[(size_t)2 * DM * DM];   // [2P, H]  K-major
__device__ __align__(16) bf16 g_W2l[(size_t)2 * DM * DM];
__device__ __align__(16) bf16 g_Cwh[(size_t)DM * 2 * DM];   // [H, 2P]  K-major
__device__ __align__(16) bf16 g_Cwl[(size_t)DM * 2 * DM];
__device__ __align__(16) bf16 g_feh[(size_t)2 * DM * DM];   // ff_enc^T [2D, D]
__device__ __align__(16) bf16 g_fel[(size_t)2 * DM * DM];
__device__ __align__(16) bf16 g_fdh[(size_t)DM * DM];       // ff_dec^T [D, D]
__device__ __align__(16) bf16 g_fdl[(size_t)DM * DM];

__device__ float2 g_lamb[DM];
__device__ float2 g_coef[DM];
__device__ float g_pooled[BATCH * DM];

// ---------------- helpers ----------------
__device__ __forceinline__ float gelu_f(float x) {
    return 0.5f * x * (1.0f + erff(x * 0.70710678118654752f));
}
__device__ __forceinline__ void split_bf16(float v, bf16& h, bf16& l) {
    h = __float2bfloat16(v);
    l = __float2bfloat16(v - __bfloat162float(h));
}
__device__ __forceinline__ uint32_t s2u(const void* p) {
    uint32_t a;
    asm("{ .reg .u64 t; cvta.to.shared.u64 t, %1; cvt.u32.u64 %0, t; }"
        : "=r"(a) : "l"(p));
    return a;
}
__device__ __forceinline__ void cpasync16(uint32_t s, const void* g) {
    asm volatile("cp.async.cg.shared.global [%0], [%1], 16;" :: "r"(s), "l"(g));
}
__device__ __forceinline__ void ldsm_x4(uint32_t* r, uint32_t addr) {
    asm volatile("ldmatrix.sync.aligned.m8n8.x4.shared.b16 {%0,%1,%2,%3}, [%4];"
                 : "=r"(r[0]), "=r"(r[1]), "=r"(r[2]), "=r"(r[3]) : "r"(addr));
}
__device__ __forceinline__ void ldsm_x2(uint32_t* r, uint32_t addr) {
    asm volatile("ldmatrix.sync.aligned.m8n8.x2.shared.b16 {%0,%1}, [%2];"
                 : "=r"(r[0]), "=r"(r[1]) : "r"(addr));
}
__device__ __forceinline__ void mma_bf16(float* d, const uint32_t* a, const uint32_t* b) {
    asm volatile(
        "mma.sync.aligned.m16n8k16.row.col.f32.bf16.bf16.f32 "
        "{%0,%1,%2,%3}, {%4,%5,%6,%7}, {%8,%9}, {%0,%1,%2,%3};"
        : "+f"(d[0]), "+f"(d[1]), "+f"(d[2]), "+f"(d[3])
        : "r"(a[0]), "r"(a[1]), "r"(a[2]), "r"(a[3]), "r"(b[0]), "r"(b[1]));
}

// ---------------- HMMA split-bf16 GEMM: C[M,N] = A[M,K] @ B[N,K]^T -----------
// CTA tile 128x128, K-chunk 32. Each smem row = 128B: [hi 64B | lo 64B], SW128
// swizzle. 4-stage cp.async pipeline. 8 warps (2m x 4n), warp tile 64x32.
// 3 MMAs/k16: hi*hi + lo*hi + hi*lo.
// EPI 0: plain  2: gelu(acc + e1[n]*e0[m,n]) + e0[m,n]  3: acc + e0[m,n]
#define KC        32
#define STAGE_B   32768      // A 16KB + B 16KB
#define NSTAGE    4
#define SMEM_GEMM (NSTAGE * STAGE_B)

template <int EPI>
__global__ void __launch_bounds__(256, 1)
hmma_gemm(const bf16* __restrict__ Ah, const bf16* __restrict__ Al,
          const bf16* __restrict__ Bh, const bf16* __restrict__ Bl,
          float* __restrict__ Cc, int N, int K,
          const float* __restrict__ e0, const float* __restrict__ e1) {
    extern __shared__ __align__(128) char smem[];
    const int tid = threadIdx.x;
    const int wid = tid >> 5;
    const int lid = tid & 31;
    const int wm = wid & 1;          // 2 warps along M
    const int wn = wid >> 1;         // 4 warps along N
    const int bm = blockIdx.y * 128;
    const int bn = blockIdx.x * 128;
    const uint32_t sbase = s2u(smem);
    const int nch = K >> 5;

    auto load_stage = [&](int st, int c) {
        const int kc = c << 5;
        const uint32_t stb = sbase + st * STAGE_B;
#pragma unroll
        for (int t = 0; t < 8; ++t) {
            int i = tid + t * 256;           // 0..2047
            int isB = i >> 10;               // first 1024 = A, next = B
            int ii = i & 1023;
            int row = ii >> 3, j = ii & 7;
            const bf16* src = isB ? ((j < 4) ? Bh : Bl) : ((j < 4) ? Ah : Al);
            size_t go = (size_t)((isB ? bn : bm) + row) * K + kc + (j & 3) * 8;
            uint32_t dst = stb + (isB ? 16384u : 0u) + row * 128 +
                           (uint32_t)((j ^ (row & 7)) << 4);
            cpasync16(dst, src + go);
        }
    };

    float acc[4][4][4];
#pragma unroll
    for (int mt = 0; mt < 4; mt++)
#pragma unroll
        for (int nt = 0; nt < 4; nt++)
#pragma unroll
            for (int q = 0; q < 4; q++) acc[mt][nt][q] = 0.0f;

    // prologue: 3 stages in flight
    load_stage(0, 0); asm volatile("cp.async.commit_group;" ::: "memory");
    load_stage(1, 1); asm volatile("cp.async.commit_group;" ::: "memory");
    load_stage(2, 2); asm volatile("cp.async.commit_group;" ::: "memory");

    for (int c = 0; c < nch; ++c) {
        const int wg = nch - 1 - c;
        if (wg >= 2)      asm volatile("cp.async.wait_group 2;" ::: "memory");
        else if (wg == 1) asm volatile("cp.async.wait_group 1;" ::: "memory");
        else              asm volatile("cp.async.wait_group 0;" ::: "memory");
        __syncthreads();

        if (c + 3 < nch) {
            load_stage((c + 3) & 3, c + 3);
        }
        asm volatile("cp.async.commit_group;" ::: "memory");

        const uint32_t sA = sbase + (c & 3) * STAGE_B;
        const uint32_t sB = sA + 16384;
#pragma unroll
        for (int ks = 0; ks < 2; ++ks) {
            uint32_t a[2][4][4];
            uint32_t b[2][4][2];
#pragma unroll
            for (int sp = 0; sp < 2; ++sp)
#pragma unroll
                for (int mt = 0; mt < 4; ++mt) {
                    int row = wm * 64 + mt * 16 + (lid & 15);
                    int ch  = sp * 4 + ks * 2 + (lid >> 4);
                    uint32_t ad = sA + row * 128 + ((ch ^ (row & 7)) << 4);
                    ldsm_x4(a[sp][mt], ad);
                }
#pragma unroll
            for (int sp = 0; sp < 2; ++sp)
#pragma unroll
                for (int nt = 0; nt < 4; ++nt) {
                    int row = wn * 32 + nt * 8 + (lid & 7);
                    int ch  = sp * 4 + ks * 2 + ((lid >> 3) & 1);
                    uint32_t ad = sB + row * 128 + ((ch ^ (row & 7)) << 4);
                    ldsm_x2(b[sp][nt], ad);
                }
#pragma unroll
            for (int mt = 0; mt < 4; ++mt)
#pragma unroll
                for (int nt = 0; nt < 4; ++nt)
                    mma_bf16(acc[mt][nt], a[0][mt], b[0][nt]);
#pragma unroll
            for (int mt = 0; mt < 4; ++mt)
#pragma unroll
                for (int nt = 0; nt < 4; ++nt)
                    mma_bf16(acc[mt][nt], a[1][mt], b[0][nt]);
#pragma unroll
            for (int mt = 0; mt < 4; ++mt)
#pragma unroll
                for (int nt = 0; nt < 4; ++nt)
                    mma_bf16(acc[mt][nt], a[0][mt], b[1][nt]);
        }
        __syncthreads();
    }

    // epilogue: thread t holds rows (t/4, t/4+8), cols 2*(t%4)+{0,1} per tile
    const int tr = lid >> 2;
    const int tc = (lid & 3) * 2;
#pragma unroll
    for (int mt = 0; mt < 4; ++mt) {
#pragma unroll
        for (int half = 0; half < 2; ++half) {
            const int m = bm + wm * 64 + mt * 16 + tr + half * 8;
            const size_t rowoff = (size_t)m * N;
#pragma unroll
            for (int nt = 0; nt < 4; ++nt) {
                const int n = bn + wn * 32 + nt * 8 + tc;
                float v0 = acc[mt][nt][half * 2 + 0];
                float v1 = acc[mt][nt][half * 2 + 1];
                const size_t idx = rowoff + n;
                if (EPI == 2) {
                    float f0 = e0[idx], f1 = e0[idx + 1];
                    v0 = gelu_f(fmaf(e1[n], f0, v0)) + f0;
                    v1 = gelu_f(fmaf(e1[n + 1], f1, v1)) + f1;
                } else if (EPI == 3) {
                    v0 += e0[idx];
                    v1 += e0[idx + 1];
                }
                *reinterpret_cast<float2*>(Cc + idx) = make_float2(v0, v1);
            }
        }
    }
}

// ---------------- fp32 SGEMM (encoder only, K=64) ----------------------------
#define TBM 128
#define TBN 128
#define TBK 8
__global__ void __launch_bounds__(256)
sgemm_enc(const float* __restrict__ A, const float* __restrict__ B,
          float* __restrict__ C, int M, int N, int K,
          const float* __restrict__ bias) {
    __shared__ float As[TBK][TBM + 4];
    __shared__ float Bs[TBK][TBN + 4];
    const int tid = threadIdx.x;
    const int bm = blockIdx.y * TBM;
    const int bn = blockIdx.x * TBN;
    const int arow = tid >> 1, akc = (tid & 1) * 4;
    const float* Aptr = A + (size_t)(bm + arow) * K + akc;
    const int br0 = tid >> 5, bc0 = (tid & 31) * 4;
    const float* Bptr = B + (size_t)br0 * N + bn + bc0;

    float acc[8][8];
#pragma unroll
    for (int i = 0; i < 8; i++)
#pragma unroll
        for (int j = 0; j < 8; j++) acc[i][j] = 0.0f;

    float4 aR = *reinterpret_cast<const float4*>(Aptr);
    float4 bR = *reinterpret_cast<const float4*>(Bptr);
    const int tm = tid >> 4, tn = tid & 15;

    for (int k0 = 0;;) {
        As[akc + 0][arow] = aR.x; As[akc + 1][arow] = aR.y;
        As[akc + 2][arow] = aR.z; As[akc + 3][arow] = aR.w;
        Bs[br0][bc0 + 0] = bR.x;  Bs[br0][bc0 + 1] = bR.y;
        Bs[br0][bc0 + 2] = bR.z;  Bs[br0][bc0 + 3] = bR.w;
        __syncthreads();
        k0 += TBK;
        bool more = (k0 < K);
        if (more) {
            aR = *reinterpret_cast<const float4*>(Aptr + k0);
            bR = *reinterpret_cast<const float4*>(Bptr + (size_t)k0 * N);
        }
#pragma unroll
        for (int kk = 0; kk < TBK; kk++) {
            float4 a0 = *reinterpret_cast<const float4*>(&As[kk][tm * 4]);
            float4 a1 = *reinterpret_cast<const float4*>(&As[kk][64 + tm * 4]);
            float4 b0 = *reinterpret_cast<const float4*>(&Bs[kk][tn * 4]);
            float4 b1 = *reinterpret_cast<const float4*>(&Bs[kk][64 + tn * 4]);
            float av[8] = {a0.x, a0.y, a0.z, a0.w, a1.x, a1.y, a1.z, a1.w};
            float bv[8] = {b0.x, b0.y, b0.z, b0.w, b1.x, b1.y, b1.z, b1.w};
#pragma unroll
            for (int i = 0; i < 8; i++)
#pragma unroll
                for (int j = 0; j < 8; j++)
                    acc[i][j] = fmaf(av[i], bv[j], acc[i][j]);
        }
        __syncthreads();
        if (!more) break;
    }
#pragma unroll
    for (int i = 0; i < 8; i++) {
        int r = bm + ((i < 4) ? (tm * 4 + i) : (64 + tm * 4 + i - 4));
        size_t rowoff = (size_t)r * N;
#pragma unroll
        for (int j = 0; j < 8; j++) {
            int c = bn + ((j < 4) ? (tn * 4 + j) : (64 + tn * 4 + j - 4));
            C[rowoff + c] = acc[i][j] + bias[c];
        }
    }
}

// ---------------- per-layer weight prep --------------------------------------
__global__ void prep_lamb_k(const float* __restrict__ lam_re,
                            const float* __restrict__ lam_im,
                            const float* __restrict__ log_step) {
    int p = blockIdx.x * blockDim.x + threadIdx.x;
    if (p >= DM) return;
    float dt = expf(log_step[p]);
    float lr = lam_re[p], li = lam_im[p];
    float er = expf(lr * dt);
    float2 lb = make_float2(er * cosf(li * dt), er * sinf(li * dt));
    g_lamb[p] = lb;
    float nr = lb.x - 1.0f, ni = lb.y;
    float den = lr * lr + li * li;
    g_coef[p] = make_float2((nr * lr + ni * li) / den, (ni * lr - nr * li) / den);
}

__global__ void prep_W2_k(const float* __restrict__ b_re,
                          const float* __restrict__ b_im) {
    size_t idx = (size_t)blockIdx.x * blockDim.x + threadIdx.x;
    if (idx >= (size_t)DM * DM) return;
    int p = (int)(idx / DM), h = (int)(idx % DM);
    float2 c = g_coef[p];
    float br = b_re[idx], bi = b_im[idx];
    float vre = c.x * br - c.y * bi;
    float vim = c.x * bi + c.y * br;
    bf16 h1, l1, h2, l2;
    split_bf16(vre, h1, l1);
    split_bf16(vim, h2, l2);
    size_t r0 = (size_t)(2 * p) * DM + h;
    size_t r1 = (size_t)(2 * p + 1) * DM + h;
    g_W2h[r0] = h1; g_W2l[r0] = l1;
    g_W2h[r1] = h2; g_W2l[r1] = l2;
}

__global__ void prep_Cw_k(const float* __restrict__ c_re,
                          const float* __restrict__ c_im) {
    size_t idx = (size_t)blockIdx.x * blockDim.x + threadIdx.x;
    if (idx >= (size_t)DM * DM) return;
    int h = (int)(idx / DM), p = (int)(idx % DM);
    bf16 h1, l1, h2, l2;
    split_bf16(c_re[idx], h1, l1);
    split_bf16(-c_im[idx], h2, l2);
    bf162* ch = reinterpret_cast<bf162*>(g_Cwh);
    bf162* cl = reinterpret_cast<bf162*>(g_Cwl);
    bf162 vh; vh.x = h1; vh.y = h2;
    bf162 vl; vl.x = l1; vl.y = l2;
    ch[(size_t)h * DM + p] = vh;
    cl[(size_t)h * DM + p] = vl;
}

// transpose-split: in [R, C2] fp32 -> out [C2, R] bf16 hi/lo
__global__ void prep_trans_k(const float* __restrict__ in,
                             bf16* __restrict__ oh, bf16* __restrict__ ol,
                             int R, int C2) {
    __shared__ float t[32][33];
    int r = blockIdx.y * 32 + threadIdx.y;
    int c = blockIdx.x * 32 + threadIdx.x;
    t[threadIdx.y][threadIdx.x] = in[(size_t)r * C2 + c];
    __syncthreads();
    int orow = blockIdx.x * 32 + threadIdx.y;
    int ocol = blockIdx.y * 32 + threadIdx.x;
    float v = t[threadIdx.x][threadIdx.y];
    bf16 h, l;
    split_bf16(v, h, l);
    oh[(size_t)orow * R + ocol] = h;
    ol[(size_t)orow * R + ocol] = l;
}

// ---------------- scan: fp32 recurrence, bf16 hi/lo output -------------------
__global__ void scan_k(const float2* __restrict__ bu,
                       bf162* __restrict__ xh, bf162* __restrict__ xl) {
    int idx = blockIdx.x * blockDim.x + threadIdx.x;
    if (idx >= BATCH * DM) return;
    int b = idx >> 10, p = idx & (DM - 1);
    float2 a = g_lamb[p];
    const float2* ptr = bu + (size_t)b * SEQ * DM + p;
    bf162* oh = xh + (size_t)b * SEQ * DM + p;
    bf162* ol = xl + (size_t)b * SEQ * DM + p;
    float xr = 0.0f, xi = 0.0f;
    const int U = 8;
    float2 cur[U], nxt[U];
#pragma unroll
    for (int i = 0; i < U; i++) cur[i] = ptr[(size_t)i * DM];
#pragma unroll
    for (int i = 0; i < U; i++) nxt[i] = make_float2(0.f, 0.f);
    for (int l0 = 0; l0 < SEQ; l0 += U) {
        if (l0 + U < SEQ) {
#pragma unroll
            for (int i = 0; i < U; i++) nxt[i] = ptr[(size_t)(l0 + U + i) * DM];
        }
#pragma unroll
        for (int i = 0; i < U; i++) {
            float ur = cur[i].x, ui = cur[i].y;
            float nr = fmaf(a.x, xr, fmaf(-a.y, xi, ur));
            float ni = fmaf(a.x, xi, fmaf(a.y, xr, ui));
            xr = nr; xi = ni;
            bf16 hr = __float2bfloat16(xr);
            bf16 hi2 = __float2bfloat16(xi);
            bf162 vh; vh.x = hr; vh.y = hi2;
            bf162 vl;
            vl.x = __float2bfloat16(xr - __bfloat162float(hr));
            vl.y = __float2bfloat16(xi - __bfloat162float(hi2));
            oh[(size_t)(l0 + i) * DM] = vh;
            ol[(size_t)(l0 + i) * DM] = vl;
        }
#pragma unroll
        for (int i = 0; i < U; i++) cur[i] = nxt[i];
    }
}

// ---------------- LayerNorm (+optional residual add, +optional bf16 split) ---
__global__ void __launch_bounds__(128)
ln_k(const float* __restrict__ in, const float* __restrict__ add,
     float* __restrict__ out, bf16* __restrict__ oh, bf16* __restrict__ ol,
     const float* __restrict__ g, const float* __restrict__ bb) {
    __shared__ float red[8];
    size_t base = (size_t)blockIdx.x * DM;
    int t = threadIdx.x;
    float v[8];
    float s = 0.0f;
#pragma unroll
    for (int i = 0; i < 8; i++) {
        float xv = in[base + t + i * 128];
        if (add) xv += add[base + t + i * 128];
        v[i] = xv;
        s += xv;
    }
#pragma unroll
    for (int o = 16; o > 0; o >>= 1) s += __shfl_xor_sync(0xffffffffu, s, o);
    if ((t & 31) == 0) red[t >> 5] = s;
    __syncthreads();
    float mean = (red[0] + red[1] + red[2] + red[3]) * (1.0f / DM);
    float s2 = 0.0f;
#pragma unroll
    for (int i = 0; i < 8; i++) { float d = v[i] - mean; s2 += d * d; }
#pragma unroll
    for (int o = 16; o > 0; o >>= 1) s2 += __shfl_xor_sync(0xffffffffu, s2, o);
    if ((t & 31) == 0) red[4 + (t >> 5)] = s2;
    __syncthreads();
    float var = (red[4] + red[5] + red[6] + red[7]) * (1.0f / DM);
    float inv = rsqrtf(var + 1e-5f);
#pragma unroll
    for (int i = 0; i < 8; i++) {
        int c = t + i * 128;
        float y = (v[i] - mean) * inv * g[c] + bb[c];
        out[base + c] = y;
        if (oh) {
            bf16 h, l;
            split_bf16(y, h, l);
            oh[base + c] = h;
            ol[base + c] = l;
        }
    }
}

// ---------------- GEGLU -> bf16 hi/lo ----------------------------------------
__global__ void geglu_k(const float* __restrict__ u2,
                        bf16* __restrict__ gh, bf16* __restrict__ gl) {
    size_t i = (size_t)blockIdx.x * blockDim.x + threadIdx.x;
    if (i >= (size_t)MROWS * DM) return;
    size_t m = i >> 10;
    int c = (int)(i & (DM - 1));
    float a = u2[m * (2 * DM) + c];
    float gg = u2[m * (2 * DM) + DM + c];
    float v = a * gelu_f(gg);
    bf16 h, l;
    split_bf16(v, h, l);
    gh[i] = h;
    gl[i] = l;
}

// ---------------- mean pool + decode -----------------------------------------
__global__ void pool_k(const float* __restrict__ h, float* __restrict__ pooled) {
    int idx = blockIdx.x * blockDim.x + threadIdx.x;
    if (idx >= BATCH * DM) return;
    int b = idx >> 10, d = idx & (DM - 1);
    const float* p = h + (size_t)b * SEQ * DM + d;
    float s = 0.0f;
#pragma unroll 8
    for (int l = 0; l < SEQ; l++) s += p[(size_t)l * DM];
    pooled[idx] = s * (1.0f / SEQ);
}

__global__ void dec_k(const float* __restrict__ pooled,
                      const float* __restrict__ w,
                      const float* __restrict__ b,
                      float* __restrict__ out) {
    __shared__ float red[8];
    int bi = blockIdx.x;
    int t = threadIdx.x;
    float s = 0.0f;
    for (int d = t; d < DM; d += 256) s += pooled[bi * DM + d] * w[d];
#pragma unroll
    for (int o = 16; o > 0; o >>= 1) s += __shfl_xor_sync(0xffffffffu, s, o);
    if ((t & 31) == 0) red[t >> 5] = s;
    __syncthreads();
    if (t == 0) {
        float tot = 0.0f;
#pragma unroll
        for (int i = 0; i < 8; i++) tot += red[i];
        out[bi] = tot + b[0];
    }
}

// ---------------- driver ----------------
extern "C" void kernel_launch(void* const* d_in, const int* in_sizes, int n_in,
                              void* d_out, int out_size) {
    const float* x        = (const float*)d_in[0];
    const float* enc_w    = (const float*)d_in[1];
    const float* enc_b    = (const float*)d_in[2];
    const float* ln1_g    = (const float*)d_in[3];
    const float* ln1_b    = (const float*)d_in[4];
    const float* lam_re   = (const float*)d_in[5];
    const float* lam_im   = (const float*)d_in[6];
    const float* b_re     = (const float*)d_in[7];
    const float* b_im     = (const float*)d_in[8];
    const float* c_re     = (const float*)d_in[9];
    const float* c_im     = (const float*)d_in[10];
    const float* d_skip   = (const float*)d_in[11];
    const float* log_step = (const float*)d_in[12];
    const float* ffn_g    = (const float*)d_in[13];
    const float* ffn_b    = (const float*)d_in[14];
    const float* ff_enc_w = (const float*)d_in[15];
    const float* ff_dec_w = (const float*)d_in[16];
    const float* norm_g   = (const float*)d_in[17];
    const float* norm_b   = (const float*)d_in[18];
    const float* dec_w    = (const float*)d_in[19];
    const float* dec_b    = (const float*)d_in[20];
    float* out = (float*)d_out;

    static int attr_done = 0;
    if (!attr_done) {
        cudaFuncSetAttribute(hmma_gemm<0>, cudaFuncAttributeMaxDynamicSharedMemorySize, SMEM_GEMM);
        cudaFuncSetAttribute(hmma_gemm<2>, cudaFuncAttributeMaxDynamicSharedMemorySize, SMEM_GEMM);
        cudaFuncSetAttribute(hmma_gemm<3>, cudaFuncAttributeMaxDynamicSharedMemorySize, SMEM_GEMM);
        attr_done = 1;
    }

    float *p_h, *p_fx, *p_fy, *p_z, *p_big, *p_pooled;
    bf16 *p_fxh, *p_fxl, *p_xsh, *p_xsl, *p_fyh, *p_fyl, *p_ggh, *p_ggl;
    bf16 *p_W2h, *p_W2l, *p_Cwh, *p_Cwl, *p_feh, *p_fel, *p_fdh, *p_fdl;
    cudaGetSymbolAddress((void**)&p_h, g_h);
    cudaGetSymbolAddress((void**)&p_fx, g_fx);
    cudaGetSymbolAddress((void**)&p_fy, g_fy);
    cudaGetSymbolAddress((void**)&p_z, g_z);
    cudaGetSymbolAddress((void**)&p_big, g_big);
    cudaGetSymbolAddress((void**)&p_pooled, g_pooled);
    cudaGetSymbolAddress((void**)&p_fxh, g_fxh);
    cudaGetSymbolAddress((void**)&p_fxl, g_fxl);
    cudaGetSymbolAddress((void**)&p_xsh, g_xsh);
    cudaGetSymbolAddress((void**)&p_xsl, g_xsl);
    cudaGetSymbolAddress((void**)&p_fyh, g_fyh);
    cudaGetSymbolAddress((void**)&p_fyl, g_fyl);
    cudaGetSymbolAddress((void**)&p_ggh, g_ggh);
    cudaGetSymbolAddress((void**)&p_ggl, g_ggl);
    cudaGetSymbolAddress((void**)&p_W2h, g_W2h);
    cudaGetSymbolAddress((void**)&p_W2l, g_W2l);
    cudaGetSymbolAddress((void**)&p_Cwh, g_Cwh);
    cudaGetSymbolAddress((void**)&p_Cwl, g_Cwl);
    cudaGetSymbolAddress((void**)&p_feh, g_feh);
    cudaGetSymbolAddress((void**)&p_fel, g_fel);
    cudaGetSymbolAddress((void**)&p_fdh, g_fdh);
    cudaGetSymbolAddress((void**)&p_fdl, g_fdl);

    const int M = MROWS;

    // encoder: h = x @ enc_w + enc_b  (fp32, K=64)
    sgemm_enc<<<dim3(DM / TBN, M / TBM), 256>>>(x, enc_w, p_h, M, DM, D_IN, enc_b);

    for (int i = 0; i < NL; i++) {
        const size_t w1 = (size_t)i * DM;
        const size_t w2 = (size_t)i * DM * DM;
        const size_t w3 = (size_t)i * DM * 2 * DM;

        prep_lamb_k<<<(DM + 127) / 128, 128>>>(lam_re + w1, lam_im + w1, log_step + w1);
        prep_W2_k<<<(DM * DM + 255) / 256, 256>>>(b_re + w2, b_im + w2);
        prep_Cw_k<<<(DM * DM + 255) / 256, 256>>>(c_re + w2, c_im + w2);
        prep_trans_k<<<dim3(2 * DM / 32, DM / 32), dim3(32, 32)>>>(
            ff_enc_w + w3, p_feh, p_fel, DM, 2 * DM);
        prep_trans_k<<<dim3(DM / 32, DM / 32), dim3(32, 32)>>>(
            ff_dec_w + w2, p_fdh, p_fdl, DM, DM);

        // fx = LN(h)  (+ split)
        ln_k<<<M, 128>>>(p_h, nullptr, p_fx, p_fxh, p_fxl, ln1_g + w1, ln1_b + w1);
        // Bu = fx @ W2^T  [M, 2P] fp32 (interleaved re/im)
        hmma_gemm<0><<<dim3(2 * DM / 128, M / 128), 256, SMEM_GEMM>>>(
            p_fxh, p_fxl, p_W2h, p_W2l, p_big, 2 * DM, DM, nullptr, nullptr);
        // complex recurrence -> xs (bf16 hi/lo)
        scan_k<<<(BATCH * DM) / 128, 128>>>((const float2*)p_big,
                                            (bf162*)p_xsh, (bf162*)p_xsl);
        // z = gelu(xs @ Cw^T + d*fx) + fx
        hmma_gemm<2><<<dim3(DM / 128, M / 128), 256, SMEM_GEMM>>>(
            p_xsh, p_xsl, p_Cwh, p_Cwl, p_z, DM, 2 * DM, p_fx, d_skip + w1);
        // fy = LN(z)  (+ split)
        ln_k<<<M, 128>>>(p_z, nullptr, p_fy, p_fyh, p_fyl, ffn_g + w1, ffn_b + w1);
        // u2 = fy @ ff_enc_w  [M, 2D]
        hmma_gemm<0><<<dim3(2 * DM / 128, M / 128), 256, SMEM_GEMM>>>(
            p_fyh, p_fyl, p_feh, p_fel, p_big, 2 * DM, DM, nullptr, nullptr);
        // geglu -> gg (bf16 hi/lo)
        geglu_k<<<(int)(((size_t)M * DM + 255) / 256), 256>>>(p_big, p_ggh, p_ggl);
        // z2 = gg @ ff_dec_w + fy   (into p_z)
        hmma_gemm<3><<<dim3(DM / 128, M / 128), 256, SMEM_GEMM>>>(
            p_ggh, p_ggl, p_fdh, p_fdl, p_z, DM, DM, p_fy, nullptr);
        // h = LN(z2 + h)
        ln_k<<<M, 128>>>(p_z, p_h, p_h, nullptr, nullptr, norm_g + w1, norm_b + w1);
    }

    pool_k<<<(BATCH * DM) / 128, 128>>>(p_h, p_pooled);
    dec_k<<<BATCH, 256>>>(p_pooled, dec_w, dec_b, out);
}

// round 4
// speedup vs baseline: 2.0627x; 1.0624x over previous
#include <cuda_runtime.h>
#include <cuda_bf16.h>
#include <math.h>
#include <stdint.h>

// ---------------- problem constants ----------------
#define BATCH   8
#define SEQ     2048
#define D_IN    64
#define DM      1024
#define NL      4
#define MROWS   (BATCH*SEQ)   // 16384

typedef __nv_bfloat16 bf16;
typedef __nv_bfloat162 bf162;

// ---------------- scratch (device globals) ----------------
__device__ float g_h  [(size_t)MROWS * DM];
__device__ float g_fx [(size_t)MROWS * DM];
__device__ float g_fy [(size_t)MROWS * DM];
__device__ float g_z  [(size_t)MROWS * DM];
__device__ float g_big[(size_t)MROWS * 2 * DM];    // bu (pre-scan) then u2

__device__ __align__(16) bf16 g_fxh[(size_t)MROWS * DM];
__device__ __align__(16) bf16 g_fxl[(size_t)MROWS * DM];
__device__ __align__(16) bf16 g_xsh[(size_t)MROWS * 2 * DM];
__device__ __align__(16) bf16 g_xsl[(size_t)MROWS * 2 * DM];
__device__ __align__(16) bf16 g_fyh[(size_t)MROWS * DM];
__device__ __align__(16) bf16 g_fyl[(size_t)MROWS * DM];
__device__ __align__(16) bf16 g_ggh[(size_t)MROWS * DM];
__device__ __align__(16) bf16 g_ggl[(size_t)MROWS * DM];

__device__ __align__(16) bf16 g_W2h[(size_t)2 * DM * DM];   // [2P, H]  K-major
__device__ __align__(16) bf16 g_W2l[(size_t)2 * DM * DM];
__device__ __align__(16) bf16 g_Cwh[(size_t)DM * 2 * DM];   // [H, 2P]  K-major
__device__ __align__(16) bf16 g_Cwl[(size_t)DM * 2 * DM];
__device__ __align__(16) bf16 g_feh[(size_t)2 * DM * DM];   // ff_enc^T [2D, D]
__device__ __align__(16) bf16 g_fel[(size_t)2 * DM * DM];
__device__ __align__(16) bf16 g_fdh[(size_t)DM * DM];       // ff_dec^T [D, D]
__device__ __align__(16) bf16 g_fdl[(size_t)DM * DM];

__device__ float2 g_lamb[DM];
__device__ float2 g_coef[DM];
__device__ float g_pooled[BATCH * DM];

// ---------------- helpers ----------------
__device__ __forceinline__ float gelu_f(float x) {
    return 0.5f * x * (1.0f + erff(x * 0.70710678118654752f));
}
__device__ __forceinline__ void split_bf16(float v, bf16& h, bf16& l) {
    h = __float2bfloat16(v);
    l = __float2bfloat16(v - __bfloat162float(h));
}
__device__ __forceinline__ uint32_t s2u(const void* p) {
    uint32_t a;
    asm("{ .reg .u64 t; cvta.to.shared.u64 t, %1; cvt.u32.u64 %0, t; }"
        : "=r"(a) : "l"(p));
    return a;
}
__device__ __forceinline__ void cpasync16(uint32_t s, const void* g) {
    asm volatile("cp.async.cg.shared.global [%0], [%1], 16;" :: "r"(s), "l"(g));
}
__device__ __forceinline__ void ldsm_x4(uint32_t* r, uint32_t addr) {
    asm volatile("ldmatrix.sync.aligned.m8n8.x4.shared.b16 {%0,%1,%2,%3}, [%4];"
                 : "=r"(r[0]), "=r"(r[1]), "=r"(r[2]), "=r"(r[3]) : "r"(addr));
}
__device__ __forceinline__ void mma_bf16(float* d, const uint32_t* a, const uint32_t* b) {
    asm volatile(
        "mma.sync.aligned.m16n8k16.row.col.f32.bf16.bf16.f32 "
        "{%0,%1,%2,%3}, {%4,%5,%6,%7}, {%8,%9}, {%0,%1,%2,%3};"
        : "+f"(d[0]), "+f"(d[1]), "+f"(d[2]), "+f"(d[3])
        : "r"(a[0]), "r"(a[1]), "r"(a[2]), "r"(a[3]), "r"(b[0]), "r"(b[1]));
}

// ---------------- HMMA split-bf16 GEMM: C[M,N] = A[M,K] @ B[N,K]^T -----------
// CTA tile 128x256, warp tile 64x64 (2m x 4n warps). K-chunk 32; smem row =
// 128B: [hi 64B | lo 64B], XOR swizzle. 4-stage cp.async. Split phases per k16:
// hh, lh, hl (b regs reused between hi and lo to cap register pressure).
// EPI 0: plain  2: gelu(acc + e1[n]*e0[m,n]) + e0[m,n]  3: acc + e0[m,n]
#define STAGE_B   49152      // A 16KB + B 32KB
#define NSTAGE    4
#define SMEM_GEMM (NSTAGE * STAGE_B)

template <int EPI>
__global__ void __launch_bounds__(256, 1)
hmma_gemm(const bf16* __restrict__ Ah, const bf16* __restrict__ Al,
          const bf16* __restrict__ Bh, const bf16* __restrict__ Bl,
          float* __restrict__ Cc, int N, int K,
          const float* __restrict__ e0, const float* __restrict__ e1) {
    extern __shared__ __align__(128) char smem[];
    const int tid = threadIdx.x;
    const int wid = tid >> 5;
    const int lid = tid & 31;
    const int wm = wid & 1;          // 2 warps along M
    const int wn = wid >> 1;         // 4 warps along N
    const int bm = blockIdx.y * 128;
    const int bn = blockIdx.x * 256;
    const uint32_t sbase = s2u(smem);
    const int nch = K >> 5;

    auto load_stage = [&](int st, int c) {
        const int kc = c << 5;
        const uint32_t stb = sbase + st * STAGE_B;
#pragma unroll
        for (int t = 0; t < 12; ++t) {
            int i = tid + t * 256;           // 0..3071
            int isB = (i >= 1024);
            int ii = isB ? (i - 1024) : i;
            int row = ii >> 3, j = ii & 7;
            const bf16* src = isB ? ((j < 4) ? Bh : Bl) : ((j < 4) ? Ah : Al);
            size_t go = (size_t)((isB ? bn : bm) + row) * K + kc + (j & 3) * 8;
            uint32_t dst = stb + (isB ? 16384u : 0u) + row * 128 +
                           (uint32_t)((j ^ (row & 7)) << 4);
            cpasync16(dst, src + go);
        }
    };

    float acc[4][8][4];
#pragma unroll
    for (int mt = 0; mt < 4; mt++)
#pragma unroll
        for (int nt = 0; nt < 8; nt++)
#pragma unroll
            for (int q = 0; q < 4; q++) acc[mt][nt][q] = 0.0f;

    // prologue: 3 stages in flight
    load_stage(0, 0); asm volatile("cp.async.commit_group;" ::: "memory");
    load_stage(1, 1); asm volatile("cp.async.commit_group;" ::: "memory");
    load_stage(2, 2); asm volatile("cp.async.commit_group;" ::: "memory");

    // per-lane ldsm address components (row, chunk-in-row lane mapping)
    const int a_row = wm * 64 + (lid & 15);          // + mt*16
    const int a_chl = (lid >> 4);                    // + sp*4 + ks*2
    const int b_row = wn * 64 + ((lid >> 4) & 1) * 8 + (lid & 7);  // + ntp*16
    const int b_chl = ((lid >> 3) & 1);              // + sp*4 + ks*2

    for (int c = 0; c < nch; ++c) {
        const int wg = nch - 1 - c;
        if (wg >= 2)      asm volatile("cp.async.wait_group 2;" ::: "memory");
        else if (wg == 1) asm volatile("cp.async.wait_group 1;" ::: "memory");
        else              asm volatile("cp.async.wait_group 0;" ::: "memory");
        __syncthreads();

        if (c + 3 < nch) {
            load_stage((c + 3) & 3, c + 3);
        }
        asm volatile("cp.async.commit_group;" ::: "memory");

        const uint32_t sA = sbase + (c & 3) * STAGE_B;
        const uint32_t sB = sA + 16384;
#pragma unroll
        for (int ks = 0; ks < 2; ++ks) {
            uint32_t a_hi[4][4], a_lo[4][4], b[4][4];
            // phase 1: hi * hi
#pragma unroll
            for (int mt = 0; mt < 4; ++mt) {
                int row = a_row + mt * 16;
                int ch = ks * 2 + a_chl;
                ldsm_x4(a_hi[mt], sA + row * 128 + ((ch ^ (row & 7)) << 4));
            }
#pragma unroll
            for (int ntp = 0; ntp < 4; ++ntp) {
                int row = b_row + ntp * 16;
                int ch = ks * 2 + b_chl;
                ldsm_x4(b[ntp], sB + row * 128 + ((ch ^ (row & 7)) << 4));
            }
#pragma unroll
            for (int mt = 0; mt < 4; ++mt)
#pragma unroll
                for (int ntp = 0; ntp < 4; ++ntp) {
                    mma_bf16(acc[mt][2 * ntp],     a_hi[mt], &b[ntp][0]);
                    mma_bf16(acc[mt][2 * ntp + 1], a_hi[mt], &b[ntp][2]);
                }
            // phase 2: lo * hi
#pragma unroll
            for (int mt = 0; mt < 4; ++mt) {
                int row = a_row + mt * 16;
                int ch = 4 + ks * 2 + a_chl;
                ldsm_x4(a_lo[mt], sA + row * 128 + ((ch ^ (row & 7)) << 4));
            }
#pragma unroll
            for (int mt = 0; mt < 4; ++mt)
#pragma unroll
                for (int ntp = 0; ntp < 4; ++ntp) {
                    mma_bf16(acc[mt][2 * ntp],     a_lo[mt], &b[ntp][0]);
                    mma_bf16(acc[mt][2 * ntp + 1], a_lo[mt], &b[ntp][2]);
                }
            // phase 3: hi * lo (reuse b regs)
#pragma unroll
            for (int ntp = 0; ntp < 4; ++ntp) {
                int row = b_row + ntp * 16;
                int ch = 4 + ks * 2 + b_chl;
                ldsm_x4(b[ntp], sB + row * 128 + ((ch ^ (row & 7)) << 4));
            }
#pragma unroll
            for (int mt = 0; mt < 4; ++mt)
#pragma unroll
                for (int ntp = 0; ntp < 4; ++ntp) {
                    mma_bf16(acc[mt][2 * ntp],     a_hi[mt], &b[ntp][0]);
                    mma_bf16(acc[mt][2 * ntp + 1], a_hi[mt], &b[ntp][2]);
                }
        }
        __syncthreads();
    }

    // epilogue: thread holds rows (tr, tr+8), cols tc,tc+1 per m16n8 tile
    const int tr = lid >> 2;
    const int tc = (lid & 3) * 2;
#pragma unroll
    for (int mt = 0; mt < 4; ++mt) {
#pragma unroll
        for (int half = 0; half < 2; ++half) {
            const int m = bm + wm * 64 + mt * 16 + tr + half * 8;
            const size_t rowoff = (size_t)m * N;
#pragma unroll
            for (int nt = 0; nt < 8; ++nt) {
                const int n = bn + wn * 64 + nt * 8 + tc;
                float v0 = acc[mt][nt][half * 2 + 0];
                float v1 = acc[mt][nt][half * 2 + 1];
                const size_t idx = rowoff + n;
                if (EPI == 2) {
                    float f0 = e0[idx], f1 = e0[idx + 1];
                    v0 = gelu_f(fmaf(e1[n], f0, v0)) + f0;
                    v1 = gelu_f(fmaf(e1[n + 1], f1, v1)) + f1;
                } else if (EPI == 3) {
                    v0 += e0[idx];
                    v1 += e0[idx + 1];
                }
                *reinterpret_cast<float2*>(Cc + idx) = make_float2(v0, v1);
            }
        }
    }
}

// ---------------- fp32 SGEMM (encoder only, K=64) ----------------------------
#define TBM 128
#define TBN 128
#define TBK 8
__global__ void __launch_bounds__(256)
sgemm_enc(const float* __restrict__ A, const float* __restrict__ B,
          float* __restrict__ C, int M, int N, int K,
          const float* __restrict__ bias) {
    __shared__ float As[TBK][TBM + 4];
    __shared__ float Bs[TBK][TBN + 4];
    const int tid = threadIdx.x;
    const int bm = blockIdx.y * TBM;
    const int bn = blockIdx.x * TBN;
    const int arow = tid >> 1, akc = (tid & 1) * 4;
    const float* Aptr = A + (size_t)(bm + arow) * K + akc;
    const int br0 = tid >> 5, bc0 = (tid & 31) * 4;
    const float* Bptr = B + (size_t)br0 * N + bn + bc0;

    float acc[8][8];
#pragma unroll
    for (int i = 0; i < 8; i++)
#pragma unroll
        for (int j = 0; j < 8; j++) acc[i][j] = 0.0f;

    float4 aR = *reinterpret_cast<const float4*>(Aptr);
    float4 bR = *reinterpret_cast<const float4*>(Bptr);
    const int tm = tid >> 4, tn = tid & 15;

    for (int k0 = 0;;) {
        As[akc + 0][arow] = aR.x; As[akc + 1][arow] = aR.y;
        As[akc + 2][arow] = aR.z; As[akc + 3][arow] = aR.w;
        Bs[br0][bc0 + 0] = bR.x;  Bs[br0][bc0 + 1] = bR.y;
        Bs[br0][bc0 + 2] = bR.z;  Bs[br0][bc0 + 3] = bR.w;
        __syncthreads();
        k0 += TBK;
        bool more = (k0 < K);
        if (more) {
            aR = *reinterpret_cast<const float4*>(Aptr + k0);
            bR = *reinterpret_cast<const float4*>(Bptr + (size_t)k0 * N);
        }
#pragma unroll
        for (int kk = 0; kk < TBK; kk++) {
            float4 a0 = *reinterpret_cast<const float4*>(&As[kk][tm * 4]);
            float4 a1 = *reinterpret_cast<const float4*>(&As[kk][64 + tm * 4]);
            float4 b0 = *reinterpret_cast<const float4*>(&Bs[kk][tn * 4]);
            float4 b1 = *reinterpret_cast<const float4*>(&Bs[kk][64 + tn * 4]);
            float av[8] = {a0.x, a0.y, a0.z, a0.w, a1.x, a1.y, a1.z, a1.w};
            float bv[8] = {b0.x, b0.y, b0.z, b0.w, b1.x, b1.y, b1.z, b1.w};
#pragma unroll
            for (int i = 0; i < 8; i++)
#pragma unroll
                for (int j = 0; j < 8; j++)
                    acc[i][j] = fmaf(av[i], bv[j], acc[i][j]);
        }
        __syncthreads();
        if (!more) break;
    }
#pragma unroll
    for (int i = 0; i < 8; i++) {
        int r = bm + ((i < 4) ? (tm * 4 + i) : (64 + tm * 4 + i - 4));
        size_t rowoff = (size_t)r * N;
#pragma unroll
        for (int j = 0; j < 8; j++) {
            int c = bn + ((j < 4) ? (tn * 4 + j) : (64 + tn * 4 + j - 4));
            C[rowoff + c] = acc[i][j] + bias[c];
        }
    }
}

// ---------------- per-layer weight prep --------------------------------------
__global__ void prep_lamb_k(const float* __restrict__ lam_re,
                            const float* __restrict__ lam_im,
                            const float* __restrict__ log_step) {
    int p = blockIdx.x * blockDim.x + threadIdx.x;
    if (p >= DM) return;
    float dt = expf(log_step[p]);
    float lr = lam_re[p], li = lam_im[p];
    float er = expf(lr * dt);
    float2 lb = make_float2(er * cosf(li * dt), er * sinf(li * dt));
    g_lamb[p] = lb;
    float nr = lb.x - 1.0f, ni = lb.y;
    float den = lr * lr + li * li;
    g_coef[p] = make_float2((nr * lr + ni * li) / den, (ni * lr - nr * li) / den);
}

__global__ void prep_W2_k(const float* __restrict__ b_re,
                          const float* __restrict__ b_im) {
    size_t idx = (size_t)blockIdx.x * blockDim.x + threadIdx.x;
    if (idx >= (size_t)DM * DM) return;
    int p = (int)(idx / DM), h = (int)(idx % DM);
    float2 c = g_coef[p];
    float br = b_re[idx], bi = b_im[idx];
    float vre = c.x * br - c.y * bi;
    float vim = c.x * bi + c.y * br;
    bf16 h1, l1, h2, l2;
    split_bf16(vre, h1, l1);
    split_bf16(vim, h2, l2);
    size_t r0 = (size_t)(2 * p) * DM + h;
    size_t r1 = (size_t)(2 * p + 1) * DM + h;
    g_W2h[r0] = h1; g_W2l[r0] = l1;
    g_W2h[r1] = h2; g_W2l[r1] = l2;
}

__global__ void prep_Cw_k(const float* __restrict__ c_re,
                          const float* __restrict__ c_im) {
    size_t idx = (size_t)blockIdx.x * blockDim.x + threadIdx.x;
    if (idx >= (size_t)DM * DM) return;
    int h = (int)(idx / DM), p = (int)(idx % DM);
    bf16 h1, l1, h2, l2;
    split_bf16(c_re[idx], h1, l1);
    split_bf16(-c_im[idx], h2, l2);
    bf162* ch = reinterpret_cast<bf162*>(g_Cwh);
    bf162* cl = reinterpret_cast<bf162*>(g_Cwl);
    bf162 vh; vh.x = h1; vh.y = h2;
    bf162 vl; vl.x = l1; vl.y = l2;
    ch[(size_t)h * DM + p] = vh;
    cl[(size_t)h * DM + p] = vl;
}

// transpose-split: in [R, C2] fp32 -> out [C2, R] bf16 hi/lo
__global__ void prep_trans_k(const float* __restrict__ in,
                             bf16* __restrict__ oh, bf16* __restrict__ ol,
                             int R, int C2) {
    __shared__ float t[32][33];
    int r = blockIdx.y * 32 + threadIdx.y;
    int c = blockIdx.x * 32 + threadIdx.x;
    t[threadIdx.y][threadIdx.x] = in[(size_t)r * C2 + c];
    __syncthreads();
    int orow = blockIdx.x * 32 + threadIdx.y;
    int ocol = blockIdx.y * 32 + threadIdx.x;
    float v = t[threadIdx.x][threadIdx.y];
    bf16 h, l;
    split_bf16(v, h, l);
    oh[(size_t)orow * R + ocol] = h;
    ol[(size_t)orow * R + ocol] = l;
}

// ---------------- scan: fp32 recurrence, bf16 hi/lo output -------------------
__global__ void scan_k(const float2* __restrict__ bu,
                       bf162* __restrict__ xh, bf162* __restrict__ xl) {
    int idx = blockIdx.x * blockDim.x + threadIdx.x;
    if (idx >= BATCH * DM) return;
    int b = idx >> 10, p = idx & (DM - 1);
    float2 a = g_lamb[p];
    const float2* ptr = bu + (size_t)b * SEQ * DM + p;
    bf162* oh = xh + (size_t)b * SEQ * DM + p;
    bf162* ol = xl + (size_t)b * SEQ * DM + p;
    float xr = 0.0f, xi = 0.0f;
    const int U = 8;
    float2 cur[U], nxt[U];
#pragma unroll
    for (int i = 0; i < U; i++) cur[i] = ptr[(size_t)i * DM];
#pragma unroll
    for (int i = 0; i < U; i++) nxt[i] = make_float2(0.f, 0.f);
    for (int l0 = 0; l0 < SEQ; l0 += U) {
        if (l0 + U < SEQ) {
#pragma unroll
            for (int i = 0; i < U; i++) nxt[i] = ptr[(size_t)(l0 + U + i) * DM];
        }
#pragma unroll
        for (int i = 0; i < U; i++) {
            float ur = cur[i].x, ui = cur[i].y;
            float nr = fmaf(a.x, xr, fmaf(-a.y, xi, ur));
            float ni = fmaf(a.x, xi, fmaf(a.y, xr, ui));
            xr = nr; xi = ni;
            bf16 hr = __float2bfloat16(xr);
            bf16 hi2 = __float2bfloat16(xi);
            bf162 vh; vh.x = hr; vh.y = hi2;
            bf162 vl;
            vl.x = __float2bfloat16(xr - __bfloat162float(hr));
            vl.y = __float2bfloat16(xi - __bfloat162float(hi2));
            oh[(size_t)(l0 + i) * DM] = vh;
            ol[(size_t)(l0 + i) * DM] = vl;
        }
#pragma unroll
        for (int i = 0; i < U; i++) cur[i] = nxt[i];
    }
}

// ---------------- LayerNorm (+optional residual add, +optional bf16 split) ---
__global__ void __launch_bounds__(128)
ln_k(const float* __restrict__ in, const float* __restrict__ add,
     float* __restrict__ out, bf16* __restrict__ oh, bf16* __restrict__ ol,
     const float* __restrict__ g, const float* __restrict__ bb) {
    __shared__ float red[8];
    size_t base = (size_t)blockIdx.x * DM;
    int t = threadIdx.x;
    float v[8];
    float s = 0.0f;
#pragma unroll
    for (int i = 0; i < 8; i++) {
        float xv = in[base + t + i * 128];
        if (add) xv += add[base + t + i * 128];
        v[i] = xv;
        s += xv;
    }
#pragma unroll
    for (int o = 16; o > 0; o >>= 1) s += __shfl_xor_sync(0xffffffffu, s, o);
    if ((t & 31) == 0) red[t >> 5] = s;
    __syncthreads();
    float mean = (red[0] + red[1] + red[2] + red[3]) * (1.0f / DM);
    float s2 = 0.0f;
#pragma unroll
    for (int i = 0; i < 8; i++) { float d = v[i] - mean; s2 += d * d; }
#pragma unroll
    for (int o = 16; o > 0; o >>= 1) s2 += __shfl_xor_sync(0xffffffffu, s2, o);
    if ((t & 31) == 0) red[4 + (t >> 5)] = s2;
    __syncthreads();
    float var = (red[4] + red[5] + red[6] + red[7]) * (1.0f / DM);
    float inv = rsqrtf(var + 1e-5f);
#pragma unroll
    for (int i = 0; i < 8; i++) {
        int c = t + i * 128;
        float y = (v[i] - mean) * inv * g[c] + bb[c];
        out[base + c] = y;
        if (oh) {
            bf16 h, l;
            split_bf16(y, h, l);
            oh[base + c] = h;
            ol[base + c] = l;
        }
    }
}

// ---------------- GEGLU -> bf16 hi/lo ----------------------------------------
__global__ void geglu_k(const float* __restrict__ u2,
                        bf16* __restrict__ gh, bf16* __restrict__ gl) {
    size_t i = (size_t)blockIdx.x * blockDim.x + threadIdx.x;
    if (i >= (size_t)MROWS * DM) return;
    size_t m = i >> 10;
    int c = (int)(i & (DM - 1));
    float a = u2[m * (2 * DM) + c];
    float gg = u2[m * (2 * DM) + DM + c];
    float v = a * gelu_f(gg);
    bf16 h, l;
    split_bf16(v, h, l);
    gh[i] = h;
    gl[i] = l;
}

// ---------------- mean pool + decode -----------------------------------------
__global__ void pool_k(const float* __restrict__ h, float* __restrict__ pooled) {
    int idx = blockIdx.x * blockDim.x + threadIdx.x;
    if (idx >= BATCH * DM) return;
    int b = idx >> 10, d = idx & (DM - 1);
    const float* p = h + (size_t)b * SEQ * DM + d;
    float s = 0.0f;
#pragma unroll 8
    for (int l = 0; l < SEQ; l++) s += p[(size_t)l * DM];
    pooled[idx] = s * (1.0f / SEQ);
}

__global__ void dec_k(const float* __restrict__ pooled,
                      const float* __restrict__ w,
                      const float* __restrict__ b,
                      float* __restrict__ out) {
    __shared__ float red[8];
    int bi = blockIdx.x;
    int t = threadIdx.x;
    float s = 0.0f;
    for (int d = t; d < DM; d += 256) s += pooled[bi * DM + d] * w[d];
#pragma unroll
    for (int o = 16; o > 0; o >>= 1) s += __shfl_xor_sync(0xffffffffu, s, o);
    if ((t & 31) == 0) red[t >> 5] = s;
    __syncthreads();
    if (t == 0) {
        float tot = 0.0f;
#pragma unroll
        for (int i = 0; i < 8; i++) tot += red[i];
        out[bi] = tot + b[0];
    }
}

// ---------------- driver ----------------
extern "C" void kernel_launch(void* const* d_in, const int* in_sizes, int n_in,
                              void* d_out, int out_size) {
    const float* x        = (const float*)d_in[0];
    const float* enc_w    = (const float*)d_in[1];
    const float* enc_b    = (const float*)d_in[2];
    const float* ln1_g    = (const float*)d_in[3];
    const float* ln1_b    = (const float*)d_in[4];
    const float* lam_re   = (const float*)d_in[5];
    const float* lam_im   = (const float*)d_in[6];
    const float* b_re     = (const float*)d_in[7];
    const float* b_im     = (const float*)d_in[8];
    const float* c_re     = (const float*)d_in[9];
    const float* c_im     = (const float*)d_in[10];
    const float* d_skip   = (const float*)d_in[11];
    const float* log_step = (const float*)d_in[12];
    const float* ffn_g    = (const float*)d_in[13];
    const float* ffn_b    = (const float*)d_in[14];
    const float* ff_enc_w = (const float*)d_in[15];
    const float* ff_dec_w = (const float*)d_in[16];
    const float* norm_g   = (const float*)d_in[17];
    const float* norm_b   = (const float*)d_in[18];
    const float* dec_w    = (const float*)d_in[19];
    const float* dec_b    = (const float*)d_in[20];
    float* out = (float*)d_out;

    static int attr_done = 0;
    if (!attr_done) {
        cudaFuncSetAttribute(hmma_gemm<0>, cudaFuncAttributeMaxDynamicSharedMemorySize, SMEM_GEMM);
        cudaFuncSetAttribute(hmma_gemm<2>, cudaFuncAttributeMaxDynamicSharedMemorySize, SMEM_GEMM);
        cudaFuncSetAttribute(hmma_gemm<3>, cudaFuncAttributeMaxDynamicSharedMemorySize, SMEM_GEMM);
        attr_done = 1;
    }

    float *p_h, *p_fx, *p_fy, *p_z, *p_big, *p_pooled;
    bf16 *p_fxh, *p_fxl, *p_xsh, *p_xsl, *p_fyh, *p_fyl, *p_ggh, *p_ggl;
    bf16 *p_W2h, *p_W2l, *p_Cwh, *p_Cwl, *p_feh, *p_fel, *p_fdh, *p_fdl;
    cudaGetSymbolAddress((void**)&p_h, g_h);
    cudaGetSymbolAddress((void**)&p_fx, g_fx);
    cudaGetSymbolAddress((void**)&p_fy, g_fy);
    cudaGetSymbolAddress((void**)&p_z, g_z);
    cudaGetSymbolAddress((void**)&p_big, g_big);
    cudaGetSymbolAddress((void**)&p_pooled, g_pooled);
    cudaGetSymbolAddress((void**)&p_fxh, g_fxh);
    cudaGetSymbolAddress((void**)&p_fxl, g_fxl);
    cudaGetSymbolAddress((void**)&p_xsh, g_xsh);
    cudaGetSymbolAddress((void**)&p_xsl, g_xsl);
    cudaGetSymbolAddress((void**)&p_fyh, g_fyh);
    cudaGetSymbolAddress((void**)&p_fyl, g_fyl);
    cudaGetSymbolAddress((void**)&p_ggh, g_ggh);
    cudaGetSymbolAddress((void**)&p_ggl, g_ggl);
    cudaGetSymbolAddress((void**)&p_W2h, g_W2h);
    cudaGetSymbolAddress((void**)&p_W2l, g_W2l);
    cudaGetSymbolAddress((void**)&p_Cwh, g_Cwh);
    cudaGetSymbolAddress((void**)&p_Cwl, g_Cwl);
    cudaGetSymbolAddress((void**)&p_feh, g_feh);
    cudaGetSymbolAddress((void**)&p_fel, g_fel);
    cudaGetSymbolAddress((void**)&p_fdh, g_fdh);
    cudaGetSymbolAddress((void**)&p_fdl, g_fdl);

    const int M = MROWS;

    // launch #1: encoder h = x @ enc_w + enc_b  (fp32, K=64)
    sgemm_enc<<<dim3(DM / TBN, M / TBM), 256>>>(x, enc_w, p_h, M, DM, D_IN, enc_b);

    for (int i = 0; i < NL; i++) {
        const size_t w1 = (size_t)i * DM;
        const size_t w2 = (size_t)i * DM * DM;
        const size_t w3 = (size_t)i * DM * 2 * DM;

        // ordered so the first hmma_gemm (Bu) is the 6th launch overall
        // (ncu -s 5 -c 1 captures it)
        prep_lamb_k<<<(DM + 127) / 128, 128>>>(lam_re + w1, lam_im + w1, log_step + w1);  // #2
        prep_W2_k<<<(DM * DM + 255) / 256, 256>>>(b_re + w2, b_im + w2);                   // #3
        // fx = LN(h)  (+ split)                                                            #4
        ln_k<<<M, 128>>>(p_h, nullptr, p_fx, p_fxh, p_fxl, ln1_g + w1, ln1_b + w1);
        prep_Cw_k<<<(DM * DM + 255) / 256, 256>>>(c_re + w2, c_im + w2);                   // #5
        // Bu = fx @ W2^T  [M, 2P] fp32 (interleaved re/im)                                 #6
        hmma_gemm<0><<<dim3(2 * DM / 256, M / 128), 256, SMEM_GEMM>>>(
            p_fxh, p_fxl, p_W2h, p_W2l, p_big, 2 * DM, DM, nullptr, nullptr);
        // complex recurrence -> xs (bf16 hi/lo)
        scan_k<<<(BATCH * DM) / 128, 128>>>((const float2*)p_big,
                                            (bf162*)p_xsh, (bf162*)p_xsl);
        // z = gelu(xs @ Cw^T + d*fx) + fx
        hmma_gemm<2><<<dim3(DM / 256, M / 128), 256, SMEM_GEMM>>>(
            p_xsh, p_xsl, p_Cwh, p_Cwl, p_z, DM, 2 * DM, p_fx, d_skip + w1);
        prep_trans_k<<<dim3(2 * DM / 32, DM / 32), dim3(32, 32)>>>(
            ff_enc_w + w3, p_feh, p_fel, DM, 2 * DM);
        // fy = LN(z)  (+ split)
        ln_k<<<M, 128>>>(p_z, nullptr, p_fy, p_fyh, p_fyl, ffn_g + w1, ffn_b + w1);
        // u2 = fy @ ff_enc_w  [M, 2D]
        hmma_gemm<0><<<dim3(2 * DM / 256, M / 128), 256, SMEM_GEMM>>>(
            p_fyh, p_fyl, p_feh, p_fel, p_big, 2 * DM, DM, nullptr, nullptr);
        // geglu -> gg (bf16 hi/lo)
        geglu_k<<<(int)(((size_t)M * DM + 255) / 256), 256>>>(p_big, p_ggh, p_ggl);
        prep_trans_k<<<dim3(DM / 32, DM / 32), dim3(32, 32)>>>(
            ff_dec_w + w2, p_fdh, p_fdl, DM, DM);
        // z2 = gg @ ff_dec_w + fy   (into p_z)
        hmma_gemm<3><<<dim3(DM / 256, M / 128), 256, SMEM_GEMM>>>(
            p_ggh, p_ggl, p_fdh, p_fdl, p_z, DM, DM, p_fy, nullptr);
        // h = LN(z2 + h)
        ln_k<<<M, 128>>>(p_z, p_h, p_h, nullptr, nullptr, norm_g + w1, norm_b + w1);
    }

    pool_k<<<(BATCH * DM) / 128, 128>>>(p_h, p_pooled);
    dec_k<<<BATCH, 256>>>(p_pooled, dec_w, dec_b, out);
}

// round 7
// speedup vs baseline: 2.9400x; 1.4253x over previous
#include <cuda_runtime.h>
#include <cuda_bf16.h>
#include <math.h>
#include <stdint.h>

// ---------------- problem constants ----------------
#define BATCH   8
#define SEQ     2048
#define D_IN    64
#define DM      1024
#define DM2     2048
#define NL      4
#define MROWS   (BATCH*SEQ)   // 16384

// ---------------- scratch (device globals) ----------------
__device__ float g_h  [(size_t)MROWS * DM];
__device__ float g_fx [(size_t)MROWS * DM];
__device__ float g_fy [(size_t)MROWS * DM];
__device__ float g_z  [(size_t)MROWS * DM];
__device__ float g_big[(size_t)MROWS * DM2];     // bu -> xs (in place) ; then u2
__device__ float g_wtmp[(size_t)DM2 * DM];       // transposed weight staging

__device__ __align__(16) int8_t g_fxq1[(size_t)MROWS * DM];
__device__ __align__(16) int8_t g_fxq2[(size_t)MROWS * DM];
__device__ __align__(16) int8_t g_xsq1[(size_t)MROWS * DM2];
__device__ __align__(16) int8_t g_xsq2[(size_t)MROWS * DM2];
__device__ __align__(16) int8_t g_fyq1[(size_t)MROWS * DM];
__device__ __align__(16) int8_t g_fyq2[(size_t)MROWS * DM];
__device__ __align__(16) int8_t g_ggq1[(size_t)MROWS * DM];
__device__ __align__(16) int8_t g_ggq2[(size_t)MROWS * DM];

__device__ __align__(16) int8_t g_W2q1[(size_t)DM2 * DM];
__device__ __align__(16) int8_t g_W2q2[(size_t)DM2 * DM];
__device__ __align__(16) int8_t g_Cwq1[(size_t)DM * DM2];
__device__ __align__(16) int8_t g_Cwq2[(size_t)DM * DM2];
__device__ __align__(16) int8_t g_feq1[(size_t)DM2 * DM];
__device__ __align__(16) int8_t g_feq2[(size_t)DM2 * DM];
__device__ __align__(16) int8_t g_fdq1[(size_t)DM * DM];
__device__ __align__(16) int8_t g_fdq2[(size_t)DM * DM];

__device__ float g_sfx[MROWS], g_sxs[MROWS], g_sfy[MROWS], g_sgg[MROWS];
__device__ float g_sW2[DM2], g_sCw[DM], g_sfe[DM2], g_sfd[DM];

__device__ float2 g_lamb[DM];
__device__ float2 g_coef[DM];
__device__ float  g_chs [DM];    // channel flattening scale (mult into Cw)
__device__ float  g_chsi[DM];    // inverse (mult into xs)
__device__ float  g_pooled[BATCH * DM];

// ---------------- helpers ----------------
__device__ __forceinline__ float gelu_f(float x) {
    return 0.5f * x * (1.0f + erff(x * 0.70710678118654752f));
}
__device__ __forceinline__ uint32_t s2u(const void* p) {
    uint32_t a;
    asm("{ .reg .u64 t; cvta.to.shared.u64 t, %1; cvt.u32.u64 %0, t; }"
        : "=r"(a) : "l"(p));
    return a;
}
__device__ __forceinline__ void cpasync16(uint32_t s, const void* g) {
    asm volatile("cp.async.cg.shared.global [%0], [%1], 16;" :: "r"(s), "l"(g));
}
__device__ __forceinline__ void ldsm_x4(uint32_t* r, uint32_t addr) {
    asm volatile("ldmatrix.sync.aligned.m8n8.x4.shared.b16 {%0,%1,%2,%3}, [%4];"
                 : "=r"(r[0]), "=r"(r[1]), "=r"(r[2]), "=r"(r[3]) : "r"(addr));
}
__device__ __forceinline__ void mma_s8(int* d, const uint32_t* a,
                                       uint32_t b0, uint32_t b1) {
    asm volatile(
        "mma.sync.aligned.m16n8k32.row.col.s32.s8.s8.s32 "
        "{%0,%1,%2,%3}, {%4,%5,%6,%7}, {%8,%9}, {%0,%1,%2,%3};"
        : "+r"(d[0]), "+r"(d[1]), "+r"(d[2]), "+r"(d[3])
        : "r"(a[0]), "r"(a[1]), "r"(a[2]), "r"(a[3]), "r"(b0), "r"(b1));
}
__device__ __forceinline__ void quant2(float v, float qs, int8_t& o1, int8_t& o2) {
    float t = v * qs;
    int q1 = __float2int_rn(t);
    int q2 = __float2int_rn((t - (float)q1) * 252.0f);
    o1 = (int8_t)q1;
    o2 = (int8_t)q2;
}

// ---------------- IMMA split-int8 GEMM: C[M,N] = sA.sB.(A @ B^T) -------------
// CTA 128x128, warp tile 64x32 (2m x 4n warps). K-chunk 64; smem row = 128B:
// [q1 64B | q2 64B], XOR swizzle. 4-stage cp.async. Per k32 step: 3 passes
// (q1q1 -> acc1; q2q1, q1q2 -> accX). Dequant: sA[m]*sB[n]*(acc1 + accX/252).
// EPI 0: plain  2: gelu(v + e1[n]*e0[m,n]) + e0[m,n]  3: v + e0[m,n]
#define STAGE_B   32768
#define NSTAGE    4
#define SMEM_GEMM (NSTAGE * STAGE_B)

template <int EPI>
__global__ void __launch_bounds__(256, 1)
imma_gemm(const int8_t* __restrict__ Aq1, const int8_t* __restrict__ Aq2,
          const int8_t* __restrict__ Bq1, const int8_t* __restrict__ Bq2,
          float* __restrict__ Cc, int N, int K,
          const float* __restrict__ sA, const float* __restrict__ sB,
          const float* __restrict__ e0, const float* __restrict__ e1) {
    extern __shared__ __align__(128) char smem[];
    const int tid = threadIdx.x;
    const int wid = tid >> 5;
    const int lid = tid & 31;
    const int wm = wid & 1;          // 2 warps along M (64 rows each)
    const int wn = wid >> 1;         // 4 warps along N (32 cols each)
    const int bm = blockIdx.y * 128;
    const int bn = blockIdx.x * 128;
    const uint32_t sbase = s2u(smem);
    const int nch = K >> 6;

    auto load_stage = [&](int st, int c) {
        const int kc = c << 6;
        const uint32_t stb = sbase + st * STAGE_B;
#pragma unroll
        for (int t = 0; t < 8; ++t) {
            int i = tid + t * 256;            // 0..2047
            int isB = (i >= 1024);
            int ii = i & 1023;
            int row = ii >> 3, j = ii & 7;
            const int8_t* src = isB ? ((j < 4) ? Bq1 : Bq2)
                                    : ((j < 4) ? Aq1 : Aq2);
            size_t go = (size_t)((isB ? bn : bm) + row) * K + kc + (j & 3) * 16;
            uint32_t dst = stb + (isB ? 16384u : 0u) + row * 128 +
                           (uint32_t)((j ^ (row & 7)) << 4);
            cpasync16(dst, src + go);
        }
    };

    int acc1[4][4][4], accX[4][4][4];
#pragma unroll
    for (int mt = 0; mt < 4; mt++)
#pragma unroll
        for (int nt = 0; nt < 4; nt++)
#pragma unroll
            for (int q = 0; q < 4; q++) { acc1[mt][nt][q] = 0; accX[mt][nt][q] = 0; }

    load_stage(0, 0); asm volatile("cp.async.commit_group;" ::: "memory");
    load_stage(1, 1); asm volatile("cp.async.commit_group;" ::: "memory");
    load_stage(2, 2); asm volatile("cp.async.commit_group;" ::: "memory");

    // ldmatrix lane mapping (identical for A tiles and B tile-pairs):
    // row = base + (lid & 15), c16-unit = +(lid >> 4)
    const int a_row = wm * 64 + (lid & 15);
    const int b_row = wn * 32 + (lid & 15);
    const int lc = lid >> 4;

    for (int c = 0; c < nch; ++c) {
        const int wg = nch - 1 - c;
        if (wg >= 2)      asm volatile("cp.async.wait_group 2;" ::: "memory");
        else if (wg == 1) asm volatile("cp.async.wait_group 1;" ::: "memory");
        else              asm volatile("cp.async.wait_group 0;" ::: "memory");
        __syncthreads();

        if (c + 3 < nch) load_stage((c + 3) & 3, c + 3);
        asm volatile("cp.async.commit_group;" ::: "memory");

        const uint32_t smA = sbase + (c & 3) * STAGE_B;
        const uint32_t smB = smA + 16384;
#pragma unroll
        for (int ks = 0; ks < 2; ++ks) {
            uint32_t aq1[4][4], aq2[4][4], bb[2][4];
#pragma unroll
            for (int mt = 0; mt < 4; ++mt) {
                int row = a_row + mt * 16;
                int c1 = ks * 2 + lc;
                int c2 = 4 + ks * 2 + lc;
                ldsm_x4(aq1[mt], smA + row * 128 + ((c1 ^ (row & 7)) << 4));
                ldsm_x4(aq2[mt], smA + row * 128 + ((c2 ^ (row & 7)) << 4));
            }
            // B q1: pass q1q1 -> acc1, q2q1 -> accX
#pragma unroll
            for (int pp = 0; pp < 2; ++pp) {
                int row = b_row + pp * 16;
                int c1 = ks * 2 + lc;
                ldsm_x4(bb[pp], smB + row * 128 + ((c1 ^ (row & 7)) << 4));
            }
#pragma unroll
            for (int mt = 0; mt < 4; ++mt)
#pragma unroll
                for (int pp = 0; pp < 2; ++pp) {
                    mma_s8(acc1[mt][2 * pp],     aq1[mt], bb[pp][0], bb[pp][2]);
                    mma_s8(acc1[mt][2 * pp + 1], aq1[mt], bb[pp][1], bb[pp][3]);
                    mma_s8(accX[mt][2 * pp],     aq2[mt], bb[pp][0], bb[pp][2]);
                    mma_s8(accX[mt][2 * pp + 1], aq2[mt], bb[pp][1], bb[pp][3]);
                }
            // B q2: pass q1q2 -> accX
#pragma unroll
            for (int pp = 0; pp < 2; ++pp) {
                int row = b_row + pp * 16;
                int c2 = 4 + ks * 2 + lc;
                ldsm_x4(bb[pp], smB + row * 128 + ((c2 ^ (row & 7)) << 4));
            }
#pragma unroll
            for (int mt = 0; mt < 4; ++mt)
#pragma unroll
                for (int pp = 0; pp < 2; ++pp) {
                    mma_s8(accX[mt][2 * pp],     aq1[mt], bb[pp][0], bb[pp][2]);
                    mma_s8(accX[mt][2 * pp + 1], aq1[mt], bb[pp][1], bb[pp][3]);
                }
        }
        __syncthreads();
    }

    const int tr = lid >> 2;
    const int tc = (lid & 3) * 2;
    const float ix = 1.0f / 252.0f;
#pragma unroll
    for (int mt = 0; mt < 4; ++mt) {
#pragma unroll
        for (int half = 0; half < 2; ++half) {
            const int m = bm + wm * 64 + mt * 16 + tr + half * 8;
            const size_t rowoff = (size_t)m * N;
            const float sa = sA[m];
#pragma unroll
            for (int nt = 0; nt < 4; ++nt) {
                const int n = bn + wn * 32 + nt * 8 + tc;
                float v0 = (__int2float_rn(acc1[mt][nt][half * 2 + 0]) +
                            __int2float_rn(accX[mt][nt][half * 2 + 0]) * ix) *
                           sa * sB[n];
                float v1 = (__int2float_rn(acc1[mt][nt][half * 2 + 1]) +
                            __int2float_rn(accX[mt][nt][half * 2 + 1]) * ix) *
                           sa * sB[n + 1];
                const size_t idx = rowoff + n;
                if (EPI == 2) {
                    float f0 = e0[idx], f1 = e0[idx + 1];
                    v0 = gelu_f(fmaf(e1[n], f0, v0)) + f0;
                    v1 = gelu_f(fmaf(e1[n + 1], f1, v1)) + f1;
                } else if (EPI == 3) {
                    v0 += e0[idx];
                    v1 += e0[idx + 1];
                }
                *reinterpret_cast<float2*>(Cc + idx) = make_float2(v0, v1);
            }
        }
    }
}

// ---------------- fp32 SGEMM (encoder only, K=64) ----------------------------
#define TBM 128
#define TBN 128
#define TBK 8
__global__ void __launch_bounds__(256)
sgemm_enc(const float* __restrict__ A, const float* __restrict__ B,
          float* __restrict__ C, int M, int N, int K,
          const float* __restrict__ bias) {
    __shared__ float As[TBK][TBM + 4];
    __shared__ float Bs[TBK][TBN + 4];
    const int tid = threadIdx.x;
    const int bm = blockIdx.y * TBM;
    const int bn = blockIdx.x * TBN;
    const int arow = tid >> 1, akc = (tid & 1) * 4;
    const float* Aptr = A + (size_t)(bm + arow) * K + akc;
    const int br0 = tid >> 5, bc0 = (tid & 31) * 4;
    const float* Bptr = B + (size_t)br0 * N + bn + bc0;

    float acc[8][8];
#pragma unroll
    for (int i = 0; i < 8; i++)
#pragma unroll
        for (int j = 0; j < 8; j++) acc[i][j] = 0.0f;

    float4 aR = *reinterpret_cast<const float4*>(Aptr);
    float4 bR = *reinterpret_cast<const float4*>(Bptr);
    const int tm = tid >> 4, tn = tid & 15;

    for (int k0 = 0;;) {
        As[akc + 0][arow] = aR.x; As[akc + 1][arow] = aR.y;
        As[akc + 2][arow] = aR.z; As[akc + 3][arow] = aR.w;
        Bs[br0][bc0 + 0] = bR.x;  Bs[br0][bc0 + 1] = bR.y;
        Bs[br0][bc0 + 2] = bR.z;  Bs[br0][bc0 + 3] = bR.w;
        __syncthreads();
        k0 += TBK;
        bool more = (k0 < K);
        if (more) {
            aR = *reinterpret_cast<const float4*>(Aptr + k0);
            bR = *reinterpret_cast<const float4*>(Bptr + (size_t)k0 * N);
        }
#pragma unroll
        for (int kk = 0; kk < TBK; kk++) {
            float4 a0 = *reinterpret_cast<const float4*>(&As[kk][tm * 4]);
            float4 a1 = *reinterpret_cast<const float4*>(&As[kk][64 + tm * 4]);
            float4 b0 = *reinterpret_cast<const float4*>(&Bs[kk][tn * 4]);
            float4 b1 = *reinterpret_cast<const float4*>(&Bs[kk][64 + tn * 4]);
            float av[8] = {a0.x, a0.y, a0.z, a0.w, a1.x, a1.y, a1.z, a1.w};
            float bv[8] = {b0.x, b0.y, b0.z, b0.w, b1.x, b1.y, b1.z, b1.w};
#pragma unroll
            for (int i = 0; i < 8; i++)
#pragma unroll
                for (int j = 0; j < 8; j++)
                    acc[i][j] = fmaf(av[i], bv[j], acc[i][j]);
        }
        __syncthreads();
        if (!more) break;
    }
#pragma unroll
    for (int i = 0; i < 8; i++) {
        int r = bm + ((i < 4) ? (tm * 4 + i) : (64 + tm * 4 + i - 4));
        size_t rowoff = (size_t)r * N;
#pragma unroll
        for (int j = 0; j < 8; j++) {
            int c = bn + ((j < 4) ? (tn * 4 + j) : (64 + tn * 4 + j - 4));
            C[rowoff + c] = acc[i][j] + bias[c];
        }
    }
}

// ---------------- per-layer weight prep --------------------------------------
__global__ void prep_lamb_k(const float* __restrict__ lam_re,
                            const float* __restrict__ lam_im,
                            const float* __restrict__ log_step) {
    int p = blockIdx.x * blockDim.x + threadIdx.x;
    if (p >= DM) return;
    float dt = expf(log_step[p]);
    float lr = lam_re[p], li = lam_im[p];
    float er = expf(lr * dt);
    float2 lb = make_float2(er * cosf(li * dt), er * sinf(li * dt));
    g_lamb[p] = lb;
    float nr = lb.x - 1.0f, ni = lb.y;
    float den = lr * lr + li * li;
    g_coef[p] = make_float2((nr * lr + ni * li) / den, (ni * lr - nr * li) / den);
    // channel flattening: expected scan gain ~ 1/sqrt(1-|lam_bar|^2)
    float mag2 = lb.x * lb.x + lb.y * lb.y;
    float s = rsqrtf(fmaxf(1.0f - mag2, 1e-6f));
    s = fminf(fmaxf(s, 1.0f), 1000.0f);
    g_chs[p] = s;
    g_chsi[p] = 1.0f / s;
}

// W2 rows (2p = re, 2p+1 = im): quantize per row. Block per p, 256 threads.
__global__ void __launch_bounds__(256)
prep_W2q_k(const float* __restrict__ b_re, const float* __restrict__ b_im) {
    __shared__ float redA[8], redB[8];
    const int p = blockIdx.x;
    const int tid = threadIdx.x;
    float2 c2 = g_coef[p];
    float vre[4], vim[4];
    float amr = 0.0f, ami = 0.0f;
#pragma unroll
    for (int k = 0; k < 4; ++k) {
        int h = tid + k * 256;
        float br = b_re[(size_t)p * DM + h];
        float bi = b_im[(size_t)p * DM + h];
        vre[k] = c2.x * br - c2.y * bi;
        vim[k] = c2.x * bi + c2.y * br;
        amr = fmaxf(amr, fabsf(vre[k]));
        ami = fmaxf(ami, fabsf(vim[k]));
    }
#pragma unroll
    for (int o = 16; o > 0; o >>= 1) {
        amr = fmaxf(amr, __shfl_xor_sync(0xffffffffu, amr, o));
        ami = fmaxf(ami, __shfl_xor_sync(0xffffffffu, ami, o));
    }
    if ((tid & 31) == 0) { redA[tid >> 5] = amr; redB[tid >> 5] = ami; }
    __syncthreads();
    amr = redA[0]; ami = redB[0];
#pragma unroll
    for (int i = 1; i < 8; ++i) { amr = fmaxf(amr, redA[i]); ami = fmaxf(ami, redB[i]); }
    float qr = amr > 0 ? 127.0f / amr : 0.0f;
    float qi = ami > 0 ? 127.0f / ami : 0.0f;
#pragma unroll
    for (int k = 0; k < 4; ++k) {
        int h = tid + k * 256;
        int8_t a, b;
        quant2(vre[k], qr, a, b);
        g_W2q1[(size_t)(2 * p) * DM + h] = a;
        g_W2q2[(size_t)(2 * p) * DM + h] = b;
        quant2(vim[k], qi, a, b);
        g_W2q1[(size_t)(2 * p + 1) * DM + h] = a;
        g_W2q2[(size_t)(2 * p + 1) * DM + h] = b;
    }
    if (tid == 0) {
        g_sW2[2 * p]     = amr * (1.0f / 127.0f);
        g_sW2[2 * p + 1] = ami * (1.0f / 127.0f);
    }
}

// Cw rows (h): interleaved re/-im * channel scale. Block per h, 256 threads.
__global__ void __launch_bounds__(256)
prep_Cwq_k(const float* __restrict__ c_re, const float* __restrict__ c_im) {
    __shared__ float red[8];
    const int h = blockIdx.x;
    const int tid = threadIdx.x;
    float v[8];
    float am = 0.0f;
#pragma unroll
    for (int k = 0; k < 8; ++k) {
        int j = tid + k * 256;
        int p = j >> 1;
        float cv = (j & 1) ? -c_im[(size_t)h * DM + p] : c_re[(size_t)h * DM + p];
        cv *= g_chs[p];
        v[k] = cv;
        am = fmaxf(am, fabsf(cv));
    }
#pragma unroll
    for (int o = 16; o > 0; o >>= 1) am = fmaxf(am, __shfl_xor_sync(0xffffffffu, am, o));
    if ((tid & 31) == 0) red[tid >> 5] = am;
    __syncthreads();
    am = red[0];
#pragma unroll
    for (int i = 1; i < 8; ++i) am = fmaxf(am, red[i]);
    float qs = am > 0 ? 127.0f / am : 0.0f;
#pragma unroll
    for (int k = 0; k < 8; ++k) {
        int j = tid + k * 256;
        int8_t a, b;
        quant2(v[k], qs, a, b);
        g_Cwq1[(size_t)h * DM2 + j] = a;
        g_Cwq2[(size_t)h * DM2 + j] = b;
    }
    if (tid == 0) g_sCw[h] = am * (1.0f / 127.0f);
}

// fp32 transpose: in [R][C2] -> out [C2][R]
__global__ void wtrans_k(const float* __restrict__ in, float* __restrict__ outT,
                         int R, int C2) {
    __shared__ float t[32][33];
    int r = blockIdx.y * 32 + threadIdx.y;
    int c = blockIdx.x * 32 + threadIdx.x;
    t[threadIdx.y][threadIdx.x] = in[(size_t)r * C2 + c];
    __syncthreads();
    int orow = blockIdx.x * 32 + threadIdx.y;
    int ocol = blockIdx.y * 32 + threadIdx.x;
    outT[(size_t)orow * R + ocol] = t[threadIdx.x][threadIdx.y];
}

// generic row quantizer: W = CNT*256 elements per row; optional channel scale
template <int CNT, bool CHS>
__global__ void __launch_bounds__(256)
rowq_k(const float* __restrict__ in, int8_t* __restrict__ q1,
       int8_t* __restrict__ q2, float* __restrict__ sOut) {
    __shared__ float red[8];
    const size_t base = (size_t)blockIdx.x * (CNT * 256);
    const int tid = threadIdx.x;
    float v[CNT];
    float am = 0.0f;
#pragma unroll
    for (int k = 0; k < CNT; ++k) {
        int c = tid + k * 256;
        float x = in[base + c];
        if (CHS) x *= g_chsi[c >> 1];
        v[k] = x;
        am = fmaxf(am, fabsf(x));
    }
#pragma unroll
    for (int o = 16; o > 0; o >>= 1) am = fmaxf(am, __shfl_xor_sync(0xffffffffu, am, o));
    if ((tid & 31) == 0) red[tid >> 5] = am;
    __syncthreads();
    am = red[0];
#pragma unroll
    for (int i = 1; i < 8; ++i) am = fmaxf(am, red[i]);
    float qs = am > 0 ? 127.0f / am : 0.0f;
#pragma unroll
    for (int k = 0; k < CNT; ++k) {
        int c = tid + k * 256;
        int8_t a, b;
        quant2(v[k], qs, a, b);
        q1[base + c] = a;
        q2[base + c] = b;
    }
    if (tid == 0) sOut[blockIdx.x] = am * (1.0f / 127.0f);
}

// ---------------- scan: fp32 recurrence, in-place ----------------------------
__global__ void scan_k(float2* __restrict__ bu) {
    int idx = blockIdx.x * blockDim.x + threadIdx.x;
    if (idx >= BATCH * DM) return;
    int b = idx >> 10, p = idx & (DM - 1);
    float2 a = g_lamb[p];
    float2* ptr = bu + (size_t)b * SEQ * DM + p;
    float xr = 0.0f, xi = 0.0f;
    const int U = 8;
    float2 cur[U], nxt[U];
#pragma unroll
    for (int i = 0; i < U; i++) cur[i] = ptr[(size_t)i * DM];
#pragma unroll
    for (int i = 0; i < U; i++) nxt[i] = make_float2(0.f, 0.f);
    for (int l0 = 0; l0 < SEQ; l0 += U) {
        if (l0 + U < SEQ) {
#pragma unroll
            for (int i = 0; i < U; i++) nxt[i] = ptr[(size_t)(l0 + U + i) * DM];
        }
#pragma unroll
        for (int i = 0; i < U; i++) {
            float ur = cur[i].x, ui = cur[i].y;
            float nr = fmaf(a.x, xr, fmaf(-a.y, xi, ur));
            float ni = fmaf(a.x, xi, fmaf(a.y, xr, ui));
            xr = nr; xi = ni;
            ptr[(size_t)(l0 + i) * DM] = make_float2(xr, xi);
        }
#pragma unroll
        for (int i = 0; i < U; i++) cur[i] = nxt[i];
    }
}

// ---------------- LayerNorm (+optional residual add, +optional int8 quant) ---
__global__ void __launch_bounds__(128)
ln_k(const float* __restrict__ in, const float* __restrict__ add,
     float* __restrict__ out, int8_t* __restrict__ q1, int8_t* __restrict__ q2,
     float* __restrict__ sOut,
     const float* __restrict__ g, const float* __restrict__ bb) {
    __shared__ float red[8];
    __shared__ float redm[4];
    size_t base = (size_t)blockIdx.x * DM;
    int t = threadIdx.x;
    float v[8];
    float s = 0.0f;
#pragma unroll
    for (int i = 0; i < 8; i++) {
        float xv = in[base + t + i * 128];
        if (add) xv += add[base + t + i * 128];
        v[i] = xv;
        s += xv;
    }
#pragma unroll
    for (int o = 16; o > 0; o >>= 1) s += __shfl_xor_sync(0xffffffffu, s, o);
    if ((t & 31) == 0) red[t >> 5] = s;
    __syncthreads();
    float mean = (red[0] + red[1] + red[2] + red[3]) * (1.0f / DM);
    float s2 = 0.0f;
#pragma unroll
    for (int i = 0; i < 8; i++) { float d = v[i] - mean; s2 += d * d; }
#pragma unroll
    for (int o = 16; o > 0; o >>= 1) s2 += __shfl_xor_sync(0xffffffffu, s2, o);
    if ((t & 31) == 0) red[4 + (t >> 5)] = s2;
    __syncthreads();
    float var = (red[4] + red[5] + red[6] + red[7]) * (1.0f / DM);
    float inv = rsqrtf(var + 1e-5f);
    float y[8];
    float am = 0.0f;
#pragma unroll
    for (int i = 0; i < 8; i++) {
        int c = t + i * 128;
        y[i] = (v[i] - mean) * inv * g[c] + bb[c];
        out[base + c] = y[i];
        am = fmaxf(am, fabsf(y[i]));
    }
    if (q1) {
#pragma unroll
        for (int o = 16; o > 0; o >>= 1) am = fmaxf(am, __shfl_xor_sync(0xffffffffu, am, o));
        if ((t & 31) == 0) redm[t >> 5] = am;
        __syncthreads();
        am = fmaxf(fmaxf(redm[0], redm[1]), fmaxf(redm[2], redm[3]));
        float qs = am > 0 ? 127.0f / am : 0.0f;
#pragma unroll
        for (int i = 0; i < 8; i++) {
            int c = t + i * 128;
            int8_t a, b;
            quant2(y[i], qs, a, b);
            q1[base + c] = a;
            q2[base + c] = b;
        }
        if (t == 0) sOut[blockIdx.x] = am * (1.0f / 127.0f);
    }
}

// ---------------- GEGLU row-quant --------------------------------------------
__global__ void __launch_bounds__(128)
geglu_rowq_k(const float* __restrict__ u2, int8_t* __restrict__ q1,
             int8_t* __restrict__ q2, float* __restrict__ sOut) {
    __shared__ float redm[4];
    const size_t m = blockIdx.x;
    const size_t base2 = m * DM2;
    const size_t base = m * DM;
    const int t = threadIdx.x;
    float v[8];
    float am = 0.0f;
#pragma unroll
    for (int i = 0; i < 8; i++) {
        int c = t + i * 128;
        float a = u2[base2 + c];
        float gg = u2[base2 + DM + c];
        v[i] = a * gelu_f(gg);
        am = fmaxf(am, fabsf(v[i]));
    }
#pragma unroll
    for (int o = 16; o > 0; o >>= 1) am = fmaxf(am, __shfl_xor_sync(0xffffffffu, am, o));
    if ((t & 31) == 0) redm[t >> 5] = am;
    __syncthreads();
    am = fmaxf(fmaxf(redm[0], redm[1]), fmaxf(redm[2], redm[3]));
    float qs = am > 0 ? 127.0f / am : 0.0f;
#pragma unroll
    for (int i = 0; i < 8; i++) {
        int c = t + i * 128;
        int8_t a, b;
        quant2(v[i], qs, a, b);
        q1[base + c] = a;
        q2[base + c] = b;
    }
    if (t == 0) sOut[blockIdx.x] = am * (1.0f / 127.0f);
}

// ---------------- mean pool + decode -----------------------------------------
__global__ void pool_k(const float* __restrict__ h, float* __restrict__ pooled) {
    int idx = blockIdx.x * blockDim.x + threadIdx.x;
    if (idx >= BATCH * DM) return;
    int b = idx >> 10, d = idx & (DM - 1);
    const float* p = h + (size_t)b * SEQ * DM + d;
    float s = 0.0f;
#pragma unroll 8
    for (int l = 0; l < SEQ; l++) s += p[(size_t)l * DM];
    pooled[idx] = s * (1.0f / SEQ);
}

__global__ void dec_k(const float* __restrict__ pooled,
                      const float* __restrict__ w,
                      const float* __restrict__ b,
                      float* __restrict__ out) {
    __shared__ float red[8];
    int bi = blockIdx.x;
    int t = threadIdx.x;
    float s = 0.0f;
    for (int d = t; d < DM; d += 256) s += pooled[bi * DM + d] * w[d];
#pragma unroll
    for (int o = 16; o > 0; o >>= 1) s += __shfl_xor_sync(0xffffffffu, s, o);
    if ((t & 31) == 0) red[t >> 5] = s;
    __syncthreads();
    if (t == 0) {
        float tot = 0.0f;
#pragma unroll
        for (int i = 0; i < 8; i++) tot += red[i];
        out[bi] = tot + b[0];
    }
}

// ---------------- driver ----------------
extern "C" void kernel_launch(void* const* d_in, const int* in_sizes, int n_in,
                              void* d_out, int out_size) {
    const float* x        = (const float*)d_in[0];
    const float* enc_w    = (const float*)d_in[1];
    const float* enc_b    = (const float*)d_in[2];
    const float* ln1_g    = (const float*)d_in[3];
    const float* ln1_b    = (const float*)d_in[4];
    const float* lam_re   = (const float*)d_in[5];
    const float* lam_im   = (const float*)d_in[6];
    const float* b_re     = (const float*)d_in[7];
    const float* b_im     = (const float*)d_in[8];
    const float* c_re     = (const float*)d_in[9];
    const float* c_im     = (const float*)d_in[10];
    const float* d_skip   = (const float*)d_in[11];
    const float* log_step = (const float*)d_in[12];
    const float* ffn_g    = (const float*)d_in[13];
    const float* ffn_b    = (const float*)d_in[14];
    const float* ff_enc_w = (const float*)d_in[15];
    const float* ff_dec_w = (const float*)d_in[16];
    const float* norm_g   = (const float*)d_in[17];
    const float* norm_b   = (const float*)d_in[18];
    const float* dec_w    = (const float*)d_in[19];
    const float* dec_b    = (const float*)d_in[20];
    float* out = (float*)d_out;

    static int attr_done = 0;
    if (!attr_done) {
        cudaFuncSetAttribute(imma_gemm<0>, cudaFuncAttributeMaxDynamicSharedMemorySize, SMEM_GEMM);
        cudaFuncSetAttribute(imma_gemm<2>, cudaFuncAttributeMaxDynamicSharedMemorySize, SMEM_GEMM);
        cudaFuncSetAttribute(imma_gemm<3>, cudaFuncAttributeMaxDynamicSharedMemorySize, SMEM_GEMM);
        attr_done = 1;
    }

    float *p_h, *p_fx, *p_fy, *p_z, *p_big, *p_wtmp, *p_pooled;
    int8_t *p_fxq1, *p_fxq2, *p_xsq1, *p_xsq2, *p_fyq1, *p_fyq2, *p_ggq1, *p_ggq2;
    int8_t *p_W2q1, *p_W2q2, *p_Cwq1, *p_Cwq2, *p_feq1, *p_feq2, *p_fdq1, *p_fdq2;
    float *p_sfx, *p_sxs, *p_sfy, *p_sgg, *p_sW2, *p_sCw, *p_sfe, *p_sfd;
    cudaGetSymbolAddress((void**)&p_h, g_h);
    cudaGetSymbolAddress((void**)&p_fx, g_fx);
    cudaGetSymbolAddress((void**)&p_fy, g_fy);
    cudaGetSymbolAddress((void**)&p_z, g_z);
    cudaGetSymbolAddress((void**)&p_big, g_big);
    cudaGetSymbolAddress((void**)&p_wtmp, g_wtmp);
    cudaGetSymbolAddress((void**)&p_pooled, g_pooled);
    cudaGetSymbolAddress((void**)&p_fxq1, g_fxq1);
    cudaGetSymbolAddress((void**)&p_fxq2, g_fxq2);
    cudaGetSymbolAddress((void**)&p_xsq1, g_xsq1);
    cudaGetSymbolAddress((void**)&p_xsq2, g_xsq2);
    cudaGetSymbolAddress((void**)&p_fyq1, g_fyq1);
    cudaGetSymbolAddress((void**)&p_fyq2, g_fyq2);
    cudaGetSymbolAddress((void**)&p_ggq1, g_ggq1);
    cudaGetSymbolAddress((void**)&p_ggq2, g_ggq2);
    cudaGetSymbolAddress((void**)&p_W2q1, g_W2q1);
    cudaGetSymbolAddress((void**)&p_W2q2, g_W2q2);
    cudaGetSymbolAddress((void**)&p_Cwq1, g_Cwq1);
    cudaGetSymbolAddress((void**)&p_Cwq2, g_Cwq2);
    cudaGetSymbolAddress((void**)&p_feq1, g_feq1);
    cudaGetSymbolAddress((void**)&p_feq2, g_feq2);
    cudaGetSymbolAddress((void**)&p_fdq1, g_fdq1);
    cudaGetSymbolAddress((void**)&p_fdq2, g_fdq2);
    cudaGetSymbolAddress((void**)&p_sfx, g_sfx);
    cudaGetSymbolAddress((void**)&p_sxs, g_sxs);
    cudaGetSymbolAddress((void**)&p_sfy, g_sfy);
    cudaGetSymbolAddress((void**)&p_sgg, g_sgg);
    cudaGetSymbolAddress((void**)&p_sW2, g_sW2);
    cudaGetSymbolAddress((void**)&p_sCw, g_sCw);
    cudaGetSymbolAddress((void**)&p_sfe, g_sfe);
    cudaGetSymbolAddress((void**)&p_sfd, g_sfd);

    const int M = MROWS;

    // #1: encoder h = x @ enc_w + enc_b  (fp32, K=64)
    sgemm_enc<<<dim3(DM / TBN, M / TBM), 256>>>(x, enc_w, p_h, M, DM, D_IN, enc_b);

    for (int i = 0; i < NL; i++) {
        const size_t w1 = (size_t)i * DM;
        const size_t w2 = (size_t)i * DM * DM;
        const size_t w3 = (size_t)i * DM * DM2;

        prep_lamb_k<<<(DM + 127) / 128, 128>>>(lam_re + w1, lam_im + w1, log_step + w1); // #2
        prep_W2q_k<<<DM, 256>>>(b_re + w2, b_im + w2);                                    // #3
        ln_k<<<M, 128>>>(p_h, nullptr, p_fx, p_fxq1, p_fxq2, p_sfx,
                         ln1_g + w1, ln1_b + w1);                                         // #4
        prep_Cwq_k<<<DM, 256>>>(c_re + w2, c_im + w2);                                    // #5
        // #6: Bu = fx @ W2^T  [M, 2P] fp32 (interleaved re/im)
        imma_gemm<0><<<dim3(DM2 / 128, M / 128), 256, SMEM_GEMM>>>(
            p_fxq1, p_fxq2, p_W2q1, p_W2q2, p_big, DM2, DM,
            p_sfx, p_sW2, nullptr, nullptr);
        // sequential complex scan, in place (fp32)
        scan_k<<<(BATCH * DM) / 128, 128>>>((float2*)p_big);
        // quantize xs rows (channel-flattened)
        rowq_k<8, true><<<M, 256>>>(p_big, p_xsq1, p_xsq2, p_sxs);
        // z = gelu(xs @ Cw^T + d*fx) + fx
        imma_gemm<2><<<dim3(DM / 128, M / 128), 256, SMEM_GEMM>>>(
            p_xsq1, p_xsq2, p_Cwq1, p_Cwq2, p_z, DM, DM2,
            p_sxs, p_sCw, p_fx, d_skip + w1);
        // ff_enc^T quant
        wtrans_k<<<dim3(DM2 / 32, DM / 32), dim3(32, 32)>>>(ff_enc_w + w3, p_wtmp, DM, DM2);
        rowq_k<4, false><<<DM2, 256>>>(p_wtmp, p_feq1, p_feq2, p_sfe);
        // fy = LN(z) + quant
        ln_k<<<M, 128>>>(p_z, nullptr, p_fy, p_fyq1, p_fyq2, p_sfy,
                         ffn_g + w1, ffn_b + w1);
        // u2 = fy @ ff_enc  [M, 2D]
        imma_gemm<0><<<dim3(DM2 / 128, M / 128), 256, SMEM_GEMM>>>(
            p_fyq1, p_fyq2, p_feq1, p_feq2, p_big, DM2, DM,
            p_sfy, p_sfe, nullptr, nullptr);
        // geglu + quant
        geglu_rowq_k<<<M, 128>>>(p_big, p_ggq1, p_ggq2, p_sgg);
        // ff_dec^T quant
        wtrans_k<<<dim3(DM / 32, DM / 32), dim3(32, 32)>>>(ff_dec_w + w2, p_wtmp, DM, DM);
        rowq_k<4, false><<<DM, 256>>>(p_wtmp, p_fdq1, p_fdq2, p_sfd);
        // z2 = gg @ ff_dec + fy   (into p_z)
        imma_gemm<3><<<dim3(DM / 128, M / 128), 256, SMEM_GEMM>>>(
            p_ggq1, p_ggq2, p_fdq1, p_fdq2, p_z, DM, DM,
            p_sgg, p_sfd, p_fy, nullptr);
        // h = LN(z2 + h)
        ln_k<<<M, 128>>>(p_z, p_h, p_h, nullptr, nullptr, nullptr,
                         norm_g + w1, norm_b + w1);
    }

    pool_k<<<(BATCH * DM) / 128, 128>>>(p_h, p_pooled);
    dec_k<<<BATCH, 256>>>(p_pooled, dec_w, dec_b, out);
}

// round 8
// speedup vs baseline: 3.0281x; 1.0300x over previous
#include <cuda_runtime.h>
#include <cuda_bf16.h>
#include <math.h>
#include <stdint.h>

// ---------------- problem constants ----------------
#define BATCH   8
#define SEQ     2048
#define D_IN    64
#define DM      1024
#define DM2     2048
#define NL      4
#define MROWS   (BATCH*SEQ)   // 16384

typedef __nv_bfloat16 bf16;
typedef __nv_bfloat162 bf162;

// ---------------- scratch (device globals) ----------------
__device__ float g_h  [(size_t)MROWS * DM];
__device__ float g_fx [(size_t)MROWS * DM];
__device__ float g_fy [(size_t)MROWS * DM];
__device__ float g_z  [(size_t)MROWS * DM];
__device__ __align__(16) bf16 g_big[(size_t)MROWS * DM2];   // bu->xs (in place); then u2
__device__ float g_wtmp[(size_t)DM2 * DM];                  // transposed weight staging

__device__ __align__(16) int8_t g_fxq1[(size_t)MROWS * DM];
__device__ __align__(16) int8_t g_fxq2[(size_t)MROWS * DM];
__device__ __align__(16) int8_t g_xsq1[(size_t)MROWS * DM2];
__device__ __align__(16) int8_t g_xsq2[(size_t)MROWS * DM2];
__device__ __align__(16) int8_t g_fyq1[(size_t)MROWS * DM];
__device__ __align__(16) int8_t g_fyq2[(size_t)MROWS * DM];
__device__ __align__(16) int8_t g_ggq1[(size_t)MROWS * DM];
__device__ __align__(16) int8_t g_ggq2[(size_t)MROWS * DM];

__device__ __align__(16) int8_t g_W2q1[(size_t)DM2 * DM];
__device__ __align__(16) int8_t g_W2q2[(size_t)DM2 * DM];
__device__ __align__(16) int8_t g_Cwq1[(size_t)DM * DM2];
__device__ __align__(16) int8_t g_Cwq2[(size_t)DM * DM2];
__device__ __align__(16) int8_t g_feq1[(size_t)DM2 * DM];
__device__ __align__(16) int8_t g_feq2[(size_t)DM2 * DM];
__device__ __align__(16) int8_t g_fdq1[(size_t)DM * DM];
__device__ __align__(16) int8_t g_fdq2[(size_t)DM * DM];

__device__ float g_sfx[MROWS], g_sxs[MROWS], g_sfy[MROWS], g_sgg[MROWS];
__device__ float g_sW2[DM2], g_sCw[DM], g_sfe[DM2], g_sfd[DM];

__device__ float2 g_lamb[DM];
__device__ float  g_chs [DM];    // channel flattening scale (mult into Cw)
__device__ float  g_chsi[DM];    // inverse (mult into xs)
__device__ float  g_pooled[BATCH * DM];

// ---------------- helpers ----------------
__device__ __forceinline__ float gelu_f(float x) {
    return 0.5f * x * (1.0f + erff(x * 0.70710678118654752f));
}
__device__ __forceinline__ uint32_t s2u(const void* p) {
    uint32_t a;
    asm("{ .reg .u64 t; cvta.to.shared.u64 t, %1; cvt.u32.u64 %0, t; }"
        : "=r"(a) : "l"(p));
    return a;
}
__device__ __forceinline__ void cpasync16(uint32_t s, const void* g) {
    asm volatile("cp.async.cg.shared.global [%0], [%1], 16;" :: "r"(s), "l"(g));
}
__device__ __forceinline__ void ldsm_x4(uint32_t* r, uint32_t addr) {
    asm volatile("ldmatrix.sync.aligned.m8n8.x4.shared.b16 {%0,%1,%2,%3}, [%4];"
                 : "=r"(r[0]), "=r"(r[1]), "=r"(r[2]), "=r"(r[3]) : "r"(addr));
}
__device__ __forceinline__ void mma_s8(int* d, const uint32_t* a,
                                       uint32_t b0, uint32_t b1) {
    asm volatile(
        "mma.sync.aligned.m16n8k32.row.col.s32.s8.s8.s32 "
        "{%0,%1,%2,%3}, {%4,%5,%6,%7}, {%8,%9}, {%0,%1,%2,%3};"
        : "+r"(d[0]), "+r"(d[1]), "+r"(d[2]), "+r"(d[3])
        : "r"(a[0]), "r"(a[1]), "r"(a[2]), "r"(a[3]), "r"(b0), "r"(b1));
}
// quantize v*qs into 2 limbs, return as packed byte values
__device__ __forceinline__ void quant2i(float v, float qs, int& o1, int& o2) {
    float t = v * qs;
    o1 = __float2int_rn(t);
    o2 = __float2int_rn((t - (float)o1) * 252.0f);
}
// pack 4 ints (byte range) into one uint32
__device__ __forceinline__ uint32_t pack4(int a, int b, int c, int d) {
    return (uint32_t)(uint8_t)a | ((uint32_t)(uint8_t)b << 8) |
           ((uint32_t)(uint8_t)c << 16) | ((uint32_t)(uint8_t)d << 24);
}
// quantize 8 values -> two uint2 (q1 limbs, q2 limbs)
__device__ __forceinline__ void quant8(const float* v, float qs,
                                       uint2& w1, uint2& w2) {
    int a1[8], a2[8];
#pragma unroll
    for (int i = 0; i < 8; i++) quant2i(v[i], qs, a1[i], a2[i]);
    w1.x = pack4(a1[0], a1[1], a1[2], a1[3]);
    w1.y = pack4(a1[4], a1[5], a1[6], a1[7]);
    w2.x = pack4(a2[0], a2[1], a2[2], a2[3]);
    w2.y = pack4(a2[4], a2[5], a2[6], a2[7]);
}

// ---------------- IMMA split-int8 GEMM: C[M,N] = sA.sB.(A @ B^T) -------------
// CTA 128x128, warp tile 64x32 (2m x 4n warps). K-chunk 64; smem row = 128B:
// [q1 64B | q2 64B], XOR swizzle. 4-stage cp.async. Per k32 step: 3 passes
// (q1q1 -> acc1; q2q1, q1q2 -> accX). Dequant: sA[m]*sB[n]*(acc1 + accX/252).
// EPI 0: plain  2: gelu(v + e1[n]*e0[m,n]) + e0[m,n]  3: v + e0[m,n]
// OBF: write bf162 pairs instead of float2.
#define STAGE_B   32768
#define NSTAGE    4
#define SMEM_GEMM (NSTAGE * STAGE_B)

template <int EPI, bool OBF>
__global__ void __launch_bounds__(256, 1)
imma_gemm(const int8_t* __restrict__ Aq1, const int8_t* __restrict__ Aq2,
          const int8_t* __restrict__ Bq1, const int8_t* __restrict__ Bq2,
          void* __restrict__ Cout, int N, int K,
          const float* __restrict__ sA, const float* __restrict__ sB,
          const float* __restrict__ e0, const float* __restrict__ e1) {
    extern __shared__ __align__(128) char smem[];
    const int tid = threadIdx.x;
    const int wid = tid >> 5;
    const int lid = tid & 31;
    const int wm = wid & 1;
    const int wn = wid >> 1;
    const int bm = blockIdx.y * 128;
    const int bn = blockIdx.x * 128;
    const uint32_t sbase = s2u(smem);
    const int nch = K >> 6;

    auto load_stage = [&](int st, int c) {
        const int kc = c << 6;
        const uint32_t stb = sbase + st * STAGE_B;
#pragma unroll
        for (int t = 0; t < 8; ++t) {
            int i = tid + t * 256;
            int isB = (i >= 1024);
            int ii = i & 1023;
            int row = ii >> 3, j = ii & 7;
            const int8_t* src = isB ? ((j < 4) ? Bq1 : Bq2)
                                    : ((j < 4) ? Aq1 : Aq2);
            size_t go = (size_t)((isB ? bn : bm) + row) * K + kc + (j & 3) * 16;
            uint32_t dst = stb + (isB ? 16384u : 0u) + row * 128 +
                           (uint32_t)((j ^ (row & 7)) << 4);
            cpasync16(dst, src + go);
        }
    };

    int acc1[4][4][4], accX[4][4][4];
#pragma unroll
    for (int mt = 0; mt < 4; mt++)
#pragma unroll
        for (int nt = 0; nt < 4; nt++)
#pragma unroll
            for (int q = 0; q < 4; q++) { acc1[mt][nt][q] = 0; accX[mt][nt][q] = 0; }

    load_stage(0, 0); asm volatile("cp.async.commit_group;" ::: "memory");
    load_stage(1, 1); asm volatile("cp.async.commit_group;" ::: "memory");
    load_stage(2, 2); asm volatile("cp.async.commit_group;" ::: "memory");

    const int a_row = wm * 64 + (lid & 15);
    const int b_row = wn * 32 + (lid & 15);
    const int lc = lid >> 4;

    for (int c = 0; c < nch; ++c) {
        const int wg = nch - 1 - c;
        if (wg >= 2)      asm volatile("cp.async.wait_group 2;" ::: "memory");
        else if (wg == 1) asm volatile("cp.async.wait_group 1;" ::: "memory");
        else              asm volatile("cp.async.wait_group 0;" ::: "memory");
        __syncthreads();

        if (c + 3 < nch) load_stage((c + 3) & 3, c + 3);
        asm volatile("cp.async.commit_group;" ::: "memory");

        const uint32_t smA = sbase + (c & 3) * STAGE_B;
        const uint32_t smB = smA + 16384;
#pragma unroll
        for (int ks = 0; ks < 2; ++ks) {
            uint32_t aq1[4][4], aq2[4][4], bb[2][4];
#pragma unroll
            for (int mt = 0; mt < 4; ++mt) {
                int row = a_row + mt * 16;
                int c1 = ks * 2 + lc;
                int c2 = 4 + ks * 2 + lc;
                ldsm_x4(aq1[mt], smA + row * 128 + ((c1 ^ (row & 7)) << 4));
                ldsm_x4(aq2[mt], smA + row * 128 + ((c2 ^ (row & 7)) << 4));
            }
#pragma unroll
            for (int pp = 0; pp < 2; ++pp) {
                int row = b_row + pp * 16;
                int c1 = ks * 2 + lc;
                ldsm_x4(bb[pp], smB + row * 128 + ((c1 ^ (row & 7)) << 4));
            }
#pragma unroll
            for (int mt = 0; mt < 4; ++mt)
#pragma unroll
                for (int pp = 0; pp < 2; ++pp) {
                    mma_s8(acc1[mt][2 * pp],     aq1[mt], bb[pp][0], bb[pp][2]);
                    mma_s8(acc1[mt][2 * pp + 1], aq1[mt], bb[pp][1], bb[pp][3]);
                    mma_s8(accX[mt][2 * pp],     aq2[mt], bb[pp][0], bb[pp][2]);
                    mma_s8(accX[mt][2 * pp + 1], aq2[mt], bb[pp][1], bb[pp][3]);
                }
#pragma unroll
            for (int pp = 0; pp < 2; ++pp) {
                int row = b_row + pp * 16;
                int c2 = 4 + ks * 2 + lc;
                ldsm_x4(bb[pp], smB + row * 128 + ((c2 ^ (row & 7)) << 4));
            }
#pragma unroll
            for (int mt = 0; mt < 4; ++mt)
#pragma unroll
                for (int pp = 0; pp < 2; ++pp) {
                    mma_s8(accX[mt][2 * pp],     aq1[mt], bb[pp][0], bb[pp][2]);
                    mma_s8(accX[mt][2 * pp + 1], aq1[mt], bb[pp][1], bb[pp][3]);
                }
        }
        __syncthreads();
    }

    const int tr = lid >> 2;
    const int tc = (lid & 3) * 2;
    const float ix = 1.0f / 252.0f;
#pragma unroll
    for (int mt = 0; mt < 4; ++mt) {
#pragma unroll
        for (int half = 0; half < 2; ++half) {
            const int m = bm + wm * 64 + mt * 16 + tr + half * 8;
            const size_t rowoff = (size_t)m * N;
            const float sa = sA[m];
#pragma unroll
            for (int nt = 0; nt < 4; ++nt) {
                const int n = bn + wn * 32 + nt * 8 + tc;
                float v0 = (__int2float_rn(acc1[mt][nt][half * 2 + 0]) +
                            __int2float_rn(accX[mt][nt][half * 2 + 0]) * ix) *
                           sa * sB[n];
                float v1 = (__int2float_rn(acc1[mt][nt][half * 2 + 1]) +
                            __int2float_rn(accX[mt][nt][half * 2 + 1]) * ix) *
                           sa * sB[n + 1];
                const size_t idx = rowoff + n;
                if (EPI == 2) {
                    float f0 = e0[idx], f1 = e0[idx + 1];
                    v0 = gelu_f(fmaf(e1[n], f0, v0)) + f0;
                    v1 = gelu_f(fmaf(e1[n + 1], f1, v1)) + f1;
                } else if (EPI == 3) {
                    v0 += e0[idx];
                    v1 += e0[idx + 1];
                }
                if (OBF) {
                    ((bf162*)Cout)[idx >> 1] = __floats2bfloat162_rn(v0, v1);
                } else {
                    *reinterpret_cast<float2*>((float*)Cout + idx) =
                        make_float2(v0, v1);
                }
            }
        }
    }
}

// ---------------- fp32 SGEMM (encoder only, K=64) ----------------------------
#define TBM 128
#define TBN 128
#define TBK 8
__global__ void __launch_bounds__(256)
sgemm_enc(const float* __restrict__ A, const float* __restrict__ B,
          float* __restrict__ C, int M, int N, int K,
          const float* __restrict__ bias) {
    __shared__ float As[TBK][TBM + 4];
    __shared__ float Bs[TBK][TBN + 4];
    const int tid = threadIdx.x;
    const int bm = blockIdx.y * TBM;
    const int bn = blockIdx.x * TBN;
    const int arow = tid >> 1, akc = (tid & 1) * 4;
    const float* Aptr = A + (size_t)(bm + arow) * K + akc;
    const int br0 = tid >> 5, bc0 = (tid & 31) * 4;
    const float* Bptr = B + (size_t)br0 * N + bn + bc0;

    float acc[8][8];
#pragma unroll
    for (int i = 0; i < 8; i++)
#pragma unroll
        for (int j = 0; j < 8; j++) acc[i][j] = 0.0f;

    float4 aR = *reinterpret_cast<const float4*>(Aptr);
    float4 bR = *reinterpret_cast<const float4*>(Bptr);
    const int tm = tid >> 4, tn = tid & 15;

    for (int k0 = 0;;) {
        As[akc + 0][arow] = aR.x; As[akc + 1][arow] = aR.y;
        As[akc + 2][arow] = aR.z; As[akc + 3][arow] = aR.w;
        Bs[br0][bc0 + 0] = bR.x;  Bs[br0][bc0 + 1] = bR.y;
        Bs[br0][bc0 + 2] = bR.z;  Bs[br0][bc0 + 3] = bR.w;
        __syncthreads();
        k0 += TBK;
        bool more = (k0 < K);
        if (more) {
            aR = *reinterpret_cast<const float4*>(Aptr + k0);
            bR = *reinterpret_cast<const float4*>(Bptr + (size_t)k0 * N);
        }
#pragma unroll
        for (int kk = 0; kk < TBK; kk++) {
            float4 a0 = *reinterpret_cast<const float4*>(&As[kk][tm * 4]);
            float4 a1 = *reinterpret_cast<const float4*>(&As[kk][64 + tm * 4]);
            float4 b0 = *reinterpret_cast<const float4*>(&Bs[kk][tn * 4]);
            float4 b1 = *reinterpret_cast<const float4*>(&Bs[kk][64 + tn * 4]);
            float av[8] = {a0.x, a0.y, a0.z, a0.w, a1.x, a1.y, a1.z, a1.w};
            float bv[8] = {b0.x, b0.y, b0.z, b0.w, b1.x, b1.y, b1.z, b1.w};
#pragma unroll
            for (int i = 0; i < 8; i++)
#pragma unroll
                for (int j = 0; j < 8; j++)
                    acc[i][j] = fmaf(av[i], bv[j], acc[i][j]);
        }
        __syncthreads();
        if (!more) break;
    }
#pragma unroll
    for (int i = 0; i < 8; i++) {
        int r = bm + ((i < 4) ? (tm * 4 + i) : (64 + tm * 4 + i - 4));
        size_t rowoff = (size_t)r * N;
#pragma unroll
        for (int j = 0; j < 8; j++) {
            int c = bn + ((j < 4) ? (tn * 4 + j) : (64 + tn * 4 + j - 4));
            C[rowoff + c] = acc[i][j] + bias[c];
        }
    }
}

// ---------------- per-layer weight prep --------------------------------------
// W2 rows (2p = re, 2p+1 = im). Block per p; also computes lamb/coef/chs inline.
__global__ void __launch_bounds__(256)
prep_W2q_k(const float* __restrict__ b_re, const float* __restrict__ b_im,
           const float* __restrict__ lam_re, const float* __restrict__ lam_im,
           const float* __restrict__ log_step) {
    __shared__ float redA[8], redB[8];
    const int p = blockIdx.x;
    const int tid = threadIdx.x;
    // every thread computes coef for this p (cheap, no divergence)
    float dt = expf(log_step[p]);
    float lr = lam_re[p], li = lam_im[p];
    float er = expf(lr * dt);
    float lbx = er * cosf(li * dt), lby = er * sinf(li * dt);
    float nr = lbx - 1.0f, ni = lby;
    float den = lr * lr + li * li;
    float2 c2 = make_float2((nr * lr + ni * li) / den, (ni * lr - nr * li) / den);
    if (tid == 0) {
        g_lamb[p] = make_float2(lbx, lby);
        float mag2 = lbx * lbx + lby * lby;
        float s = rsqrtf(fmaxf(1.0f - mag2, 1e-6f));
        s = fminf(fmaxf(s, 1.0f), 1000.0f);
        g_chs[p] = s;
        g_chsi[p] = 1.0f / s;
    }
    float vre[4], vim[4];
    float amr = 0.0f, ami = 0.0f;
#pragma unroll
    for (int k = 0; k < 4; ++k) {
        int h = tid + k * 256;
        float br = b_re[(size_t)p * DM + h];
        float bi = b_im[(size_t)p * DM + h];
        vre[k] = c2.x * br - c2.y * bi;
        vim[k] = c2.x * bi + c2.y * br;
        amr = fmaxf(amr, fabsf(vre[k]));
        ami = fmaxf(ami, fabsf(vim[k]));
    }
#pragma unroll
    for (int o = 16; o > 0; o >>= 1) {
        amr = fmaxf(amr, __shfl_xor_sync(0xffffffffu, amr, o));
        ami = fmaxf(ami, __shfl_xor_sync(0xffffffffu, ami, o));
    }
    if ((tid & 31) == 0) { redA[tid >> 5] = amr; redB[tid >> 5] = ami; }
    __syncthreads();
    amr = redA[0]; ami = redB[0];
#pragma unroll
    for (int i = 1; i < 8; ++i) { amr = fmaxf(amr, redA[i]); ami = fmaxf(ami, redB[i]); }
    float qr = amr > 0 ? 127.0f / amr : 0.0f;
    float qi = ami > 0 ? 127.0f / ami : 0.0f;
#pragma unroll
    for (int k = 0; k < 4; ++k) {
        int h = tid + k * 256;
        int a1, a2;
        quant2i(vre[k], qr, a1, a2);
        g_W2q1[(size_t)(2 * p) * DM + h] = (int8_t)a1;
        g_W2q2[(size_t)(2 * p) * DM + h] = (int8_t)a2;
        quant2i(vim[k], qi, a1, a2);
        g_W2q1[(size_t)(2 * p + 1) * DM + h] = (int8_t)a1;
        g_W2q2[(size_t)(2 * p + 1) * DM + h] = (int8_t)a2;
    }
    if (tid == 0) {
        g_sW2[2 * p]     = amr * (1.0f / 127.0f);
        g_sW2[2 * p + 1] = ami * (1.0f / 127.0f);
    }
}

// Cw rows (h): interleaved re/-im * channel scale. Block per h, 256 threads.
__global__ void __launch_bounds__(256)
prep_Cwq_k(const float* __restrict__ c_re, const float* __restrict__ c_im) {
    __shared__ float red[8];
    const int h = blockIdx.x;
    const int tid = threadIdx.x;
    float v[8];
    float am = 0.0f;
#pragma unroll
    for (int k = 0; k < 4; ++k) {          // thread owns 4 consecutive p (8 elems)
        int p = tid * 4 + k * 0;           // placeholder (rewritten below)
    }
    // thread owns p in {tid, tid+256, tid+512, tid+768}; 2 elements each
#pragma unroll
    for (int k = 0; k < 4; ++k) {
        int p = tid + k * 256;
        float re = c_re[(size_t)h * DM + p] * g_chs[p];
        float im = -c_im[(size_t)h * DM + p] * g_chs[p];
        v[2 * k] = re;
        v[2 * k + 1] = im;
        am = fmaxf(am, fmaxf(fabsf(re), fabsf(im)));
    }
#pragma unroll
    for (int o = 16; o > 0; o >>= 1) am = fmaxf(am, __shfl_xor_sync(0xffffffffu, am, o));
    if ((tid & 31) == 0) red[tid >> 5] = am;
    __syncthreads();
    am = red[0];
#pragma unroll
    for (int i = 1; i < 8; ++i) am = fmaxf(am, red[i]);
    float qs = am > 0 ? 127.0f / am : 0.0f;
#pragma unroll
    for (int k = 0; k < 4; ++k) {
        int p = tid + k * 256;
        int a1, a2, b1, b2;
        quant2i(v[2 * k], qs, a1, a2);
        quant2i(v[2 * k + 1], qs, b1, b2);
        uint16_t w1 = (uint16_t)((uint8_t)a1 | ((uint16_t)(uint8_t)b1 << 8));
        uint16_t w2 = (uint16_t)((uint8_t)a2 | ((uint16_t)(uint8_t)b2 << 8));
        *(uint16_t*)(g_Cwq1 + (size_t)h * DM2 + 2 * p) = w1;
        *(uint16_t*)(g_Cwq2 + (size_t)h * DM2 + 2 * p) = w2;
    }
    if (tid == 0) g_sCw[h] = am * (1.0f / 127.0f);
}

// fp32 transpose: in [R][C2] -> out [C2][R]
__global__ void wtrans_k(const float* __restrict__ in, float* __restrict__ outT,
                         int R, int C2) {
    __shared__ float t[32][33];
    int r = blockIdx.y * 32 + threadIdx.y;
    int c = blockIdx.x * 32 + threadIdx.x;
    t[threadIdx.y][threadIdx.x] = in[(size_t)r * C2 + c];
    __syncthreads();
    int orow = blockIdx.x * 32 + threadIdx.y;
    int ocol = blockIdx.y * 32 + threadIdx.x;
    outT[(size_t)orow * R + ocol] = t[threadIdx.x][threadIdx.y];
}

// weight row quantizer (fp32 in, 1024/row, 256 thr x 4 contiguous)
__global__ void __launch_bounds__(256)
rowq_w_k(const float* __restrict__ in, int8_t* __restrict__ q1,
         int8_t* __restrict__ q2, float* __restrict__ sOut) {
    __shared__ float red[8];
    const size_t base = (size_t)blockIdx.x * DM;
    const int tid = threadIdx.x;
    const int c0 = tid * 4;
    float4 vv = *reinterpret_cast<const float4*>(in + base + c0);
    float v[4] = {vv.x, vv.y, vv.z, vv.w};
    float am = 0.0f;
#pragma unroll
    for (int k = 0; k < 4; ++k) am = fmaxf(am, fabsf(v[k]));
#pragma unroll
    for (int o = 16; o > 0; o >>= 1) am = fmaxf(am, __shfl_xor_sync(0xffffffffu, am, o));
    if ((tid & 31) == 0) red[tid >> 5] = am;
    __syncthreads();
    am = red[0];
#pragma unroll
    for (int i = 1; i < 8; ++i) am = fmaxf(am, red[i]);
    float qs = am > 0 ? 127.0f / am : 0.0f;
    int a1[4], a2[4];
#pragma unroll
    for (int k = 0; k < 4; ++k) quant2i(v[k], qs, a1[k], a2[k]);
    *(uint32_t*)(q1 + base + c0) = pack4(a1[0], a1[1], a1[2], a1[3]);
    *(uint32_t*)(q2 + base + c0) = pack4(a2[0], a2[1], a2[2], a2[3]);
    if (tid == 0) sOut[blockIdx.x] = am * (1.0f / 127.0f);
}

// xs row quantizer: bf16 in, 2048/row, channel-flattening. 256 thr x 8 contig.
__global__ void __launch_bounds__(256)
rowq_xs_k(const bf16* __restrict__ in, int8_t* __restrict__ q1,
          int8_t* __restrict__ q2, float* __restrict__ sOut) {
    __shared__ float red[8];
    const size_t base = (size_t)blockIdx.x * DM2;
    const int tid = threadIdx.x;
    const int c0 = tid * 8;
    const bf162* pin = reinterpret_cast<const bf162*>(in + base + c0);
    float v[8];
    float am = 0.0f;
#pragma unroll
    for (int k = 0; k < 4; ++k) {
        float2 f = __bfloat1622float2(pin[k]);
        float sc = g_chsi[(c0 >> 1) + k];
        v[2 * k] = f.x * sc;
        v[2 * k + 1] = f.y * sc;
        am = fmaxf(am, fmaxf(fabsf(v[2 * k]), fabsf(v[2 * k + 1])));
    }
#pragma unroll
    for (int o = 16; o > 0; o >>= 1) am = fmaxf(am, __shfl_xor_sync(0xffffffffu, am, o));
    if ((tid & 31) == 0) red[tid >> 5] = am;
    __syncthreads();
    am = red[0];
#pragma unroll
    for (int i = 1; i < 8; ++i) am = fmaxf(am, red[i]);
    float qs = am > 0 ? 127.0f / am : 0.0f;
    uint2 w1, w2;
    quant8(v, qs, w1, w2);
    *(uint2*)(q1 + base + c0) = w1;
    *(uint2*)(q2 + base + c0) = w2;
    if (tid == 0) sOut[blockIdx.x] = am * (1.0f / 127.0f);
}

// ---------------- scan: fp32 recurrence over bf16 data, in-place -------------
__global__ void scan_k(bf162* __restrict__ bu) {
    int idx = blockIdx.x * blockDim.x + threadIdx.x;
    if (idx >= BATCH * DM) return;
    int b = idx >> 10, p = idx & (DM - 1);
    float2 a = g_lamb[p];
    bf162* ptr = bu + (size_t)b * SEQ * DM + p;
    float xr = 0.0f, xi = 0.0f;
    const int U = 8;
    bf162 cur[U], nxt[U];
#pragma unroll
    for (int i = 0; i < U; i++) cur[i] = ptr[(size_t)i * DM];
#pragma unroll
    for (int i = 0; i < U; i++) nxt[i] = __floats2bfloat162_rn(0.f, 0.f);
    for (int l0 = 0; l0 < SEQ; l0 += U) {
        if (l0 + U < SEQ) {
#pragma unroll
            for (int i = 0; i < U; i++) nxt[i] = ptr[(size_t)(l0 + U + i) * DM];
        }
#pragma unroll
        for (int i = 0; i < U; i++) {
            float2 u = __bfloat1622float2(cur[i]);
            float nr = fmaf(a.x, xr, fmaf(-a.y, xi, u.x));
            float ni = fmaf(a.x, xi, fmaf(a.y, xr, u.y));
            xr = nr; xi = ni;
            ptr[(size_t)(l0 + i) * DM] = __floats2bfloat162_rn(xr, xi);
        }
#pragma unroll
        for (int i = 0; i < U; i++) cur[i] = nxt[i];
    }
}

// ---------------- LayerNorm (+optional residual add, +optional int8 quant) ---
// 128 threads, each owns 8 contiguous elements.
__global__ void __launch_bounds__(128)
ln_k(const float* __restrict__ in, const float* __restrict__ add,
     float* __restrict__ out, int8_t* __restrict__ q1, int8_t* __restrict__ q2,
     float* __restrict__ sOut,
     const float* __restrict__ g, const float* __restrict__ bb) {
    __shared__ float red[8];
    __shared__ float redm[4];
    size_t base = (size_t)blockIdx.x * DM;
    int t = threadIdx.x;
    int c0 = t * 8;
    float v[8];
    float4 i0 = *reinterpret_cast<const float4*>(in + base + c0);
    float4 i1 = *reinterpret_cast<const float4*>(in + base + c0 + 4);
    v[0] = i0.x; v[1] = i0.y; v[2] = i0.z; v[3] = i0.w;
    v[4] = i1.x; v[5] = i1.y; v[6] = i1.z; v[7] = i1.w;
    if (add) {
        float4 a0 = *reinterpret_cast<const float4*>(add + base + c0);
        float4 a1 = *reinterpret_cast<const float4*>(add + base + c0 + 4);
        v[0] += a0.x; v[1] += a0.y; v[2] += a0.z; v[3] += a0.w;
        v[4] += a1.x; v[5] += a1.y; v[6] += a1.z; v[7] += a1.w;
    }
    float s = 0.0f;
#pragma unroll
    for (int i = 0; i < 8; i++) s += v[i];
#pragma unroll
    for (int o = 16; o > 0; o >>= 1) s += __shfl_xor_sync(0xffffffffu, s, o);
    if ((t & 31) == 0) red[t >> 5] = s;
    __syncthreads();
    float mean = (red[0] + red[1] + red[2] + red[3]) * (1.0f / DM);
    float s2 = 0.0f;
#pragma unroll
    for (int i = 0; i < 8; i++) { float d = v[i] - mean; s2 += d * d; }
#pragma unroll
    for (int o = 16; o > 0; o >>= 1) s2 += __shfl_xor_sync(0xffffffffu, s2, o);
    if ((t & 31) == 0) red[4 + (t >> 5)] = s2;
    __syncthreads();
    float var = (red[4] + red[5] + red[6] + red[7]) * (1.0f / DM);
    float inv = rsqrtf(var + 1e-5f);
    float4 g0 = *reinterpret_cast<const float4*>(g + c0);
    float4 g1 = *reinterpret_cast<const float4*>(g + c0 + 4);
    float4 b0 = *reinterpret_cast<const float4*>(bb + c0);
    float4 b1 = *reinterpret_cast<const float4*>(bb + c0 + 4);
    float gg[8] = {g0.x, g0.y, g0.z, g0.w, g1.x, g1.y, g1.z, g1.w};
    float bbv[8] = {b0.x, b0.y, b0.z, b0.w, b1.x, b1.y, b1.z, b1.w};
    float y[8];
    float am = 0.0f;
#pragma unroll
    for (int i = 0; i < 8; i++) {
        y[i] = (v[i] - mean) * inv * gg[i] + bbv[i];
        am = fmaxf(am, fabsf(y[i]));
    }
    *reinterpret_cast<float4*>(out + base + c0) =
        make_float4(y[0], y[1], y[2], y[3]);
    *reinterpret_cast<float4*>(out + base + c0 + 4) =
        make_float4(y[4], y[5], y[6], y[7]);
    if (q1) {
#pragma unroll
        for (int o = 16; o > 0; o >>= 1) am = fmaxf(am, __shfl_xor_sync(0xffffffffu, am, o));
        if ((t & 31) == 0) redm[t >> 5] = am;
        __syncthreads();
        am = fmaxf(fmaxf(redm[0], redm[1]), fmaxf(redm[2], redm[3]));
        float qs = am > 0 ? 127.0f / am : 0.0f;
        uint2 w1, w2;
        quant8(y, qs, w1, w2);
        *(uint2*)(q1 + base + c0) = w1;
        *(uint2*)(q2 + base + c0) = w2;
        if (t == 0) sOut[blockIdx.x] = am * (1.0f / 127.0f);
    }
}

// ---------------- GEGLU row-quant (bf16 in) -----------------------------------
__global__ void __launch_bounds__(128)
geglu_rowq_k(const bf16* __restrict__ u2, int8_t* __restrict__ q1,
             int8_t* __restrict__ q2, float* __restrict__ sOut) {
    __shared__ float redm[4];
    const size_t m = blockIdx.x;
    const size_t base2 = m * DM2;
    const size_t base = m * DM;
    const int t = threadIdx.x;
    const int c0 = t * 8;
    const bf162* pa = reinterpret_cast<const bf162*>(u2 + base2 + c0);
    const bf162* pg = reinterpret_cast<const bf162*>(u2 + base2 + DM + c0);
    float v[8];
    float am = 0.0f;
#pragma unroll
    for (int k = 0; k < 4; ++k) {
        float2 fa = __bfloat1622float2(pa[k]);
        float2 fg = __bfloat1622float2(pg[k]);
        v[2 * k]     = fa.x * gelu_f(fg.x);
        v[2 * k + 1] = fa.y * gelu_f(fg.y);
        am = fmaxf(am, fmaxf(fabsf(v[2 * k]), fabsf(v[2 * k + 1])));
    }
#pragma unroll
    for (int o = 16; o > 0; o >>= 1) am = fmaxf(am, __shfl_xor_sync(0xffffffffu, am, o));
    if ((t & 31) == 0) redm[t >> 5] = am;
    __syncthreads();
    am = fmaxf(fmaxf(redm[0], redm[1]), fmaxf(redm[2], redm[3]));
    float qs = am > 0 ? 127.0f / am : 0.0f;
    uint2 w1, w2;
    quant8(v, qs, w1, w2);
    *(uint2*)(q1 + base + c0) = w1;
    *(uint2*)(q2 + base + c0) = w2;
    if (t == 0) sOut[blockIdx.x] = am * (1.0f / 127.0f);
}

// ---------------- mean pool + decode -----------------------------------------
__global__ void pool_k(const float* __restrict__ h, float* __restrict__ pooled) {
    int idx = blockIdx.x * blockDim.x + threadIdx.x;
    if (idx >= BATCH * DM) return;
    int b = idx >> 10, d = idx & (DM - 1);
    const float* p = h + (size_t)b * SEQ * DM + d;
    float s = 0.0f;
#pragma unroll 8
    for (int l = 0; l < SEQ; l++) s += p[(size_t)l * DM];
    pooled[idx] = s * (1.0f / SEQ);
}

__global__ void dec_k(const float* __restrict__ pooled,
                      const float* __restrict__ w,
                      const float* __restrict__ b,
                      float* __restrict__ out) {
    __shared__ float red[8];
    int bi = blockIdx.x;
    int t = threadIdx.x;
    float s = 0.0f;
    for (int d = t; d < DM; d += 256) s += pooled[bi * DM + d] * w[d];
#pragma unroll
    for (int o = 16; o > 0; o >>= 1) s += __shfl_xor_sync(0xffffffffu, s, o);
    if ((t & 31) == 0) red[t >> 5] = s;
    __syncthreads();
    if (t == 0) {
        float tot = 0.0f;
#pragma unroll
        for (int i = 0; i < 8; i++) tot += red[i];
        out[bi] = tot + b[0];
    }
}

// ---------------- driver ----------------
extern "C" void kernel_launch(void* const* d_in, const int* in_sizes, int n_in,
                              void* d_out, int out_size) {
    const float* x        = (const float*)d_in[0];
    const float* enc_w    = (const float*)d_in[1];
    const float* enc_b    = (const float*)d_in[2];
    const float* ln1_g    = (const float*)d_in[3];
    const float* ln1_b    = (const float*)d_in[4];
    const float* lam_re   = (const float*)d_in[5];
    const float* lam_im   = (const float*)d_in[6];
    const float* b_re     = (const float*)d_in[7];
    const float* b_im     = (const float*)d_in[8];
    const float* c_re     = (const float*)d_in[9];
    const float* c_im     = (const float*)d_in[10];
    const float* d_skip   = (const float*)d_in[11];
    const float* log_step = (const float*)d_in[12];
    const float* ffn_g    = (const float*)d_in[13];
    const float* ffn_b    = (const float*)d_in[14];
    const float* ff_enc_w = (const float*)d_in[15];
    const float* ff_dec_w = (const float*)d_in[16];
    const float* norm_g   = (const float*)d_in[17];
    const float* norm_b   = (const float*)d_in[18];
    const float* dec_w    = (const float*)d_in[19];
    const float* dec_b    = (const float*)d_in[20];
    float* out = (float*)d_out;

    static int attr_done = 0;
    if (!attr_done) {
        cudaFuncSetAttribute((const void*)imma_gemm<0, true>,
                             cudaFuncAttributeMaxDynamicSharedMemorySize, SMEM_GEMM);
        cudaFuncSetAttribute((const void*)imma_gemm<2, false>,
                             cudaFuncAttributeMaxDynamicSharedMemorySize, SMEM_GEMM);
        cudaFuncSetAttribute((const void*)imma_gemm<3, false>,
                             cudaFuncAttributeMaxDynamicSharedMemorySize, SMEM_GEMM);
        attr_done = 1;
    }

    float *p_h, *p_fx, *p_fy, *p_z, *p_wtmp, *p_pooled;
    bf16 *p_big;
    int8_t *p_fxq1, *p_fxq2, *p_xsq1, *p_xsq2, *p_fyq1, *p_fyq2, *p_ggq1, *p_ggq2;
    int8_t *p_W2q1, *p_W2q2, *p_Cwq1, *p_Cwq2, *p_feq1, *p_feq2, *p_fdq1, *p_fdq2;
    float *p_sfx, *p_sxs, *p_sfy, *p_sgg, *p_sW2, *p_sCw, *p_sfe, *p_sfd;
    cudaGetSymbolAddress((void**)&p_h, g_h);
    cudaGetSymbolAddress((void**)&p_fx, g_fx);
    cudaGetSymbolAddress((void**)&p_fy, g_fy);
    cudaGetSymbolAddress((void**)&p_z, g_z);
    cudaGetSymbolAddress((void**)&p_big, g_big);
    cudaGetSymbolAddress((void**)&p_wtmp, g_wtmp);
    cudaGetSymbolAddress((void**)&p_pooled, g_pooled);
    cudaGetSymbolAddress((void**)&p_fxq1, g_fxq1);
    cudaGetSymbolAddress((void**)&p_fxq2, g_fxq2);
    cudaGetSymbolAddress((void**)&p_xsq1, g_xsq1);
    cudaGetSymbolAddress((void**)&p_xsq2, g_xsq2);
    cudaGetSymbolAddress((void**)&p_fyq1, g_fyq1);
    cudaGetSymbolAddress((void**)&p_fyq2, g_fyq2);
    cudaGetSymbolAddress((void**)&p_ggq1, g_ggq1);
    cudaGetSymbolAddress((void**)&p_ggq2, g_ggq2);
    cudaGetSymbolAddress((void**)&p_W2q1, g_W2q1);
    cudaGetSymbolAddress((void**)&p_W2q2, g_W2q2);
    cudaGetSymbolAddress((void**)&p_Cwq1, g_Cwq1);
    cudaGetSymbolAddress((void**)&p_Cwq2, g_Cwq2);
    cudaGetSymbolAddress((void**)&p_feq1, g_feq1);
    cudaGetSymbolAddress((void**)&p_feq2, g_feq2);
    cudaGetSymbolAddress((void**)&p_fdq1, g_fdq1);
    cudaGetSymbolAddress((void**)&p_fdq2, g_fdq2);
    cudaGetSymbolAddress((void**)&p_sfx, g_sfx);
    cudaGetSymbolAddress((void**)&p_sxs, g_sxs);
    cudaGetSymbolAddress((void**)&p_sfy, g_sfy);
    cudaGetSymbolAddress((void**)&p_sgg, g_sgg);
    cudaGetSymbolAddress((void**)&p_sW2, g_sW2);
    cudaGetSymbolAddress((void**)&p_sCw, g_sCw);
    cudaGetSymbolAddress((void**)&p_sfe, g_sfe);
    cudaGetSymbolAddress((void**)&p_sfd, g_sfd);

    const int M = MROWS;

    // #1: encoder h = x @ enc_w + enc_b  (fp32, K=64)
    sgemm_enc<<<dim3(DM / TBN, M / TBM), 256>>>(x, enc_w, p_h, M, DM, D_IN, enc_b);

    for (int i = 0; i < NL; i++) {
        const size_t w1 = (size_t)i * DM;
        const size_t w2 = (size_t)i * DM * DM;
        const size_t w3 = (size_t)i * DM * DM2;

        // #2 (layer 0): W2 quant + inline lamb/chs
        prep_W2q_k<<<DM, 256>>>(b_re + w2, b_im + w2,
                                lam_re + w1, lam_im + w1, log_step + w1);
        // #3: fx = LN(h) + quant
        ln_k<<<M, 128>>>(p_h, nullptr, p_fx, p_fxq1, p_fxq2, p_sfx,
                         ln1_g + w1, ln1_b + w1);
        // #4: Bu = fx @ W2^T  [M, 2P] bf16 out  <-- ncu-captured launch
        imma_gemm<0, true><<<dim3(DM2 / 128, M / 128), 256, SMEM_GEMM>>>(
            p_fxq1, p_fxq2, p_W2q1, p_W2q2, p_big, DM2, DM,
            p_sfx, p_sW2, nullptr, nullptr);
        // #5: Cw quant (needs g_chs from #2)
        prep_Cwq_k<<<DM, 256>>>(c_re + w2, c_im + w2);
        // sequential complex scan, in place (bf16 storage, fp32 recurrence)
        scan_k<<<(BATCH * DM) / 128, 128>>>((bf162*)p_big);
        // quantize xs rows (channel-flattened)
        rowq_xs_k<<<M, 256>>>(p_big, p_xsq1, p_xsq2, p_sxs);
        // z = gelu(xs @ Cw^T + d*fx) + fx
        imma_gemm<2, false><<<dim3(DM / 128, M / 128), 256, SMEM_GEMM>>>(
            p_xsq1, p_xsq2, p_Cwq1, p_Cwq2, p_z, DM, DM2,
            p_sxs, p_sCw, p_fx, d_skip + w1);
        // ff_enc^T quant
        wtrans_k<<<dim3(DM2 / 32, DM / 32), dim3(32, 32)>>>(ff_enc_w + w3, p_wtmp, DM, DM2);
        rowq_w_k<<<DM2, 256>>>(p_wtmp, p_feq1, p_feq2, p_sfe);
        // fy = LN(z) + quant
        ln_k<<<M, 128>>>(p_z, nullptr, p_fy, p_fyq1, p_fyq2, p_sfy,
                         ffn_g + w1, ffn_b + w1);
        // u2 = fy @ ff_enc  [M, 2D] bf16 out
        imma_gemm<0, true><<<dim3(DM2 / 128, M / 128), 256, SMEM_GEMM>>>(
            p_fyq1, p_fyq2, p_feq1, p_feq2, p_big, DM2, DM,
            p_sfy, p_sfe, nullptr, nullptr);
        // geglu + quant
        geglu_rowq_k<<<M, 128>>>(p_big, p_ggq1, p_ggq2, p_sgg);
        // ff_dec^T quant
        wtrans_k<<<dim3(DM / 32, DM / 32), dim3(32, 32)>>>(ff_dec_w + w2, p_wtmp, DM, DM);
        rowq_w_k<<<DM, 256>>>(p_wtmp, p_fdq1, p_fdq2, p_sfd);
        // z2 = gg @ ff_dec + fy   (into p_z)
        imma_gemm<3, false><<<dim3(DM / 128, M / 128), 256, SMEM_GEMM>>>(
            p_ggq1, p_ggq2, p_fdq1, p_fdq2, p_z, DM, DM,
            p_sgg, p_sfd, p_fy, nullptr);
        // h = LN(z2 + h)
        ln_k<<<M, 128>>>(p_z, p_h, p_h, nullptr, nullptr, nullptr,
                         norm_g + w1, norm_b + w1);
    }

    pool_k<<<(BATCH * DM) / 128, 128>>>(p_h, p_pooled);
    dec_k<<<BATCH, 256>>>(p_pooled, dec_w, dec_b, out);
}

// round 10
// speedup vs baseline: 3.2854x; 1.0849x over previous
#include <cuda_runtime.h>
#include <cuda_bf16.h>
#include <math.h>
#include <stdint.h>

// ---------------- problem constants ----------------
#define BATCH   8
#define SEQ     2048
#define D_IN    64
#define DM      1024
#define DM2     2048
#define NL      4
#define MROWS   (BATCH*SEQ)   // 16384

typedef __nv_bfloat16 bf16;
typedef __nv_bfloat162 bf162;

// ---------------- scratch (device globals) ----------------
__device__ float g_h  [(size_t)MROWS * DM];
__device__ float g_fx [(size_t)MROWS * DM];
__device__ float g_fy [(size_t)MROWS * DM];
__device__ float g_z  [(size_t)MROWS * DM];
__device__ __align__(16) bf16 g_big[(size_t)MROWS * DM2];   // bu->xs (in place); then u2
__device__ float g_wtmp[(size_t)DM2 * DM];                  // transposed weight staging

__device__ __align__(16) int8_t g_fxq1[(size_t)MROWS * DM];
__device__ __align__(16) int8_t g_fxq2[(size_t)MROWS * DM];
__device__ __align__(16) int8_t g_xsq1[(size_t)MROWS * DM2];
__device__ __align__(16) int8_t g_xsq2[(size_t)MROWS * DM2];
__device__ __align__(16) int8_t g_fyq1[(size_t)MROWS * DM];
__device__ __align__(16) int8_t g_fyq2[(size_t)MROWS * DM];
__device__ __align__(16) int8_t g_ggq1[(size_t)MROWS * DM];
__device__ __align__(16) int8_t g_ggq2[(size_t)MROWS * DM];

__device__ __align__(16) int8_t g_W2q1[(size_t)DM2 * DM];
__device__ __align__(16) int8_t g_W2q2[(size_t)DM2 * DM];
__device__ __align__(16) int8_t g_Cwq1[(size_t)DM * DM2];
__device__ __align__(16) int8_t g_Cwq2[(size_t)DM * DM2];
__device__ __align__(16) int8_t g_feq1[(size_t)DM2 * DM];
__device__ __align__(16) int8_t g_feq2[(size_t)DM2 * DM];
__device__ __align__(16) int8_t g_fdq1[(size_t)DM * DM];
__device__ __align__(16) int8_t g_fdq2[(size_t)DM * DM];

__device__ float g_sfx[MROWS], g_sxs[MROWS], g_sfy[MROWS], g_sgg[MROWS];
__device__ float g_sW2[DM2], g_sCw[DM], g_sfe[DM2], g_sfd[DM];

__device__ float2 g_lamb[DM];
__device__ float  g_chs [DM];    // channel flattening scale (mult into Cw)
__device__ float  g_chsi[DM];    // inverse (mult into xs)
__device__ float  g_pooled[BATCH * DM];

// ---------------- helpers ----------------
__device__ __forceinline__ float gelu_f(float x) {
    return 0.5f * x * (1.0f + erff(x * 0.70710678118654752f));
}
__device__ __forceinline__ uint32_t s2u(const void* p) {
    uint32_t a;
    asm("{ .reg .u64 t; cvta.to.shared.u64 t, %1; cvt.u32.u64 %0, t; }"
        : "=r"(a) : "l"(p));
    return a;
}
__device__ __forceinline__ void cpasync16(uint32_t s, const void* g) {
    asm volatile("cp.async.cg.shared.global [%0], [%1], 16;" :: "r"(s), "l"(g));
}
__device__ __forceinline__ void ldsm_x4(uint32_t* r, uint32_t addr) {
    asm volatile("ldmatrix.sync.aligned.m8n8.x4.shared.b16 {%0,%1,%2,%3}, [%4];"
                 : "=r"(r[0]), "=r"(r[1]), "=r"(r[2]), "=r"(r[3]) : "r"(addr));
}
__device__ __forceinline__ void mma_s8(int* d, const uint32_t* a,
                                       uint32_t b0, uint32_t b1) {
    asm volatile(
        "mma.sync.aligned.m16n8k32.row.col.s32.s8.s8.s32 "
        "{%0,%1,%2,%3}, {%4,%5,%6,%7}, {%8,%9}, {%0,%1,%2,%3};"
        : "+r"(d[0]), "+r"(d[1]), "+r"(d[2]), "+r"(d[3])
        : "r"(a[0]), "r"(a[1]), "r"(a[2]), "r"(a[3]), "r"(b0), "r"(b1));
}
// quantize v*qs into 2 limbs
__device__ __forceinline__ void quant2i(float v, float qs, int& o1, int& o2) {
    float t = v * qs;
    o1 = __float2int_rn(t);
    o2 = __float2int_rn((t - (float)o1) * 252.0f);
}
__device__ __forceinline__ uint32_t pack4(int a, int b, int c, int d) {
    return (uint32_t)(uint8_t)a | ((uint32_t)(uint8_t)b << 8) |
           ((uint32_t)(uint8_t)c << 16) | ((uint32_t)(uint8_t)d << 24);
}
__device__ __forceinline__ void quant8(const float* v, float qs,
                                       uint2& w1, uint2& w2) {
    int a1[8], a2[8];
#pragma unroll
    for (int i = 0; i < 8; i++) quant2i(v[i], qs, a1[i], a2[i]);
    w1.x = pack4(a1[0], a1[1], a1[2], a1[3]);
    w1.y = pack4(a1[4], a1[5], a1[6], a1[7]);
    w2.x = pack4(a2[0], a2[1], a2[2], a2[3]);
    w2.y = pack4(a2[4], a2[5], a2[6], a2[7]);
}

// ---------------- IMMA split-int8 GEMM: C[M,N] = sA.sB.(A @ B^T) -------------
// CTA 128x64, warp tile 32x32 (4m x 2n warps), 2 CTAs/SM. K-chunk 64; smem
// row = 128B: [q1 64B | q2 64B], XOR swizzle. Stage 24KB (A 16K + B 8K),
// 4 stages. One barrier per chunk. Per k32 step: 3 passes (q1q1 -> acc1;
// q2q1, q1q2 -> accX). Dequant: sA[m]*sB[n]*(acc1 + accX/252).
// EPI 0: plain  2: gelu(v + e1[n]*e0[m,n]) + e0[m,n]  3: v + e0[m,n]
// OBF: write bf162 pairs instead of float2.
#define STAGE_B   24576
#define NSTAGE    4
#define SMEM_GEMM (NSTAGE * STAGE_B)

template <int EPI, bool OBF>
__global__ void __launch_bounds__(256, 2)
imma_gemm(const int8_t* __restrict__ Aq1, const int8_t* __restrict__ Aq2,
          const int8_t* __restrict__ Bq1, const int8_t* __restrict__ Bq2,
          void* __restrict__ Cout, int N, int K,
          const float* __restrict__ sA, const float* __restrict__ sB,
          const float* __restrict__ e0, const float* __restrict__ e1) {
    extern __shared__ __align__(128) char smem[];
    const int tid = threadIdx.x;
    const int wid = tid >> 5;
    const int lid = tid & 31;
    const int wm = wid & 3;          // 4 warps along M (32 rows each)
    const int wn = wid >> 2;         // 2 warps along N (32 cols each)
    const int bm = blockIdx.y * 128;
    const int bn = blockIdx.x * 64;
    const uint32_t sbase = s2u(smem);
    const int nch = K >> 6;

    auto load_stage = [&](int st, int c) {
        const int kc = c << 6;
        const uint32_t stb = sbase + st * STAGE_B;
#pragma unroll
        for (int t = 0; t < 6; ++t) {
            int i = tid + t * 256;            // 0..1535
            int isB = (i >= 1024);
            int ii = isB ? (i - 1024) : i;
            int row = ii >> 3, j = ii & 7;
            const int8_t* src = isB ? ((j < 4) ? Bq1 : Bq2)
                                    : ((j < 4) ? Aq1 : Aq2);
            size_t go = (size_t)((isB ? bn : bm) + row) * K + kc + (j & 3) * 16;
            uint32_t dst = stb + (isB ? 16384u : 0u) + row * 128 +
                           (uint32_t)((j ^ (row & 7)) << 4);
            cpasync16(dst, src + go);
        }
    };

    int acc1[2][4][4], accX[2][4][4];
#pragma unroll
    for (int mt = 0; mt < 2; mt++)
#pragma unroll
        for (int nt = 0; nt < 4; nt++)
#pragma unroll
            for (int q = 0; q < 4; q++) { acc1[mt][nt][q] = 0; accX[mt][nt][q] = 0; }

    load_stage(0, 0); asm volatile("cp.async.commit_group;" ::: "memory");
    load_stage(1, 1); asm volatile("cp.async.commit_group;" ::: "memory");
    load_stage(2, 2); asm volatile("cp.async.commit_group;" ::: "memory");

    // ldmatrix lane mapping: row = base + (lid & 15), c16-unit = +(lid >> 4)
    const int a_row = wm * 32 + (lid & 15);
    const int b_row = wn * 32 + (lid & 15);
    const int lc = lid >> 4;

    for (int c = 0; c < nch; ++c) {
        const int wg = nch - 1 - c;
        if (wg >= 2)      asm volatile("cp.async.wait_group 2;" ::: "memory");
        else if (wg == 1) asm volatile("cp.async.wait_group 1;" ::: "memory");
        else              asm volatile("cp.async.wait_group 0;" ::: "memory");
        // single barrier per chunk: orders (a) cp.async data visibility and
        // (b) previous chunk's compute vs the load below that overwrites
        // buffer (c-1)&3 == (c+3)&3.
        __syncthreads();

        if (c + 3 < nch) load_stage((c + 3) & 3, c + 3);
        asm volatile("cp.async.commit_group;" ::: "memory");

        const uint32_t smA = sbase + (c & 3) * STAGE_B;
        const uint32_t smB = smA + 16384;
#pragma unroll
        for (int ks = 0; ks < 2; ++ks) {
            uint32_t aq1[2][4], aq2[2][4], bb[2][4];
#pragma unroll
            for (int mt = 0; mt < 2; ++mt) {
                int row = a_row + mt * 16;
                int c1 = ks * 2 + lc;
                int c2 = 4 + ks * 2 + lc;
                ldsm_x4(aq1[mt], smA + row * 128 + ((c1 ^ (row & 7)) << 4));
                ldsm_x4(aq2[mt], smA + row * 128 + ((c2 ^ (row & 7)) << 4));
            }
#pragma unroll
            for (int pp = 0; pp < 2; ++pp) {
                int row = b_row + pp * 16;
                int c1 = ks * 2 + lc;
                ldsm_x4(bb[pp], smB + row * 128 + ((c1 ^ (row & 7)) << 4));
            }
#pragma unroll
            for (int mt = 0; mt < 2; ++mt)
#pragma unroll
                for (int pp = 0; pp < 2; ++pp) {
                    mma_s8(acc1[mt][2 * pp],     aq1[mt], bb[pp][0], bb[pp][2]);
                    mma_s8(acc1[mt][2 * pp + 1], aq1[mt], bb[pp][1], bb[pp][3]);
                    mma_s8(accX[mt][2 * pp],     aq2[mt], bb[pp][0], bb[pp][2]);
                    mma_s8(accX[mt][2 * pp + 1], aq2[mt], bb[pp][1], bb[pp][3]);
                }
#pragma unroll
            for (int pp = 0; pp < 2; ++pp) {
                int row = b_row + pp * 16;
                int c2 = 4 + ks * 2 + lc;
                ldsm_x4(bb[pp], smB + row * 128 + ((c2 ^ (row & 7)) << 4));
            }
#pragma unroll
            for (int mt = 0; mt < 2; ++mt)
#pragma unroll
                for (int pp = 0; pp < 2; ++pp) {
                    mma_s8(accX[mt][2 * pp],     aq1[mt], bb[pp][0], bb[pp][2]);
                    mma_s8(accX[mt][2 * pp + 1], aq1[mt], bb[pp][1], bb[pp][3]);
                }
        }
    }

    const int tr = lid >> 2;
    const int tc = (lid & 3) * 2;
    const float ix = 1.0f / 252.0f;
#pragma unroll
    for (int mt = 0; mt < 2; ++mt) {
#pragma unroll
        for (int half = 0; half < 2; ++half) {
            const int m = bm + wm * 32 + mt * 16 + tr + half * 8;
            const size_t rowoff = (size_t)m * N;
            const float sa = sA[m];
#pragma unroll
            for (int nt = 0; nt < 4; ++nt) {
                const int n = bn + wn * 32 + nt * 8 + tc;
                float v0 = (__int2float_rn(acc1[mt][nt][half * 2 + 0]) +
                            __int2float_rn(accX[mt][nt][half * 2 + 0]) * ix) *
                           sa * sB[n];
                float v1 = (__int2float_rn(acc1[mt][nt][half * 2 + 1]) +
                            __int2float_rn(accX[mt][nt][half * 2 + 1]) * ix) *
                           sa * sB[n + 1];
                const size_t idx = rowoff + n;
                if (EPI == 2) {
                    float f0 = e0[idx], f1 = e0[idx + 1];
                    v0 = gelu_f(fmaf(e1[n], f0, v0)) + f0;
                    v1 = gelu_f(fmaf(e1[n + 1], f1, v1)) + f1;
                } else if (EPI == 3) {
                    v0 += e0[idx];
                    v1 += e0[idx + 1];
                }
                if (OBF) {
                    ((bf162*)Cout)[idx >> 1] = __floats2bfloat162_rn(v0, v1);
                } else {
                    *reinterpret_cast<float2*>((float*)Cout + idx) =
                        make_float2(v0, v1);
                }
            }
        }
    }
}

// ---------------- fp32 SGEMM (encoder only, K=64) ----------------------------
#define TBM 128
#define TBN 128
#define TBK 8
__global__ void __launch_bounds__(256)
sgemm_enc(const float* __restrict__ A, const float* __restrict__ B,
          float* __restrict__ C, int M, int N, int K,
          const float* __restrict__ bias) {
    __shared__ float As[TBK][TBM + 4];
    __shared__ float Bs[TBK][TBN + 4];
    const int tid = threadIdx.x;
    const int bm = blockIdx.y * TBM;
    const int bn = blockIdx.x * TBN;
    const int arow = tid >> 1, akc = (tid & 1) * 4;
    const float* Aptr = A + (size_t)(bm + arow) * K + akc;
    const int br0 = tid >> 5, bc0 = (tid & 31) * 4;
    const float* Bptr = B + (size_t)br0 * N + bn + bc0;

    float acc[8][8];
#pragma unroll
    for (int i = 0; i < 8; i++)
#pragma unroll
        for (int j = 0; j < 8; j++) acc[i][j] = 0.0f;

    float4 aR = *reinterpret_cast<const float4*>(Aptr);
    float4 bR = *reinterpret_cast<const float4*>(Bptr);
    const int tm = tid >> 4, tn = tid & 15;

    for (int k0 = 0;;) {
        As[akc + 0][arow] = aR.x; As[akc + 1][arow] = aR.y;
        As[akc + 2][arow] = aR.z; As[akc + 3][arow] = aR.w;
        Bs[br0][bc0 + 0] = bR.x;  Bs[br0][bc0 + 1] = bR.y;
        Bs[br0][bc0 + 2] = bR.z;  Bs[br0][bc0 + 3] = bR.w;
        __syncthreads();
        k0 += TBK;
        bool more = (k0 < K);
        if (more) {
            aR = *reinterpret_cast<const float4*>(Aptr + k0);
            bR = *reinterpret_cast<const float4*>(Bptr + (size_t)k0 * N);
        }
#pragma unroll
        for (int kk = 0; kk < TBK; kk++) {
            float4 a0 = *reinterpret_cast<const float4*>(&As[kk][tm * 4]);
            float4 a1 = *reinterpret_cast<const float4*>(&As[kk][64 + tm * 4]);
            float4 b0 = *reinterpret_cast<const float4*>(&Bs[kk][tn * 4]);
            float4 b1 = *reinterpret_cast<const float4*>(&Bs[kk][64 + tn * 4]);
            float av[8] = {a0.x, a0.y, a0.z, a0.w, a1.x, a1.y, a1.z, a1.w};
            float bv[8] = {b0.x, b0.y, b0.z, b0.w, b1.x, b1.y, b1.z, b1.w};
#pragma unroll
            for (int i = 0; i < 8; i++)
#pragma unroll
                for (int j = 0; j < 8; j++)
                    acc[i][j] = fmaf(av[i], bv[j], acc[i][j]);
        }
        __syncthreads();
        if (!more) break;
    }
#pragma unroll
    for (int i = 0; i < 8; i++) {
        int r = bm + ((i < 4) ? (tm * 4 + i) : (64 + tm * 4 + i - 4));
        size_t rowoff = (size_t)r * N;
#pragma unroll
        for (int j = 0; j < 8; j++) {
            int c = bn + ((j < 4) ? (tn * 4 + j) : (64 + tn * 4 + j - 4));
            C[rowoff + c] = acc[i][j] + bias[c];
        }
    }
}

// ---------------- per-layer weight prep --------------------------------------
// W2 rows (2p = re, 2p+1 = im). Block per p; also computes lamb/coef/chs inline.
__global__ void __launch_bounds__(256)
prep_W2q_k(const float* __restrict__ b_re, const float* __restrict__ b_im,
           const float* __restrict__ lam_re, const float* __restrict__ lam_im,
           const float* __restrict__ log_step) {
    __shared__ float redA[8], redB[8];
    const int p = blockIdx.x;
    const int tid = threadIdx.x;
    float dt = expf(log_step[p]);
    float lr = lam_re[p], li = lam_im[p];
    float er = expf(lr * dt);
    float lbx = er * cosf(li * dt), lby = er * sinf(li * dt);
    float nr = lbx - 1.0f, ni = lby;
    float den = lr * lr + li * li;
    float2 c2 = make_float2((nr * lr + ni * li) / den, (ni * lr - nr * li) / den);
    if (tid == 0) {
        g_lamb[p] = make_float2(lbx, lby);
        float mag2 = lbx * lbx + lby * lby;
        float s = rsqrtf(fmaxf(1.0f - mag2, 1e-6f));
        s = fminf(fmaxf(s, 1.0f), 1000.0f);
        g_chs[p] = s;
        g_chsi[p] = 1.0f / s;
    }
    float vre[4], vim[4];
    float amr = 0.0f, ami = 0.0f;
#pragma unroll
    for (int k = 0; k < 4; ++k) {
        int h = tid + k * 256;
        float br = b_re[(size_t)p * DM + h];
        float bi = b_im[(size_t)p * DM + h];
        vre[k] = c2.x * br - c2.y * bi;
        vim[k] = c2.x * bi + c2.y * br;
        amr = fmaxf(amr, fabsf(vre[k]));
        ami = fmaxf(ami, fabsf(vim[k]));
    }
#pragma unroll
    for (int o = 16; o > 0; o >>= 1) {
        amr = fmaxf(amr, __shfl_xor_sync(0xffffffffu, amr, o));
        ami = fmaxf(ami, __shfl_xor_sync(0xffffffffu, ami, o));
    }
    if ((tid & 31) == 0) { redA[tid >> 5] = amr; redB[tid >> 5] = ami; }
    __syncthreads();
    amr = redA[0]; ami = redB[0];
#pragma unroll
    for (int i = 1; i < 8; ++i) { amr = fmaxf(amr, redA[i]); ami = fmaxf(ami, redB[i]); }
    float qr = amr > 0 ? 127.0f / amr : 0.0f;
    float qi = ami > 0 ? 127.0f / ami : 0.0f;
#pragma unroll
    for (int k = 0; k < 4; ++k) {
        int h = tid + k * 256;
        int a1, a2;
        quant2i(vre[k], qr, a1, a2);
        g_W2q1[(size_t)(2 * p) * DM + h] = (int8_t)a1;
        g_W2q2[(size_t)(2 * p) * DM + h] = (int8_t)a2;
        quant2i(vim[k], qi, a1, a2);
        g_W2q1[(size_t)(2 * p + 1) * DM + h] = (int8_t)a1;
        g_W2q2[(size_t)(2 * p + 1) * DM + h] = (int8_t)a2;
    }
    if (tid == 0) {
        g_sW2[2 * p]     = amr * (1.0f / 127.0f);
        g_sW2[2 * p + 1] = ami * (1.0f / 127.0f);
    }
}

// Cw rows (h): interleaved re/-im * channel scale. Block per h, 256 threads.
__global__ void __launch_bounds__(256)
prep_Cwq_k(const float* __restrict__ c_re, const float* __restrict__ c_im) {
    __shared__ float red[8];
    const int h = blockIdx.x;
    const int tid = threadIdx.x;
    float v[8];
    float am = 0.0f;
#pragma unroll
    for (int k = 0; k < 4; ++k) {
        int p = tid + k * 256;
        float re = c_re[(size_t)h * DM + p] * g_chs[p];
        float im = -c_im[(size_t)h * DM + p] * g_chs[p];
        v[2 * k] = re;
        v[2 * k + 1] = im;
        am = fmaxf(am, fmaxf(fabsf(re), fabsf(im)));
    }
#pragma unroll
    for (int o = 16; o > 0; o >>= 1) am = fmaxf(am, __shfl_xor_sync(0xffffffffu, am, o));
    if ((tid & 31) == 0) red[tid >> 5] = am;
    __syncthreads();
    am = red[0];
#pragma unroll
    for (int i = 1; i < 8; ++i) am = fmaxf(am, red[i]);
    float qs = am > 0 ? 127.0f / am : 0.0f;
#pragma unroll
    for (int k = 0; k < 4; ++k) {
        int p = tid + k * 256;
        int a1, a2, b1, b2;
        quant2i(v[2 * k], qs, a1, a2);
        quant2i(v[2 * k + 1], qs, b1, b2);
        uint16_t w1 = (uint16_t)((uint8_t)a1 | ((uint16_t)(uint8_t)b1 << 8));
        uint16_t w2 = (uint16_t)((uint8_t)a2 | ((uint16_t)(uint8_t)b2 << 8));
        *(uint16_t*)(g_Cwq1 + (size_t)h * DM2 + 2 * p) = w1;
        *(uint16_t*)(g_Cwq2 + (size_t)h * DM2 + 2 * p) = w2;
    }
    if (tid == 0) g_sCw[h] = am * (1.0f / 127.0f);
}

// fp32 transpose: in [R][C2] -> out [C2][R]
__global__ void wtrans_k(const float* __restrict__ in, float* __restrict__ outT,
                         int R, int C2) {
    __shared__ float t[32][33];
    int r = blockIdx.y * 32 + threadIdx.y;
    int c = blockIdx.x * 32 + threadIdx.x;
    t[threadIdx.y][threadIdx.x] = in[(size_t)r * C2 + c];
    __syncthreads();
    int orow = blockIdx.x * 32 + threadIdx.y;
    int ocol = blockIdx.y * 32 + threadIdx.x;
    outT[(size_t)orow * R + ocol] = t[threadIdx.x][threadIdx.y];
}

// weight row quantizer (fp32 in, 1024/row, 256 thr x 4 contiguous)
__global__ void __launch_bounds__(256)
rowq_w_k(const float* __restrict__ in, int8_t* __restrict__ q1,
         int8_t* __restrict__ q2, float* __restrict__ sOut) {
    __shared__ float red[8];
    const size_t base = (size_t)blockIdx.x * DM;
    const int tid = threadIdx.x;
    const int c0 = tid * 4;
    float4 vv = *reinterpret_cast<const float4*>(in + base + c0);
    float v[4] = {vv.x, vv.y, vv.z, vv.w};
    float am = 0.0f;
#pragma unroll
    for (int k = 0; k < 4; ++k) am = fmaxf(am, fabsf(v[k]));
#pragma unroll
    for (int o = 16; o > 0; o >>= 1) am = fmaxf(am, __shfl_xor_sync(0xffffffffu, am, o));
    if ((tid & 31) == 0) red[tid >> 5] = am;
    __syncthreads();
    am = red[0];
#pragma unroll
    for (int i = 1; i < 8; ++i) am = fmaxf(am, red[i]);
    float qs = am > 0 ? 127.0f / am : 0.0f;
    int a1[4], a2[4];
#pragma unroll
    for (int k = 0; k < 4; ++k) quant2i(v[k], qs, a1[k], a2[k]);
    *(uint32_t*)(q1 + base + c0) = pack4(a1[0], a1[1], a1[2], a1[3]);
    *(uint32_t*)(q2 + base + c0) = pack4(a2[0], a2[1], a2[2], a2[3]);
    if (tid == 0) sOut[blockIdx.x] = am * (1.0f / 127.0f);
}

// xs row quantizer: bf16 in, 2048/row, channel-flattening. 256 thr x 8 contig.
__global__ void __launch_bounds__(256)
rowq_xs_k(const bf16* __restrict__ in, int8_t* __restrict__ q1,
          int8_t* __restrict__ q2, float* __restrict__ sOut) {
    __shared__ float red[8];
    const size_t base = (size_t)blockIdx.x * DM2;
    const int tid = threadIdx.x;
    const int c0 = tid * 8;
    const bf162* pin = reinterpret_cast<const bf162*>(in + base + c0);
    float v[8];
    float am = 0.0f;
#pragma unroll
    for (int k = 0; k < 4; ++k) {
        float2 f = __bfloat1622float2(pin[k]);
        float sc = g_chsi[(c0 >> 1) + k];
        v[2 * k] = f.x * sc;
        v[2 * k + 1] = f.y * sc;
        am = fmaxf(am, fmaxf(fabsf(v[2 * k]), fabsf(v[2 * k + 1])));
    }
#pragma unroll
    for (int o = 16; o > 0; o >>= 1) am = fmaxf(am, __shfl_xor_sync(0xffffffffu, am, o));
    if ((tid & 31) == 0) red[tid >> 5] = am;
    __syncthreads();
    am = red[0];
#pragma unroll
    for (int i = 1; i < 8; ++i) am = fmaxf(am, red[i]);
    float qs = am > 0 ? 127.0f / am : 0.0f;
    uint2 w1, w2;
    quant8(v, qs, w1, w2);
    *(uint2*)(q1 + base + c0) = w1;
    *(uint2*)(q2 + base + c0) = w2;
    if (tid == 0) sOut[blockIdx.x] = am * (1.0f / 127.0f);
}

// ---------------- scan: fp32 recurrence over bf16 data, in-place -------------
__global__ void scan_k(bf162* __restrict__ bu) {
    int idx = blockIdx.x * blockDim.x + threadIdx.x;
    if (idx >= BATCH * DM) return;
    int b = idx >> 10, p = idx & (DM - 1);
    float2 a = g_lamb[p];
    bf162* ptr = bu + (size_t)b * SEQ * DM + p;
    float xr = 0.0f, xi = 0.0f;
    const int U = 8;
    bf162 cur[U], nxt[U];
#pragma unroll
    for (int i = 0; i < U; i++) cur[i] = ptr[(size_t)i * DM];
#pragma unroll
    for (int i = 0; i < U; i++) nxt[i] = __floats2bfloat162_rn(0.f, 0.f);
    for (int l0 = 0; l0 < SEQ; l0 += U) {
        if (l0 + U < SEQ) {
#pragma unroll
            for (int i = 0; i < U; i++) nxt[i] = ptr[(size_t)(l0 + U + i) * DM];
        }
#pragma unroll
        for (int i = 0; i < U; i++) {
            float2 u = __bfloat1622float2(cur[i]);
            float nr = fmaf(a.x, xr, fmaf(-a.y, xi, u.x));
            float ni = fmaf(a.x, xi, fmaf(a.y, xr, u.y));
            xr = nr; xi = ni;
            ptr[(size_t)(l0 + i) * DM] = __floats2bfloat162_rn(xr, xi);
        }
#pragma unroll
        for (int i = 0; i < U; i++) cur[i] = nxt[i];
    }
}

// ---------------- LayerNorm (+optional residual add, +optional int8 quant) ---
__global__ void __launch_bounds__(128)
ln_k(const float* __restrict__ in, const float* __restrict__ add,
     float* __restrict__ out, int8_t* __restrict__ q1, int8_t* __restrict__ q2,
     float* __restrict__ sOut,
     const float* __restrict__ g, const float* __restrict__ bb) {
    __shared__ float red[8];
    __shared__ float redm[4];
    size_t base = (size_t)blockIdx.x * DM;
    int t = threadIdx.x;
    int c0 = t * 8;
    float v[8];
    float4 i0 = *reinterpret_cast<const float4*>(in + base + c0);
    float4 i1 = *reinterpret_cast<const float4*>(in + base + c0 + 4);
    v[0] = i0.x; v[1] = i0.y; v[2] = i0.z; v[3] = i0.w;
    v[4] = i1.x; v[5] = i1.y; v[6] = i1.z; v[7] = i1.w;
    if (add) {
        float4 a0 = *reinterpret_cast<const float4*>(add + base + c0);
        float4 a1 = *reinterpret_cast<const float4*>(add + base + c0 + 4);
        v[0] += a0.x; v[1] += a0.y; v[2] += a0.z; v[3] += a0.w;
        v[4] += a1.x; v[5] += a1.y; v[6] += a1.z; v[7] += a1.w;
    }
    float s = 0.0f;
#pragma unroll
    for (int i = 0; i < 8; i++) s += v[i];
#pragma unroll
    for (int o = 16; o > 0; o >>= 1) s += __shfl_xor_sync(0xffffffffu, s, o);
    if ((t & 31) == 0) red[t >> 5] = s;
    __syncthreads();
    float mean = (red[0] + red[1] + red[2] + red[3]) * (1.0f / DM);
    float s2 = 0.0f;
#pragma unroll
    for (int i = 0; i < 8; i++) { float d = v[i] - mean; s2 += d * d; }
#pragma unroll
    for (int o = 16; o > 0; o >>= 1) s2 += __shfl_xor_sync(0xffffffffu, s2, o);
    if ((t & 31) == 0) red[4 + (t >> 5)] = s2;
    __syncthreads();
    float var = (red[4] + red[5] + red[6] + red[7]) * (1.0f / DM);
    float inv = rsqrtf(var + 1e-5f);
    float4 g0 = *reinterpret_cast<const float4*>(g + c0);
    float4 g1 = *reinterpret_cast<const float4*>(g + c0 + 4);
    float4 b0 = *reinterpret_cast<const float4*>(bb + c0);
    float4 b1 = *reinterpret_cast<const float4*>(bb + c0 + 4);
    float gg[8] = {g0.x, g0.y, g0.z, g0.w, g1.x, g1.y, g1.z, g1.w};
    float bbv[8] = {b0.x, b0.y, b0.z, b0.w, b1.x, b1.y, b1.z, b1.w};
    float y[8];
    float am = 0.0f;
#pragma unroll
    for (int i = 0; i < 8; i++) {
        y[i] = (v[i] - mean) * inv * gg[i] + bbv[i];
        am = fmaxf(am, fabsf(y[i]));
    }
    *reinterpret_cast<float4*>(out + base + c0) =
        make_float4(y[0], y[1], y[2], y[3]);
    *reinterpret_cast<float4*>(out + base + c0 + 4) =
        make_float4(y[4], y[5], y[6], y[7]);
    if (q1) {
#pragma unroll
        for (int o = 16; o > 0; o >>= 1) am = fmaxf(am, __shfl_xor_sync(0xffffffffu, am, o));
        if ((t & 31) == 0) redm[t >> 5] = am;
        __syncthreads();
        am = fmaxf(fmaxf(redm[0], redm[1]), fmaxf(redm[2], redm[3]));
        float qs = am > 0 ? 127.0f / am : 0.0f;
        uint2 w1, w2;
        quant8(y, qs, w1, w2);
        *(uint2*)(q1 + base + c0) = w1;
        *(uint2*)(q2 + base + c0) = w2;
        if (t == 0) sOut[blockIdx.x] = am * (1.0f / 127.0f);
    }
}

// ---------------- GEGLU row-quant (bf16 in) -----------------------------------
__global__ void __launch_bounds__(128)
geglu_rowq_k(const bf16* __restrict__ u2, int8_t* __restrict__ q1,
             int8_t* __restrict__ q2, float* __restrict__ sOut) {
    __shared__ float redm[4];
    const size_t m = blockIdx.x;
    const size_t base2 = m * DM2;
    const size_t base = m * DM;
    const int t = threadIdx.x;
    const int c0 = t * 8;
    const bf162* pa = reinterpret_cast<const bf162*>(u2 + base2 + c0);
    const bf162* pg = reinterpret_cast<const bf162*>(u2 + base2 + DM + c0);
    float v[8];
    float am = 0.0f;
#pragma unroll
    for (int k = 0; k < 4; ++k) {
        float2 fa = __bfloat1622float2(pa[k]);
        float2 fg = __bfloat1622float2(pg[k]);
        v[2 * k]     = fa.x * gelu_f(fg.x);
        v[2 * k + 1] = fa.y * gelu_f(fg.y);
        am = fmaxf(am, fmaxf(fabsf(v[2 * k]), fabsf(v[2 * k + 1])));
    }
#pragma unroll
    for (int o = 16; o > 0; o >>= 1) am = fmaxf(am, __shfl_xor_sync(0xffffffffu, am, o));
    if ((t & 31) == 0) redm[t >> 5] = am;
    __syncthreads();
    am = fmaxf(fmaxf(redm[0], redm[1]), fmaxf(redm[2], redm[3]));
    float qs = am > 0 ? 127.0f / am : 0.0f;
    uint2 w1, w2;
    quant8(v, qs, w1, w2);
    *(uint2*)(q1 + base + c0) = w1;
    *(uint2*)(q2 + base + c0) = w2;
    if (t == 0) sOut[blockIdx.x] = am * (1.0f / 127.0f);
}

// ---------------- mean pool + decode -----------------------------------------
__global__ void pool_k(const float* __restrict__ h, float* __restrict__ pooled) {
    int idx = blockIdx.x * blockDim.x + threadIdx.x;
    if (idx >= BATCH * DM) return;
    int b = idx >> 10, d = idx & (DM - 1);
    const float* p = h + (size_t)b * SEQ * DM + d;
    float s = 0.0f;
#pragma unroll 8
    for (int l = 0; l < SEQ; l++) s += p[(size_t)l * DM];
    pooled[idx] = s * (1.0f / SEQ);
}

__global__ void dec_k(const float* __restrict__ pooled,
                      const float* __restrict__ w,
                      const float* __restrict__ b,
                      float* __restrict__ out) {
    __shared__ float red[8];
    int bi = blockIdx.x;
    int t = threadIdx.x;
    float s = 0.0f;
    for (int d = t; d < DM; d += 256) s += pooled[bi * DM + d] * w[d];
#pragma unroll
    for (int o = 16; o > 0; o >>= 1) s += __shfl_xor_sync(0xffffffffu, s, o);
    if ((t & 31) == 0) red[t >> 5] = s;
    __syncthreads();
    if (t == 0) {
        float tot = 0.0f;
#pragma unroll
        for (int i = 0; i < 8; i++) tot += red[i];
        out[bi] = tot + b[0];
    }
}

// ---------------- driver ----------------
extern "C" void kernel_launch(void* const* d_in, const int* in_sizes, int n_in,
                              void* d_out, int out_size) {
    const float* x        = (const float*)d_in[0];
    const float* enc_w    = (const float*)d_in[1];
    const float* enc_b    = (const float*)d_in[2];
    const float* ln1_g    = (const float*)d_in[3];
    const float* ln1_b    = (const float*)d_in[4];
    const float* lam_re   = (const float*)d_in[5];
    const float* lam_im   = (const float*)d_in[6];
    const float* b_re     = (const float*)d_in[7];
    const float* b_im     = (const float*)d_in[8];
    const float* c_re     = (const float*)d_in[9];
    const float* c_im     = (const float*)d_in[10];
    const float* d_skip   = (const float*)d_in[11];
    const float* log_step = (const float*)d_in[12];
    const float* ffn_g    = (const float*)d_in[13];
    const float* ffn_b    = (const float*)d_in[14];
    const float* ff_enc_w = (const float*)d_in[15];
    const float* ff_dec_w = (const float*)d_in[16];
    const float* norm_g   = (const float*)d_in[17];
    const float* norm_b   = (const float*)d_in[18];
    const float* dec_w    = (const float*)d_in[19];
    const float* dec_b    = (const float*)d_in[20];
    float* out = (float*)d_out;

    static int attr_done = 0;
    if (!attr_done) {
        cudaFuncSetAttribute((const void*)imma_gemm<0, true>,
                             cudaFuncAttributeMaxDynamicSharedMemorySize, SMEM_GEMM);
        cudaFuncSetAttribute((const void*)imma_gemm<2, false>,
                             cudaFuncAttributeMaxDynamicSharedMemorySize, SMEM_GEMM);
        cudaFuncSetAttribute((const void*)imma_gemm<3, false>,
                             cudaFuncAttributeMaxDynamicSharedMemorySize, SMEM_GEMM);
        attr_done = 1;
    }

    float *p_h, *p_fx, *p_fy, *p_z, *p_wtmp, *p_pooled;
    bf16 *p_big;
    int8_t *p_fxq1, *p_fxq2, *p_xsq1, *p_xsq2, *p_fyq1, *p_fyq2, *p_ggq1, *p_ggq2;
    int8_t *p_W2q1, *p_W2q2, *p_Cwq1, *p_Cwq2, *p_feq1, *p_feq2, *p_fdq1, *p_fdq2;
    float *p_sfx, *p_sxs, *p_sfy, *p_sgg, *p_sW2, *p_sCw, *p_sfe, *p_sfd;
    cudaGetSymbolAddress((void**)&p_h, g_h);
    cudaGetSymbolAddress((void**)&p_fx, g_fx);
    cudaGetSymbolAddress((void**)&p_fy, g_fy);
    cudaGetSymbolAddress((void**)&p_z, g_z);
    cudaGetSymbolAddress((void**)&p_big, g_big);
    cudaGetSymbolAddress((void**)&p_wtmp, g_wtmp);
    cudaGetSymbolAddress((void**)&p_pooled, g_pooled);
    cudaGetSymbolAddress((void**)&p_fxq1, g_fxq1);
    cudaGetSymbolAddress((void**)&p_fxq2, g_fxq2);
    cudaGetSymbolAddress((void**)&p_xsq1, g_xsq1);
    cudaGetSymbolAddress((void**)&p_xsq2, g_xsq2);
    cudaGetSymbolAddress((void**)&p_fyq1, g_fyq1);
    cudaGetSymbolAddress((void**)&p_fyq2, g_fyq2);
    cudaGetSymbolAddress((void**)&p_ggq1, g_ggq1);
    cudaGetSymbolAddress((void**)&p_ggq2, g_ggq2);
    cudaGetSymbolAddress((void**)&p_W2q1, g_W2q1);
    cudaGetSymbolAddress((void**)&p_W2q2, g_W2q2);
    cudaGetSymbolAddress((void**)&p_Cwq1, g_Cwq1);
    cudaGetSymbolAddress((void**)&p_Cwq2, g_Cwq2);
    cudaGetSymbolAddress((void**)&p_feq1, g_feq1);
    cudaGetSymbolAddress((void**)&p_feq2, g_feq2);
    cudaGetSymbolAddress((void**)&p_fdq1, g_fdq1);
    cudaGetSymbolAddress((void**)&p_fdq2, g_fdq2);
    cudaGetSymbolAddress((void**)&p_sfx, g_sfx);
    cudaGetSymbolAddress((void**)&p_sxs, g_sxs);
    cudaGetSymbolAddress((void**)&p_sfy, g_sfy);
    cudaGetSymbolAddress((void**)&p_sgg, g_sgg);
    cudaGetSymbolAddress((void**)&p_sW2, g_sW2);
    cudaGetSymbolAddress((void**)&p_sCw, g_sCw);
    cudaGetSymbolAddress((void**)&p_sfe, g_sfe);
    cudaGetSymbolAddress((void**)&p_sfd, g_sfd);

    const int M = MROWS;

    // #1: encoder h = x @ enc_w + enc_b  (fp32, K=64)
    sgemm_enc<<<dim3(DM / TBN, M / TBM), 256>>>(x, enc_w, p_h, M, DM, D_IN, enc_b);

    for (int i = 0; i < NL; i++) {
        const size_t w1 = (size_t)i * DM;
        const size_t w2 = (size_t)i * DM * DM;
        const size_t w3 = (size_t)i * DM * DM2;

        // #2 (layer 0): W2 quant + inline lamb/chs
        prep_W2q_k<<<DM, 256>>>(b_re + w2, b_im + w2,
                                lam_re + w1, lam_im + w1, log_step + w1);
        // #3: fx = LN(h) + quant
        ln_k<<<M, 128>>>(p_h, nullptr, p_fx, p_fxq1, p_fxq2, p_sfx,
                         ln1_g + w1, ln1_b + w1);
        // #4: Bu = fx @ W2^T  [M, 2P] bf16 out  <-- ncu-captured launch
        imma_gemm<0, true><<<dim3(DM2 / 64, M / 128), 256, SMEM_GEMM>>>(
            p_fxq1, p_fxq2, p_W2q1, p_W2q2, p_big, DM2, DM,
            p_sfx, p_sW2, nullptr, nullptr);
        // #5: Cw quant (needs g_chs from #2)
        prep_Cwq_k<<<DM, 256>>>(c_re + w2, c_im + w2);
        // sequential complex scan, in place (bf16 storage, fp32 recurrence)
        scan_k<<<(BATCH * DM) / 128, 128>>>((bf162*)p_big);
        // quantize xs rows (channel-flattened)
        rowq_xs_k<<<M, 256>>>(p_big, p_xsq1, p_xsq2, p_sxs);
        // z = gelu(xs @ Cw^T + d*fx) + fx
        imma_gemm<2, false><<<dim3(DM / 64, M / 128), 256, SMEM_GEMM>>>(
            p_xsq1, p_xsq2, p_Cwq1, p_Cwq2, p_z, DM, DM2,
            p_sxs, p_sCw, p_fx, d_skip + w1);
        // ff_enc^T quant
        wtrans_k<<<dim3(DM2 / 32, DM / 32), dim3(32, 32)>>>(ff_enc_w + w3, p_wtmp, DM, DM2);
        rowq_w_k<<<DM2, 256>>>(p_wtmp, p_feq1, p_feq2, p_sfe);
        // fy = LN(z) + quant
        ln_k<<<M, 128>>>(p_z, nullptr, p_fy, p_fyq1, p_fyq2, p_sfy,
                         ffn_g + w1, ffn_b + w1);
        // u2 = fy @ ff_enc  [M, 2D] bf16 out
        imma_gemm<0, true><<<dim3(DM2 / 64, M / 128), 256, SMEM_GEMM>>>(
            p_fyq1, p_fyq2, p_feq1, p_feq2, p_big, DM2, DM,
            p_sfy, p_sfe, nullptr, nullptr);
        // geglu + quant
        geglu_rowq_k<<<M, 128>>>(p_big, p_ggq1, p_ggq2, p_sgg);
        // ff_dec^T quant
        wtrans_k<<<dim3(DM / 32, DM / 32), dim3(32, 32)>>>(ff_dec_w + w2, p_wtmp, DM, DM);
        rowq_w_k<<<DM, 256>>>(p_wtmp, p_fdq1, p_fdq2, p_sfd);
        // z2 = gg @ ff_dec + fy   (into p_z)
        imma_gemm<3, false><<<dim3(DM / 64, M / 128), 256, SMEM_GEMM>>>(
            p_ggq1, p_ggq2, p_fdq1, p_fdq2, p_z, DM, DM,
            p_sgg, p_sfd, p_fy, nullptr);
        // h = LN(z2 + h)
        ln_k<<<M, 128>>>(p_z, p_h, p_h, nullptr, nullptr, nullptr,
                         norm_g + w1, norm_b + w1);
    }

    pool_k<<<(BATCH * DM) / 128, 128>>>(p_h, p_pooled);
    dec_k<<<BATCH, 256>>>(p_pooled, dec_w, dec_b, out);
}

// round 11
// speedup vs baseline: 3.3141x; 1.0087x over previous
#include <cuda_runtime.h>
#include <cuda_bf16.h>
#include <math.h>
#include <stdint.h>

// ---------------- problem constants ----------------
#define BATCH   8
#define SEQ     2048
#define D_IN    64
#define DM      1024
#define DM2     2048
#define NL      4
#define MROWS   (BATCH*SEQ)   // 16384

typedef __nv_bfloat16 bf16;
typedef __nv_bfloat162 bf162;

// ---------------- scratch (device globals) ----------------
__device__ float g_h  [(size_t)MROWS * DM];
__device__ float g_fx [(size_t)MROWS * DM];
__device__ float g_fy [(size_t)MROWS * DM];
__device__ float g_z  [(size_t)MROWS * DM];
__device__ __align__(16) bf16 g_big[(size_t)MROWS * DM2];   // bu->xs (in place); then u2
__device__ float g_wtmp[(size_t)DM2 * DM];                  // transposed weight staging

__device__ __align__(16) int8_t g_fxq1[(size_t)MROWS * DM];
__device__ __align__(16) int8_t g_fxq2[(size_t)MROWS * DM];
__device__ __align__(16) int8_t g_xsq1[(size_t)MROWS * DM2];
__device__ __align__(16) int8_t g_xsq2[(size_t)MROWS * DM2];
__device__ __align__(16) int8_t g_fyq1[(size_t)MROWS * DM];
__device__ __align__(16) int8_t g_fyq2[(size_t)MROWS * DM];
__device__ __align__(16) int8_t g_ggq1[(size_t)MROWS * DM];
__device__ __align__(16) int8_t g_ggq2[(size_t)MROWS * DM];

__device__ __align__(16) int8_t g_W2q1[(size_t)DM2 * DM];
__device__ __align__(16) int8_t g_W2q2[(size_t)DM2 * DM];
__device__ __align__(16) int8_t g_Cwq1[(size_t)DM * DM2];
__device__ __align__(16) int8_t g_Cwq2[(size_t)DM * DM2];
__device__ __align__(16) int8_t g_feq1[(size_t)DM2 * DM];
__device__ __align__(16) int8_t g_feq2[(size_t)DM2 * DM];
__device__ __align__(16) int8_t g_fdq1[(size_t)DM * DM];
__device__ __align__(16) int8_t g_fdq2[(size_t)DM * DM];

__device__ float g_sfx[MROWS], g_sxs[MROWS], g_sfy[MROWS], g_sgg[MROWS];
__device__ float g_sW2[DM2], g_sCw[DM], g_sfe[DM2], g_sfd[DM];

__device__ float2 g_lamb[DM];
__device__ float  g_chs [DM];    // channel flattening scale (mult into Cw)
__device__ float  g_chsi[DM];    // inverse (mult into xs)
__device__ float  g_pooled[BATCH * DM];

// ---------------- helpers ----------------
__device__ __forceinline__ float gelu_f(float x) {
    return 0.5f * x * (1.0f + erff(x * 0.70710678118654752f));
}
__device__ __forceinline__ uint32_t s2u(const void* p) {
    uint32_t a;
    asm("{ .reg .u64 t; cvta.to.shared.u64 t, %1; cvt.u32.u64 %0, t; }"
        : "=r"(a) : "l"(p));
    return a;
}
__device__ __forceinline__ void cpasync16(uint32_t s, const void* g) {
    asm volatile("cp.async.cg.shared.global [%0], [%1], 16;" :: "r"(s), "l"(g));
}
__device__ __forceinline__ void ldsm_x4(uint32_t* r, uint32_t addr) {
    asm volatile("ldmatrix.sync.aligned.m8n8.x4.shared.b16 {%0,%1,%2,%3}, [%4];"
                 : "=r"(r[0]), "=r"(r[1]), "=r"(r[2]), "=r"(r[3]) : "r"(addr));
}
__device__ __forceinline__ void mma_s8(int* d, const uint32_t* a,
                                       uint32_t b0, uint32_t b1) {
    asm volatile(
        "mma.sync.aligned.m16n8k32.row.col.s32.s8.s8.s32 "
        "{%0,%1,%2,%3}, {%4,%5,%6,%7}, {%8,%9}, {%0,%1,%2,%3};"
        : "+r"(d[0]), "+r"(d[1]), "+r"(d[2]), "+r"(d[3])
        : "r"(a[0]), "r"(a[1]), "r"(a[2]), "r"(a[3]), "r"(b0), "r"(b1));
}
// quantize v*qs into 2 limbs
__device__ __forceinline__ void quant2i(float v, float qs, int& o1, int& o2) {
    float t = v * qs;
    o1 = __float2int_rn(t);
    o2 = __float2int_rn((t - (float)o1) * 252.0f);
}
__device__ __forceinline__ uint32_t pack4(int a, int b, int c, int d) {
    return (uint32_t)(uint8_t)a | ((uint32_t)(uint8_t)b << 8) |
           ((uint32_t)(uint8_t)c << 16) | ((uint32_t)(uint8_t)d << 24);
}
__device__ __forceinline__ void quant8(const float* v, float qs,
                                       uint2& w1, uint2& w2) {
    int a1[8], a2[8];
#pragma unroll
    for (int i = 0; i < 8; i++) quant2i(v[i], qs, a1[i], a2[i]);
    w1.x = pack4(a1[0], a1[1], a1[2], a1[3]);
    w1.y = pack4(a1[4], a1[5], a1[6], a1[7]);
    w2.x = pack4(a2[0], a2[1], a2[2], a2[3]);
    w2.y = pack4(a2[4], a2[5], a2[6], a2[7]);
}

// ---------------- IMMA split-int8 GEMM: C[M,N] = sA.sB.(A @ B^T) -------------
// CTA 64x64, 4 warps (2m x 2n, warp tile 32x32), 4 CTAs/SM. K-chunk 64; smem
// row = 128B: [q1 64B | q2 64B], XOR swizzle. Stage 16KB (A 8K + B 8K),
// 3 stages. One barrier per chunk. Per k32 step: 3 passes (q1q1 -> acc1;
// q2q1, q1q2 -> accX). Dequant: sA[m]*sB[n]*(acc1 + accX/252).
// EPI 0: plain  2: gelu(v + e1[n]*e0[m,n]) + e0[m,n]  3: v + e0[m,n]
// OBF: write bf162 pairs instead of float2.
#define STAGE_B   16384
#define NSTAGE    3
#define SMEM_GEMM (NSTAGE * STAGE_B)

template <int EPI, bool OBF>
__global__ void __launch_bounds__(128, 4)
imma_gemm(const int8_t* __restrict__ Aq1, const int8_t* __restrict__ Aq2,
          const int8_t* __restrict__ Bq1, const int8_t* __restrict__ Bq2,
          void* __restrict__ Cout, int N, int K,
          const float* __restrict__ sA, const float* __restrict__ sB,
          const float* __restrict__ e0, const float* __restrict__ e1) {
    extern __shared__ __align__(128) char smem[];
    const int tid = threadIdx.x;
    const int wid = tid >> 5;
    const int lid = tid & 31;
    const int wm = wid & 1;          // 2 warps along M (32 rows each)
    const int wn = wid >> 1;         // 2 warps along N (32 cols each)
    const int bm = blockIdx.y * 64;
    const int bn = blockIdx.x * 64;
    const uint32_t sbase = s2u(smem);
    const int nch = K >> 6;

    auto load_stage = [&](int st, int c) {
        const int kc = c << 6;
        const uint32_t stb = sbase + st * STAGE_B;
#pragma unroll
        for (int t = 0; t < 8; ++t) {
            int i = tid + t * 128;            // 0..1023
            int isB = (i >= 512);
            int ii = i & 511;
            int row = ii >> 3, j = ii & 7;
            const int8_t* src = isB ? ((j < 4) ? Bq1 : Bq2)
                                    : ((j < 4) ? Aq1 : Aq2);
            size_t go = (size_t)((isB ? bn : bm) + row) * K + kc + (j & 3) * 16;
            uint32_t dst = stb + (isB ? 8192u : 0u) + row * 128 +
                           (uint32_t)((j ^ (row & 7)) << 4);
            cpasync16(dst, src + go);
        }
    };

    int acc1[2][4][4], accX[2][4][4];
#pragma unroll
    for (int mt = 0; mt < 2; mt++)
#pragma unroll
        for (int nt = 0; nt < 4; nt++)
#pragma unroll
            for (int q = 0; q < 4; q++) { acc1[mt][nt][q] = 0; accX[mt][nt][q] = 0; }

    load_stage(0, 0); asm volatile("cp.async.commit_group;" ::: "memory");
    load_stage(1, 1); asm volatile("cp.async.commit_group;" ::: "memory");

    // ldmatrix lane mapping: row = base + (lid & 15), c16-unit = +(lid >> 4)
    const int a_row = wm * 32 + (lid & 15);
    const int b_row = wn * 32 + (lid & 15);
    const int lc = lid >> 4;

    int st = 0;   // rotating stage index for chunk c
    for (int c = 0; c < nch; ++c) {
        if (c + 1 < nch) asm volatile("cp.async.wait_group 1;" ::: "memory");
        else             asm volatile("cp.async.wait_group 0;" ::: "memory");
        // single barrier per chunk: publishes chunk c's smem and orders all
        // threads' compute of chunk c-1 before the load below overwrites
        // its buffer ((c+2)%3 == (c-1)%3).
        __syncthreads();

        int st2 = st + 2; if (st2 >= 3) st2 -= 3;
        if (c + 2 < nch) load_stage(st2, c + 2);
        asm volatile("cp.async.commit_group;" ::: "memory");

        const uint32_t smA = sbase + st * STAGE_B;
        const uint32_t smB = smA + 8192;
#pragma unroll
        for (int ks = 0; ks < 2; ++ks) {
            uint32_t aq1[2][4], aq2[2][4], bb[2][4];
#pragma unroll
            for (int mt = 0; mt < 2; ++mt) {
                int row = a_row + mt * 16;
                int c1 = ks * 2 + lc;
                int c2 = 4 + ks * 2 + lc;
                ldsm_x4(aq1[mt], smA + row * 128 + ((c1 ^ (row & 7)) << 4));
                ldsm_x4(aq2[mt], smA + row * 128 + ((c2 ^ (row & 7)) << 4));
            }
#pragma unroll
            for (int pp = 0; pp < 2; ++pp) {
                int row = b_row + pp * 16;
                int c1 = ks * 2 + lc;
                ldsm_x4(bb[pp], smB + row * 128 + ((c1 ^ (row & 7)) << 4));
            }
#pragma unroll
            for (int mt = 0; mt < 2; ++mt)
#pragma unroll
                for (int pp = 0; pp < 2; ++pp) {
                    mma_s8(acc1[mt][2 * pp],     aq1[mt], bb[pp][0], bb[pp][2]);
                    mma_s8(acc1[mt][2 * pp + 1], aq1[mt], bb[pp][1], bb[pp][3]);
                    mma_s8(accX[mt][2 * pp],     aq2[mt], bb[pp][0], bb[pp][2]);
                    mma_s8(accX[mt][2 * pp + 1], aq2[mt], bb[pp][1], bb[pp][3]);
                }
#pragma unroll
            for (int pp = 0; pp < 2; ++pp) {
                int row = b_row + pp * 16;
                int c2 = 4 + ks * 2 + lc;
                ldsm_x4(bb[pp], smB + row * 128 + ((c2 ^ (row & 7)) << 4));
            }
#pragma unroll
            for (int mt = 0; mt < 2; ++mt)
#pragma unroll
                for (int pp = 0; pp < 2; ++pp) {
                    mma_s8(accX[mt][2 * pp],     aq1[mt], bb[pp][0], bb[pp][2]);
                    mma_s8(accX[mt][2 * pp + 1], aq1[mt], bb[pp][1], bb[pp][3]);
                }
        }
        if (++st >= 3) st = 0;
    }

    const int tr = lid >> 2;
    const int tc = (lid & 3) * 2;
    const float ix = 1.0f / 252.0f;
#pragma unroll
    for (int mt = 0; mt < 2; ++mt) {
#pragma unroll
        for (int half = 0; half < 2; ++half) {
            const int m = bm + wm * 32 + mt * 16 + tr + half * 8;
            const size_t rowoff = (size_t)m * N;
            const float sa = sA[m];
#pragma unroll
            for (int nt = 0; nt < 4; ++nt) {
                const int n = bn + wn * 32 + nt * 8 + tc;
                float v0 = (__int2float_rn(acc1[mt][nt][half * 2 + 0]) +
                            __int2float_rn(accX[mt][nt][half * 2 + 0]) * ix) *
                           sa * sB[n];
                float v1 = (__int2float_rn(acc1[mt][nt][half * 2 + 1]) +
                            __int2float_rn(accX[mt][nt][half * 2 + 1]) * ix) *
                           sa * sB[n + 1];
                const size_t idx = rowoff + n;
                if (EPI == 2) {
                    float f0 = e0[idx], f1 = e0[idx + 1];
                    v0 = gelu_f(fmaf(e1[n], f0, v0)) + f0;
                    v1 = gelu_f(fmaf(e1[n + 1], f1, v1)) + f1;
                } else if (EPI == 3) {
                    v0 += e0[idx];
                    v1 += e0[idx + 1];
                }
                if (OBF) {
                    ((bf162*)Cout)[idx >> 1] = __floats2bfloat162_rn(v0, v1);
                } else {
                    *reinterpret_cast<float2*>((float*)Cout + idx) =
                        make_float2(v0, v1);
                }
            }
        }
    }
}

// ---------------- fp32 SGEMM (encoder only, K=64) ----------------------------
#define TBM 128
#define TBN 128
#define TBK 8
__global__ void __launch_bounds__(256)
sgemm_enc(const float* __restrict__ A, const float* __restrict__ B,
          float* __restrict__ C, int M, int N, int K,
          const float* __restrict__ bias) {
    __shared__ float As[TBK][TBM + 4];
    __shared__ float Bs[TBK][TBN + 4];
    const int tid = threadIdx.x;
    const int bm = blockIdx.y * TBM;
    const int bn = blockIdx.x * TBN;
    const int arow = tid >> 1, akc = (tid & 1) * 4;
    const float* Aptr = A + (size_t)(bm + arow) * K + akc;
    const int br0 = tid >> 5, bc0 = (tid & 31) * 4;
    const float* Bptr = B + (size_t)br0 * N + bn + bc0;

    float acc[8][8];
#pragma unroll
    for (int i = 0; i < 8; i++)
#pragma unroll
        for (int j = 0; j < 8; j++) acc[i][j] = 0.0f;

    float4 aR = *reinterpret_cast<const float4*>(Aptr);
    float4 bR = *reinterpret_cast<const float4*>(Bptr);
    const int tm = tid >> 4, tn = tid & 15;

    for (int k0 = 0;;) {
        As[akc + 0][arow] = aR.x; As[akc + 1][arow] = aR.y;
        As[akc + 2][arow] = aR.z; As[akc + 3][arow] = aR.w;
        Bs[br0][bc0 + 0] = bR.x;  Bs[br0][bc0 + 1] = bR.y;
        Bs[br0][bc0 + 2] = bR.z;  Bs[br0][bc0 + 3] = bR.w;
        __syncthreads();
        k0 += TBK;
        bool more = (k0 < K);
        if (more) {
            aR = *reinterpret_cast<const float4*>(Aptr + k0);
            bR = *reinterpret_cast<const float4*>(Bptr + (size_t)k0 * N);
        }
#pragma unroll
        for (int kk = 0; kk < TBK; kk++) {
            float4 a0 = *reinterpret_cast<const float4*>(&As[kk][tm * 4]);
            float4 a1 = *reinterpret_cast<const float4*>(&As[kk][64 + tm * 4]);
            float4 b0 = *reinterpret_cast<const float4*>(&Bs[kk][tn * 4]);
            float4 b1 = *reinterpret_cast<const float4*>(&Bs[kk][64 + tn * 4]);
            float av[8] = {a0.x, a0.y, a0.z, a0.w, a1.x, a1.y, a1.z, a1.w};
            float bv[8] = {b0.x, b0.y, b0.z, b0.w, b1.x, b1.y, b1.z, b1.w};
#pragma unroll
            for (int i = 0; i < 8; i++)
#pragma unroll
                for (int j = 0; j < 8; j++)
                    acc[i][j] = fmaf(av[i], bv[j], acc[i][j]);
        }
        __syncthreads();
        if (!more) break;
    }
#pragma unroll
    for (int i = 0; i < 8; i++) {
        int r = bm + ((i < 4) ? (tm * 4 + i) : (64 + tm * 4 + i - 4));
        size_t rowoff = (size_t)r * N;
#pragma unroll
        for (int j = 0; j < 8; j++) {
            int c = bn + ((j < 4) ? (tn * 4 + j) : (64 + tn * 4 + j - 4));
            C[rowoff + c] = acc[i][j] + bias[c];
        }
    }
}

// ---------------- per-layer weight prep --------------------------------------
// W2 rows (2p = re, 2p+1 = im). Block per p; also computes lamb/coef/chs inline.
__global__ void __launch_bounds__(256)
prep_W2q_k(const float* __restrict__ b_re, const float* __restrict__ b_im,
           const float* __restrict__ lam_re, const float* __restrict__ lam_im,
           const float* __restrict__ log_step) {
    __shared__ float redA[8], redB[8];
    const int p = blockIdx.x;
    const int tid = threadIdx.x;
    float dt = expf(log_step[p]);
    float lr = lam_re[p], li = lam_im[p];
    float er = expf(lr * dt);
    float lbx = er * cosf(li * dt), lby = er * sinf(li * dt);
    float nr = lbx - 1.0f, ni = lby;
    float den = lr * lr + li * li;
    float2 c2 = make_float2((nr * lr + ni * li) / den, (ni * lr - nr * li) / den);
    if (tid == 0) {
        g_lamb[p] = make_float2(lbx, lby);
        float mag2 = lbx * lbx + lby * lby;
        float s = rsqrtf(fmaxf(1.0f - mag2, 1e-6f));
        s = fminf(fmaxf(s, 1.0f), 1000.0f);
        g_chs[p] = s;
        g_chsi[p] = 1.0f / s;
    }
    float vre[4], vim[4];
    float amr = 0.0f, ami = 0.0f;
#pragma unroll
    for (int k = 0; k < 4; ++k) {
        int h = tid + k * 256;
        float br = b_re[(size_t)p * DM + h];
        float bi = b_im[(size_t)p * DM + h];
        vre[k] = c2.x * br - c2.y * bi;
        vim[k] = c2.x * bi + c2.y * br;
        amr = fmaxf(amr, fabsf(vre[k]));
        ami = fmaxf(ami, fabsf(vim[k]));
    }
#pragma unroll
    for (int o = 16; o > 0; o >>= 1) {
        amr = fmaxf(amr, __shfl_xor_sync(0xffffffffu, amr, o));
        ami = fmaxf(ami, __shfl_xor_sync(0xffffffffu, ami, o));
    }
    if ((tid & 31) == 0) { redA[tid >> 5] = amr; redB[tid >> 5] = ami; }
    __syncthreads();
    amr = redA[0]; ami = redB[0];
#pragma unroll
    for (int i = 1; i < 8; ++i) { amr = fmaxf(amr, redA[i]); ami = fmaxf(ami, redB[i]); }
    float qr = amr > 0 ? 127.0f / amr : 0.0f;
    float qi = ami > 0 ? 127.0f / ami : 0.0f;
#pragma unroll
    for (int k = 0; k < 4; ++k) {
        int h = tid + k * 256;
        int a1, a2;
        quant2i(vre[k], qr, a1, a2);
        g_W2q1[(size_t)(2 * p) * DM + h] = (int8_t)a1;
        g_W2q2[(size_t)(2 * p) * DM + h] = (int8_t)a2;
        quant2i(vim[k], qi, a1, a2);
        g_W2q1[(size_t)(2 * p + 1) * DM + h] = (int8_t)a1;
        g_W2q2[(size_t)(2 * p + 1) * DM + h] = (int8_t)a2;
    }
    if (tid == 0) {
        g_sW2[2 * p]     = amr * (1.0f / 127.0f);
        g_sW2[2 * p + 1] = ami * (1.0f / 127.0f);
    }
}

// Cw rows (h): interleaved re/-im * channel scale. Block per h, 256 threads.
__global__ void __launch_bounds__(256)
prep_Cwq_k(const float* __restrict__ c_re, const float* __restrict__ c_im) {
    __shared__ float red[8];
    const int h = blockIdx.x;
    const int tid = threadIdx.x;
    float v[8];
    float am = 0.0f;
#pragma unroll
    for (int k = 0; k < 4; ++k) {
        int p = tid + k * 256;
        float re = c_re[(size_t)h * DM + p] * g_chs[p];
        float im = -c_im[(size_t)h * DM + p] * g_chs[p];
        v[2 * k] = re;
        v[2 * k + 1] = im;
        am = fmaxf(am, fmaxf(fabsf(re), fabsf(im)));
    }
#pragma unroll
    for (int o = 16; o > 0; o >>= 1) am = fmaxf(am, __shfl_xor_sync(0xffffffffu, am, o));
    if ((tid & 31) == 0) red[tid >> 5] = am;
    __syncthreads();
    am = red[0];
#pragma unroll
    for (int i = 1; i < 8; ++i) am = fmaxf(am, red[i]);
    float qs = am > 0 ? 127.0f / am : 0.0f;
#pragma unroll
    for (int k = 0; k < 4; ++k) {
        int p = tid + k * 256;
        int a1, a2, b1, b2;
        quant2i(v[2 * k], qs, a1, a2);
        quant2i(v[2 * k + 1], qs, b1, b2);
        uint16_t w1 = (uint16_t)((uint8_t)a1 | ((uint16_t)(uint8_t)b1 << 8));
        uint16_t w2 = (uint16_t)((uint8_t)a2 | ((uint16_t)(uint8_t)b2 << 8));
        *(uint16_t*)(g_Cwq1 + (size_t)h * DM2 + 2 * p) = w1;
        *(uint16_t*)(g_Cwq2 + (size_t)h * DM2 + 2 * p) = w2;
    }
    if (tid == 0) g_sCw[h] = am * (1.0f / 127.0f);
}

// fp32 transpose: in [R][C2] -> out [C2][R]
__global__ void wtrans_k(const float* __restrict__ in, float* __restrict__ outT,
                         int R, int C2) {
    __shared__ float t[32][33];
    int r = blockIdx.y * 32 + threadIdx.y;
    int c = blockIdx.x * 32 + threadIdx.x;
    t[threadIdx.y][threadIdx.x] = in[(size_t)r * C2 + c];
    __syncthreads();
    int orow = blockIdx.x * 32 + threadIdx.y;
    int ocol = blockIdx.y * 32 + threadIdx.x;
    outT[(size_t)orow * R + ocol] = t[threadIdx.x][threadIdx.y];
}

// weight row quantizer (fp32 in, 1024/row, 256 thr x 4 contiguous)
__global__ void __launch_bounds__(256)
rowq_w_k(const float* __restrict__ in, int8_t* __restrict__ q1,
         int8_t* __restrict__ q2, float* __restrict__ sOut) {
    __shared__ float red[8];
    const size_t base = (size_t)blockIdx.x * DM;
    const int tid = threadIdx.x;
    const int c0 = tid * 4;
    float4 vv = *reinterpret_cast<const float4*>(in + base + c0);
    float v[4] = {vv.x, vv.y, vv.z, vv.w};
    float am = 0.0f;
#pragma unroll
    for (int k = 0; k < 4; ++k) am = fmaxf(am, fabsf(v[k]));
#pragma unroll
    for (int o = 16; o > 0; o >>= 1) am = fmaxf(am, __shfl_xor_sync(0xffffffffu, am, o));
    if ((tid & 31) == 0) red[tid >> 5] = am;
    __syncthreads();
    am = red[0];
#pragma unroll
    for (int i = 1; i < 8; ++i) am = fmaxf(am, red[i]);
    float qs = am > 0 ? 127.0f / am : 0.0f;
    int a1[4], a2[4];
#pragma unroll
    for (int k = 0; k < 4; ++k) quant2i(v[k], qs, a1[k], a2[k]);
    *(uint32_t*)(q1 + base + c0) = pack4(a1[0], a1[1], a1[2], a1[3]);
    *(uint32_t*)(q2 + base + c0) = pack4(a2[0], a2[1], a2[2], a2[3]);
    if (tid == 0) sOut[blockIdx.x] = am * (1.0f / 127.0f);
}

// xs row quantizer: bf16 in, 2048/row, channel-flattening. 256 thr x 8 contig.
__global__ void __launch_bounds__(256)
rowq_xs_k(const bf16* __restrict__ in, int8_t* __restrict__ q1,
          int8_t* __restrict__ q2, float* __restrict__ sOut) {
    __shared__ float red[8];
    const size_t base = (size_t)blockIdx.x * DM2;
    const int tid = threadIdx.x;
    const int c0 = tid * 8;
    const bf162* pin = reinterpret_cast<const bf162*>(in + base + c0);
    float v[8];
    float am = 0.0f;
#pragma unroll
    for (int k = 0; k < 4; ++k) {
        float2 f = __bfloat1622float2(pin[k]);
        float sc = g_chsi[(c0 >> 1) + k];
        v[2 * k] = f.x * sc;
        v[2 * k + 1] = f.y * sc;
        am = fmaxf(am, fmaxf(fabsf(v[2 * k]), fabsf(v[2 * k + 1])));
    }
#pragma unroll
    for (int o = 16; o > 0; o >>= 1) am = fmaxf(am, __shfl_xor_sync(0xffffffffu, am, o));
    if ((tid & 31) == 0) red[tid >> 5] = am;
    __syncthreads();
    am = red[0];
#pragma unroll
    for (int i = 1; i < 8; ++i) am = fmaxf(am, red[i]);
    float qs = am > 0 ? 127.0f / am : 0.0f;
    uint2 w1, w2;
    quant8(v, qs, w1, w2);
    *(uint2*)(q1 + base + c0) = w1;
    *(uint2*)(q2 + base + c0) = w2;
    if (tid == 0) sOut[blockIdx.x] = am * (1.0f / 127.0f);
}

// ---------------- scan: fp32 recurrence over bf16 data, in-place -------------
__global__ void scan_k(bf162* __restrict__ bu) {
    int idx = blockIdx.x * blockDim.x + threadIdx.x;
    if (idx >= BATCH * DM) return;
    int b = idx >> 10, p = idx & (DM - 1);
    float2 a = g_lamb[p];
    bf162* ptr = bu + (size_t)b * SEQ * DM + p;
    float xr = 0.0f, xi = 0.0f;
    const int U = 8;
    bf162 cur[U], nxt[U];
#pragma unroll
    for (int i = 0; i < U; i++) cur[i] = ptr[(size_t)i * DM];
#pragma unroll
    for (int i = 0; i < U; i++) nxt[i] = __floats2bfloat162_rn(0.f, 0.f);
    for (int l0 = 0; l0 < SEQ; l0 += U) {
        if (l0 + U < SEQ) {
#pragma unroll
            for (int i = 0; i < U; i++) nxt[i] = ptr[(size_t)(l0 + U + i) * DM];
        }
#pragma unroll
        for (int i = 0; i < U; i++) {
            float2 u = __bfloat1622float2(cur[i]);
            float nr = fmaf(a.x, xr, fmaf(-a.y, xi, u.x));
            float ni = fmaf(a.x, xi, fmaf(a.y, xr, u.y));
            xr = nr; xi = ni;
            ptr[(size_t)(l0 + i) * DM] = __floats2bfloat162_rn(xr, xi);
        }
#pragma unroll
        for (int i = 0; i < U; i++) cur[i] = nxt[i];
    }
}

// ---------------- LayerNorm (+optional residual add, +optional int8 quant) ---
__global__ void __launch_bounds__(128)
ln_k(const float* __restrict__ in, const float* __restrict__ add,
     float* __restrict__ out, int8_t* __restrict__ q1, int8_t* __restrict__ q2,
     float* __restrict__ sOut,
     const float* __restrict__ g, const float* __restrict__ bb) {
    __shared__ float red[8];
    __shared__ float redm[4];
    size_t base = (size_t)blockIdx.x * DM;
    int t = threadIdx.x;
    int c0 = t * 8;
    float v[8];
    float4 i0 = *reinterpret_cast<const float4*>(in + base + c0);
    float4 i1 = *reinterpret_cast<const float4*>(in + base + c0 + 4);
    v[0] = i0.x; v[1] = i0.y; v[2] = i0.z; v[3] = i0.w;
    v[4] = i1.x; v[5] = i1.y; v[6] = i1.z; v[7] = i1.w;
    if (add) {
        float4 a0 = *reinterpret_cast<const float4*>(add + base + c0);
        float4 a1 = *reinterpret_cast<const float4*>(add + base + c0 + 4);
        v[0] += a0.x; v[1] += a0.y; v[2] += a0.z; v[3] += a0.w;
        v[4] += a1.x; v[5] += a1.y; v[6] += a1.z; v[7] += a1.w;
    }
    float s = 0.0f;
#pragma unroll
    for (int i = 0; i < 8; i++) s += v[i];
#pragma unroll
    for (int o = 16; o > 0; o >>= 1) s += __shfl_xor_sync(0xffffffffu, s, o);
    if ((t & 31) == 0) red[t >> 5] = s;
    __syncthreads();
    float mean = (red[0] + red[1] + red[2] + red[3]) * (1.0f / DM);
    float s2 = 0.0f;
#pragma unroll
    for (int i = 0; i < 8; i++) { float d = v[i] - mean; s2 += d * d; }
#pragma unroll
    for (int o = 16; o > 0; o >>= 1) s2 += __shfl_xor_sync(0xffffffffu, s2, o);
    if ((t & 31) == 0) red[4 + (t >> 5)] = s2;
    __syncthreads();
    float var = (red[4] + red[5] + red[6] + red[7]) * (1.0f / DM);
    float inv = rsqrtf(var + 1e-5f);
    float4 g0 = *reinterpret_cast<const float4*>(g + c0);
    float4 g1 = *reinterpret_cast<const float4*>(g + c0 + 4);
    float4 b0 = *reinterpret_cast<const float4*>(bb + c0);
    float4 b1 = *reinterpret_cast<const float4*>(bb + c0 + 4);
    float gg[8] = {g0.x, g0.y, g0.z, g0.w, g1.x, g1.y, g1.z, g1.w};
    float bbv[8] = {b0.x, b0.y, b0.z, b0.w, b1.x, b1.y, b1.z, b1.w};
    float y[8];
    float am = 0.0f;
#pragma unroll
    for (int i = 0; i < 8; i++) {
        y[i] = (v[i] - mean) * inv * gg[i] + bbv[i];
        am = fmaxf(am, fabsf(y[i]));
    }
    *reinterpret_cast<float4*>(out + base + c0) =
        make_float4(y[0], y[1], y[2], y[3]);
    *reinterpret_cast<float4*>(out + base + c0 + 4) =
        make_float4(y[4], y[5], y[6], y[7]);
    if (q1) {
#pragma unroll
        for (int o = 16; o > 0; o >>= 1) am = fmaxf(am, __shfl_xor_sync(0xffffffffu, am, o));
        if ((t & 31) == 0) redm[t >> 5] = am;
        __syncthreads();
        am = fmaxf(fmaxf(redm[0], redm[1]), fmaxf(redm[2], redm[3]));
        float qs = am > 0 ? 127.0f / am : 0.0f;
        uint2 w1, w2;
        quant8(y, qs, w1, w2);
        *(uint2*)(q1 + base + c0) = w1;
        *(uint2*)(q2 + base + c0) = w2;
        if (t == 0) sOut[blockIdx.x] = am * (1.0f / 127.0f);
    }
}

// ---------------- fused double-LN at layer boundary ---------------------------
// h = LN(z + hprev; g1,b1);  fx = LN(h; g2,b2)  (+ int8 quant of fx)
__global__ void __launch_bounds__(128)
ln2_k(const float* __restrict__ z, const float* __restrict__ hprev,
      float* __restrict__ hout, float* __restrict__ fxout,
      int8_t* __restrict__ q1, int8_t* __restrict__ q2,
      float* __restrict__ sOut,
      const float* __restrict__ g1v, const float* __restrict__ b1v,
      const float* __restrict__ g2v, const float* __restrict__ b2v) {
    __shared__ float red[8];
    __shared__ float redm[4];
    size_t base = (size_t)blockIdx.x * DM;
    int t = threadIdx.x;
    int c0 = t * 8;
    float v[8];
    {
        float4 i0 = *reinterpret_cast<const float4*>(z + base + c0);
        float4 i1 = *reinterpret_cast<const float4*>(z + base + c0 + 4);
        float4 a0 = *reinterpret_cast<const float4*>(hprev + base + c0);
        float4 a1 = *reinterpret_cast<const float4*>(hprev + base + c0 + 4);
        v[0] = i0.x + a0.x; v[1] = i0.y + a0.y; v[2] = i0.z + a0.z; v[3] = i0.w + a0.w;
        v[4] = i1.x + a1.x; v[5] = i1.y + a1.y; v[6] = i1.z + a1.z; v[7] = i1.w + a1.w;
    }
    // --- LN 1 ---
    float s = 0.0f;
#pragma unroll
    for (int i = 0; i < 8; i++) s += v[i];
#pragma unroll
    for (int o = 16; o > 0; o >>= 1) s += __shfl_xor_sync(0xffffffffu, s, o);
    if ((t & 31) == 0) red[t >> 5] = s;
    __syncthreads();
    float mean = (red[0] + red[1] + red[2] + red[3]) * (1.0f / DM);
    float s2 = 0.0f;
#pragma unroll
    for (int i = 0; i < 8; i++) { float d = v[i] - mean; s2 += d * d; }
#pragma unroll
    for (int o = 16; o > 0; o >>= 1) s2 += __shfl_xor_sync(0xffffffffu, s2, o);
    if ((t & 31) == 0) red[4 + (t >> 5)] = s2;
    __syncthreads();
    float var = (red[4] + red[5] + red[6] + red[7]) * (1.0f / DM);
    float inv = rsqrtf(var + 1e-5f);
    float y1[8];
    {
        float4 g0 = *reinterpret_cast<const float4*>(g1v + c0);
        float4 g1 = *reinterpret_cast<const float4*>(g1v + c0 + 4);
        float4 b0 = *reinterpret_cast<const float4*>(b1v + c0);
        float4 b1 = *reinterpret_cast<const float4*>(b1v + c0 + 4);
        float gg[8] = {g0.x, g0.y, g0.z, g0.w, g1.x, g1.y, g1.z, g1.w};
        float bb[8] = {b0.x, b0.y, b0.z, b0.w, b1.x, b1.y, b1.z, b1.w};
#pragma unroll
        for (int i = 0; i < 8; i++)
            y1[i] = (v[i] - mean) * inv * gg[i] + bb[i];
    }
    *reinterpret_cast<float4*>(hout + base + c0) =
        make_float4(y1[0], y1[1], y1[2], y1[3]);
    *reinterpret_cast<float4*>(hout + base + c0 + 4) =
        make_float4(y1[4], y1[5], y1[6], y1[7]);
    __syncthreads();   // allow red[] reuse for LN 2
    // --- LN 2 ---
    s = 0.0f;
#pragma unroll
    for (int i = 0; i < 8; i++) s += y1[i];
#pragma unroll
    for (int o = 16; o > 0; o >>= 1) s += __shfl_xor_sync(0xffffffffu, s, o);
    if ((t & 31) == 0) red[t >> 5] = s;
    __syncthreads();
    mean = (red[0] + red[1] + red[2] + red[3]) * (1.0f / DM);
    s2 = 0.0f;
#pragma unroll
    for (int i = 0; i < 8; i++) { float d = y1[i] - mean; s2 += d * d; }
#pragma unroll
    for (int o = 16; o > 0; o >>= 1) s2 += __shfl_xor_sync(0xffffffffu, s2, o);
    if ((t & 31) == 0) red[4 + (t >> 5)] = s2;
    __syncthreads();
    var = (red[4] + red[5] + red[6] + red[7]) * (1.0f / DM);
    inv = rsqrtf(var + 1e-5f);
    float y2[8];
    float am = 0.0f;
    {
        float4 g0 = *reinterpret_cast<const float4*>(g2v + c0);
        float4 g1 = *reinterpret_cast<const float4*>(g2v + c0 + 4);
        float4 b0 = *reinterpret_cast<const float4*>(b2v + c0);
        float4 b1 = *reinterpret_cast<const float4*>(b2v + c0 + 4);
        float gg[8] = {g0.x, g0.y, g0.z, g0.w, g1.x, g1.y, g1.z, g1.w};
        float bb[8] = {b0.x, b0.y, b0.z, b0.w, b1.x, b1.y, b1.z, b1.w};
#pragma unroll
        for (int i = 0; i < 8; i++) {
            y2[i] = (y1[i] - mean) * inv * gg[i] + bb[i];
            am = fmaxf(am, fabsf(y2[i]));
        }
    }
    *reinterpret_cast<float4*>(fxout + base + c0) =
        make_float4(y2[0], y2[1], y2[2], y2[3]);
    *reinterpret_cast<float4*>(fxout + base + c0 + 4) =
        make_float4(y2[4], y2[5], y2[6], y2[7]);
#pragma unroll
    for (int o = 16; o > 0; o >>= 1) am = fmaxf(am, __shfl_xor_sync(0xffffffffu, am, o));
    if ((t & 31) == 0) redm[t >> 5] = am;
    __syncthreads();
    am = fmaxf(fmaxf(redm[0], redm[1]), fmaxf(redm[2], redm[3]));
    float qs = am > 0 ? 127.0f / am : 0.0f;
    uint2 w1, w2;
    quant8(y2, qs, w1, w2);
    *(uint2*)(q1 + base + c0) = w1;
    *(uint2*)(q2 + base + c0) = w2;
    if (t == 0) sOut[blockIdx.x] = am * (1.0f / 127.0f);
}

// ---------------- GEGLU row-quant (bf16 in) -----------------------------------
__global__ void __launch_bounds__(128)
geglu_rowq_k(const bf16* __restrict__ u2, int8_t* __restrict__ q1,
             int8_t* __restrict__ q2, float* __restrict__ sOut) {
    __shared__ float redm[4];
    const size_t m = blockIdx.x;
    const size_t base2 = m * DM2;
    const size_t base = m * DM;
    const int t = threadIdx.x;
    const int c0 = t * 8;
    const bf162* pa = reinterpret_cast<const bf162*>(u2 + base2 + c0);
    const bf162* pg = reinterpret_cast<const bf162*>(u2 + base2 + DM + c0);
    float v[8];
    float am = 0.0f;
#pragma unroll
    for (int k = 0; k < 4; ++k) {
        float2 fa = __bfloat1622float2(pa[k]);
        float2 fg = __bfloat1622float2(pg[k]);
        v[2 * k]     = fa.x * gelu_f(fg.x);
        v[2 * k + 1] = fa.y * gelu_f(fg.y);
        am = fmaxf(am, fmaxf(fabsf(v[2 * k]), fabsf(v[2 * k + 1])));
    }
#pragma unroll
    for (int o = 16; o > 0; o >>= 1) am = fmaxf(am, __shfl_xor_sync(0xffffffffu, am, o));
    if ((t & 31) == 0) redm[t >> 5] = am;
    __syncthreads();
    am = fmaxf(fmaxf(redm[0], redm[1]), fmaxf(redm[2], redm[3]));
    float qs = am > 0 ? 127.0f / am : 0.0f;
    uint2 w1, w2;
    quant8(v, qs, w1, w2);
    *(uint2*)(q1 + base + c0) = w1;
    *(uint2*)(q2 + base + c0) = w2;
    if (t == 0) sOut[blockIdx.x] = am * (1.0f / 127.0f);
}

// ---------------- mean pool + decode -----------------------------------------
__global__ void pool_k(const float* __restrict__ h, float* __restrict__ pooled) {
    int idx = blockIdx.x * blockDim.x + threadIdx.x;
    if (idx >= BATCH * DM) return;
    int b = idx >> 10, d = idx & (DM - 1);
    const float* p = h + (size_t)b * SEQ * DM + d;
    float s = 0.0f;
#pragma unroll 8
    for (int l = 0; l < SEQ; l++) s += p[(size_t)l * DM];
    pooled[idx] = s * (1.0f / SEQ);
}

__global__ void dec_k(const float* __restrict__ pooled,
                      const float* __restrict__ w,
                      const float* __restrict__ b,
                      float* __restrict__ out) {
    __shared__ float red[8];
    int bi = blockIdx.x;
    int t = threadIdx.x;
    float s = 0.0f;
    for (int d = t; d < DM; d += 256) s += pooled[bi * DM + d] * w[d];
#pragma unroll
    for (int o = 16; o > 0; o >>= 1) s += __shfl_xor_sync(0xffffffffu, s, o);
    if ((t & 31) == 0) red[t >> 5] = s;
    __syncthreads();
    if (t == 0) {
        float tot = 0.0f;
#pragma unroll
        for (int i = 0; i < 8; i++) tot += red[i];
        out[bi] = tot + b[0];
    }
}

// ---------------- driver ----------------
extern "C" void kernel_launch(void* const* d_in, const int* in_sizes, int n_in,
                              void* d_out, int out_size) {
    const float* x        = (const float*)d_in[0];
    const float* enc_w    = (const float*)d_in[1];
    const float* enc_b    = (const float*)d_in[2];
    const float* ln1_g    = (const float*)d_in[3];
    const float* ln1_b    = (const float*)d_in[4];
    const float* lam_re   = (const float*)d_in[5];
    const float* lam_im   = (const float*)d_in[6];
    const float* b_re     = (const float*)d_in[7];
    const float* b_im     = (const float*)d_in[8];
    const float* c_re     = (const float*)d_in[9];
    const float* c_im     = (const float*)d_in[10];
    const float* d_skip   = (const float*)d_in[11];
    const float* log_step = (const float*)d_in[12];
    const float* ffn_g    = (const float*)d_in[13];
    const float* ffn_b    = (const float*)d_in[14];
    const float* ff_enc_w = (const float*)d_in[15];
    const float* ff_dec_w = (const float*)d_in[16];
    const float* norm_g   = (const float*)d_in[17];
    const float* norm_b   = (const float*)d_in[18];
    const float* dec_w    = (const float*)d_in[19];
    const float* dec_b    = (const float*)d_in[20];
    float* out = (float*)d_out;

    static int attr_done = 0;
    if (!attr_done) {
        cudaFuncSetAttribute((const void*)imma_gemm<0, true>,
                             cudaFuncAttributeMaxDynamicSharedMemorySize, SMEM_GEMM);
        cudaFuncSetAttribute((const void*)imma_gemm<2, false>,
                             cudaFuncAttributeMaxDynamicSharedMemorySize, SMEM_GEMM);
        cudaFuncSetAttribute((const void*)imma_gemm<3, false>,
                             cudaFuncAttributeMaxDynamicSharedMemorySize, SMEM_GEMM);
        attr_done = 1;
    }

    float *p_h, *p_fx, *p_fy, *p_z, *p_wtmp, *p_pooled;
    bf16 *p_big;
    int8_t *p_fxq1, *p_fxq2, *p_xsq1, *p_xsq2, *p_fyq1, *p_fyq2, *p_ggq1, *p_ggq2;
    int8_t *p_W2q1, *p_W2q2, *p_Cwq1, *p_Cwq2, *p_feq1, *p_feq2, *p_fdq1, *p_fdq2;
    float *p_sfx, *p_sxs, *p_sfy, *p_sgg, *p_sW2, *p_sCw, *p_sfe, *p_sfd;
    cudaGetSymbolAddress((void**)&p_h, g_h);
    cudaGetSymbolAddress((void**)&p_fx, g_fx);
    cudaGetSymbolAddress((void**)&p_fy, g_fy);
    cudaGetSymbolAddress((void**)&p_z, g_z);
    cudaGetSymbolAddress((void**)&p_big, g_big);
    cudaGetSymbolAddress((void**)&p_wtmp, g_wtmp);
    cudaGetSymbolAddress((void**)&p_pooled, g_pooled);
    cudaGetSymbolAddress((void**)&p_fxq1, g_fxq1);
    cudaGetSymbolAddress((void**)&p_fxq2, g_fxq2);
    cudaGetSymbolAddress((void**)&p_xsq1, g_xsq1);
    cudaGetSymbolAddress((void**)&p_xsq2, g_xsq2);
    cudaGetSymbolAddress((void**)&p_fyq1, g_fyq1);
    cudaGetSymbolAddress((void**)&p_fyq2, g_fyq2);
    cudaGetSymbolAddress((void**)&p_ggq1, g_ggq1);
    cudaGetSymbolAddress((void**)&p_ggq2, g_ggq2);
    cudaGetSymbolAddress((void**)&p_W2q1, g_W2q1);
    cudaGetSymbolAddress((void**)&p_W2q2, g_W2q2);
    cudaGetSymbolAddress((void**)&p_Cwq1, g_Cwq1);
    cudaGetSymbolAddress((void**)&p_Cwq2, g_Cwq2);
    cudaGetSymbolAddress((void**)&p_feq1, g_feq1);
    cudaGetSymbolAddress((void**)&p_feq2, g_feq2);
    cudaGetSymbolAddress((void**)&p_fdq1, g_fdq1);
    cudaGetSymbolAddress((void**)&p_fdq2, g_fdq2);
    cudaGetSymbolAddress((void**)&p_sfx, g_sfx);
    cudaGetSymbolAddress((void**)&p_sxs, g_sxs);
    cudaGetSymbolAddress((void**)&p_sfy, g_sfy);
    cudaGetSymbolAddress((void**)&p_sgg, g_sgg);
    cudaGetSymbolAddress((void**)&p_sW2, g_sW2);
    cudaGetSymbolAddress((void**)&p_sCw, g_sCw);
    cudaGetSymbolAddress((void**)&p_sfe, g_sfe);
    cudaGetSymbolAddress((void**)&p_sfd, g_sfd);

    const int M = MROWS;

    // #1: encoder h = x @ enc_w + enc_b  (fp32, K=64)
    sgemm_enc<<<dim3(DM / TBN, M / TBM), 256>>>(x, enc_w, p_h, M, DM, D_IN, enc_b);
    // #2: layer-0 W2 quant + inline lamb/chs
    prep_W2q_k<<<DM, 256>>>(b_re, b_im, lam_re, lam_im, log_step);
    // #3: layer-0 fx = LN(h) + quant
    ln_k<<<M, 128>>>(p_h, nullptr, p_fx, p_fxq1, p_fxq2, p_sfx, ln1_g, ln1_b);

    for (int i = 0; i < NL; i++) {
        const size_t w1 = (size_t)i * DM;
        const size_t w2 = (size_t)i * DM * DM;
        const size_t w3 = (size_t)i * DM * DM2;

        // #4 (i=0): Bu = fx @ W2^T  [M, 2P] bf16 out  <-- ncu-captured launch
        imma_gemm<0, true><<<dim3(DM2 / 64, M / 64), 128, SMEM_GEMM>>>(
            p_fxq1, p_fxq2, p_W2q1, p_W2q2, p_big, DM2, DM,
            p_sfx, p_sW2, nullptr, nullptr);
        // Cw quant (needs g_chs from this layer's prep_W2q)
        prep_Cwq_k<<<DM, 256>>>(c_re + w2, c_im + w2);
        // sequential complex scan, in place (uses g_lamb of layer i)
        scan_k<<<(BATCH * DM) / 128, 128>>>((bf162*)p_big);
        // quantize xs rows (channel-flattened, uses g_chsi of layer i)
        rowq_xs_k<<<M, 256>>>(p_big, p_xsq1, p_xsq2, p_sxs);
        // z = gelu(xs @ Cw^T + d*fx) + fx
        imma_gemm<2, false><<<dim3(DM / 64, M / 64), 128, SMEM_GEMM>>>(
            p_xsq1, p_xsq2, p_Cwq1, p_Cwq2, p_z, DM, DM2,
            p_sxs, p_sCw, p_fx, d_skip + w1);
        // ff_enc^T quant
        wtrans_k<<<dim3(DM2 / 32, DM / 32), dim3(32, 32)>>>(ff_enc_w + w3, p_wtmp, DM, DM2);
        rowq_w_k<<<DM2, 256>>>(p_wtmp, p_feq1, p_feq2, p_sfe);
        // fy = LN(z) + quant
        ln_k<<<M, 128>>>(p_z, nullptr, p_fy, p_fyq1, p_fyq2, p_sfy,
                         ffn_g + w1, ffn_b + w1);
        // u2 = fy @ ff_enc  [M, 2D] bf16 out
        imma_gemm<0, true><<<dim3(DM2 / 64, M / 64), 128, SMEM_GEMM>>>(
            p_fyq1, p_fyq2, p_feq1, p_feq2, p_big, DM2, DM,
            p_sfy, p_sfe, nullptr, nullptr);
        // geglu + quant
        geglu_rowq_k<<<M, 128>>>(p_big, p_ggq1, p_ggq2, p_sgg);
        // ff_dec^T quant
        wtrans_k<<<dim3(DM / 32, DM / 32), dim3(32, 32)>>>(ff_dec_w + w2, p_wtmp, DM, DM);
        rowq_w_k<<<DM, 256>>>(p_wtmp, p_fdq1, p_fdq2, p_sfd);
        // z2 = gg @ ff_dec + fy   (into p_z)
        imma_gemm<3, false><<<dim3(DM / 64, M / 64), 128, SMEM_GEMM>>>(
            p_ggq1, p_ggq2, p_fdq1, p_fdq2, p_z, DM, DM,
            p_sgg, p_sfd, p_fy, nullptr);

        if (i + 1 < NL) {
            const size_t nw1 = (size_t)(i + 1) * DM;
            const size_t nw2 = (size_t)(i + 1) * DM * DM;
            // next layer's W2 quant (overwrites g_lamb/chs — all layer-i users done)
            prep_W2q_k<<<DM, 256>>>(b_re + nw2, b_im + nw2,
                                    lam_re + nw1, lam_im + nw1, log_step + nw1);
            // fused: h = LN(z2+h, norm_i);  fx = LN(h, ln1_{i+1}) + quant
            ln2_k<<<M, 128>>>(p_z, p_h, p_h, p_fx, p_fxq1, p_fxq2, p_sfx,
                              norm_g + w1, norm_b + w1, ln1_g + nw1, ln1_b + nw1);
        } else {
            // final: h = LN(z2 + h, norm)
            ln_k<<<M, 128>>>(p_z, p_h, p_h, nullptr, nullptr, nullptr,
                             norm_g + w1, norm_b + w1);
        }
    }

    pool_k<<<(BATCH * DM) / 128, 128>>>(p_h, p_pooled);
    dec_k<<<BATCH, 256>>>(p_pooled, dec_w, dec_b, out);
}

// round 13
// speedup vs baseline: 3.3930x; 1.0238x over previous
#include <cuda_runtime.h>
#include <cuda_bf16.h>
#include <math.h>
#include <stdint.h>

// ---------------- problem constants ----------------
#define BATCH   8
#define SEQ     2048
#define D_IN    64
#define DM      1024
#define DM2     2048
#define NL      4
#define MROWS   (BATCH*SEQ)   // 16384

typedef __nv_bfloat16 bf16;
typedef __nv_bfloat162 bf162;

// ---------------- scratch (device globals) ----------------
__device__ float g_h  [(size_t)MROWS * DM];
__device__ float g_fx [(size_t)MROWS * DM];
__device__ float g_fy [(size_t)MROWS * DM];
__device__ float g_z  [(size_t)MROWS * DM];
__device__ __align__(16) bf16 g_big[(size_t)MROWS * DM2];   // bu->xs; then gg [M,DM]
__device__ float g_wtmp[(size_t)DM2 * DM];                  // transposed weight staging

__device__ __align__(16) int8_t g_fxq1[(size_t)MROWS * DM];
__device__ __align__(16) int8_t g_fxq2[(size_t)MROWS * DM];
__device__ __align__(16) int8_t g_xsq1[(size_t)MROWS * DM2];
__device__ __align__(16) int8_t g_xsq2[(size_t)MROWS * DM2];
__device__ __align__(16) int8_t g_fyq1[(size_t)MROWS * DM];
__device__ __align__(16) int8_t g_fyq2[(size_t)MROWS * DM];
__device__ __align__(16) int8_t g_ggq1[(size_t)MROWS * DM];
__device__ __align__(16) int8_t g_ggq2[(size_t)MROWS * DM];

__device__ __align__(16) int8_t g_W2q1[(size_t)DM2 * DM];
__device__ __align__(16) int8_t g_W2q2[(size_t)DM2 * DM];
__device__ __align__(16) int8_t g_Cwq1[(size_t)DM * DM2];
__device__ __align__(16) int8_t g_Cwq2[(size_t)DM * DM2];
__device__ __align__(16) int8_t g_feq1[(size_t)DM2 * DM];
__device__ __align__(16) int8_t g_feq2[(size_t)DM2 * DM];
__device__ __align__(16) int8_t g_fdq1[(size_t)DM * DM];
__device__ __align__(16) int8_t g_fdq2[(size_t)DM * DM];

__device__ float g_sfx[MROWS], g_sxs[MROWS], g_sfy[MROWS], g_sgg[MROWS];
__device__ float g_sW2[DM2], g_sCw[DM], g_sfe[DM2], g_sfd[DM];

__device__ float2 g_lamb[DM];
__device__ float  g_chs [DM];
__device__ float  g_chsi[DM];
__device__ float  g_pooled[BATCH * DM];

// ---------------- helpers ----------------
__device__ __forceinline__ float gelu_f(float x) {
    return 0.5f * x * (1.0f + erff(x * 0.70710678118654752f));
}
__device__ __forceinline__ uint32_t s2u(const void* p) {
    uint32_t a;
    asm("{ .reg .u64 t; cvta.to.shared.u64 t, %1; cvt.u32.u64 %0, t; }"
        : "=r"(a) : "l"(p));
    return a;
}
__device__ __forceinline__ void cpasync16(uint32_t s, const void* g) {
    asm volatile("cp.async.cg.shared.global [%0], [%1], 16;" :: "r"(s), "l"(g));
}
__device__ __forceinline__ void ldsm_x4(uint32_t* r, uint32_t addr) {
    asm volatile("ldmatrix.sync.aligned.m8n8.x4.shared.b16 {%0,%1,%2,%3}, [%4];"
                 : "=r"(r[0]), "=r"(r[1]), "=r"(r[2]), "=r"(r[3]) : "r"(addr));
}
__device__ __forceinline__ void mma_s8(int* d, const uint32_t* a,
                                       uint32_t b0, uint32_t b1) {
    asm volatile(
        "mma.sync.aligned.m16n8k32.row.col.s32.s8.s8.s32 "
        "{%0,%1,%2,%3}, {%4,%5,%6,%7}, {%8,%9}, {%0,%1,%2,%3};"
        : "+r"(d[0]), "+r"(d[1]), "+r"(d[2]), "+r"(d[3])
        : "r"(a[0]), "r"(a[1]), "r"(a[2]), "r"(a[3]), "r"(b0), "r"(b1));
}
__device__ __forceinline__ void quant2i(float v, float qs, int& o1, int& o2) {
    float t = v * qs;
    o1 = __float2int_rn(t);
    o2 = __float2int_rn((t - (float)o1) * 252.0f);
}
__device__ __forceinline__ uint32_t pack4(int a, int b, int c, int d) {
    return (uint32_t)(uint8_t)a | ((uint32_t)(uint8_t)b << 8) |
           ((uint32_t)(uint8_t)c << 16) | ((uint32_t)(uint8_t)d << 24);
}
__device__ __forceinline__ void quant8(const float* v, float qs,
                                       uint2& w1, uint2& w2) {
    int a1[8], a2[8];
#pragma unroll
    for (int i = 0; i < 8; i++) quant2i(v[i], qs, a1[i], a2[i]);
    w1.x = pack4(a1[0], a1[1], a1[2], a1[3]);
    w1.y = pack4(a1[4], a1[5], a1[6], a1[7]);
    w2.x = pack4(a2[0], a2[1], a2[2], a2[3]);
    w2.y = pack4(a2[4], a2[5], a2[6], a2[7]);
}

// ---------------- IMMA split-int8 GEMM: C[M,N] = sA.sB.(A @ B^T) -------------
// CTA 64x64, 4 warps (2m x 2n, 32x32 each), 4 CTAs/SM, 3-stage, 1 barrier/chunk.
// Fragment prefetch: all 8 ldsm of a ks-step issued before its mma.
// EPI 0: plain  2: gelu(v + e1[n]*e0[m,n]) + e0[m,n]  3: v + e0[m,n]
// EPI 4: geglu pair-fused: out[m, n/2] = bf16( v0 * gelu(v1) )   (B rows
//        interleaved a0,g0,a1,g1,... so (n, n+1) = (a_c, g_c))
// OBF: write bf162 pairs instead of float2 (EPI 0 path).
#define STAGE_B   16384
#define NSTAGE    3
#define SMEM_GEMM (NSTAGE * STAGE_B)

template <int EPI, bool OBF>
__global__ void __launch_bounds__(128, 4)
imma_gemm(const int8_t* __restrict__ Aq1, const int8_t* __restrict__ Aq2,
          const int8_t* __restrict__ Bq1, const int8_t* __restrict__ Bq2,
          void* __restrict__ Cout, int N, int K,
          const float* __restrict__ sA, const float* __restrict__ sB,
          const float* __restrict__ e0, const float* __restrict__ e1) {
    extern __shared__ __align__(128) char smem[];
    const int tid = threadIdx.x;
    const int wid = tid >> 5;
    const int lid = tid & 31;
    const int wm = wid & 1;
    const int wn = wid >> 1;
    const int bm = blockIdx.y * 64;
    const int bn = blockIdx.x * 64;
    const uint32_t sbase = s2u(smem);
    const int nch = K >> 6;

    auto load_stage = [&](int st, int c) {
        const int kc = c << 6;
        const uint32_t stb = sbase + st * STAGE_B;
#pragma unroll
        for (int t = 0; t < 8; ++t) {
            int i = tid + t * 128;
            int isB = (i >= 512);
            int ii = i & 511;
            int row = ii >> 3, j = ii & 7;
            const int8_t* src = isB ? ((j < 4) ? Bq1 : Bq2)
                                    : ((j < 4) ? Aq1 : Aq2);
            size_t go = (size_t)((isB ? bn : bm) + row) * K + kc + (j & 3) * 16;
            uint32_t dst = stb + (isB ? 8192u : 0u) + row * 128 +
                           (uint32_t)((j ^ (row & 7)) << 4);
            cpasync16(dst, src + go);
        }
    };

    int acc1[2][4][4], accX[2][4][4];
#pragma unroll
    for (int mt = 0; mt < 2; mt++)
#pragma unroll
        for (int nt = 0; nt < 4; nt++)
#pragma unroll
            for (int q = 0; q < 4; q++) { acc1[mt][nt][q] = 0; accX[mt][nt][q] = 0; }

    load_stage(0, 0); asm volatile("cp.async.commit_group;" ::: "memory");
    load_stage(1, 1); asm volatile("cp.async.commit_group;" ::: "memory");

    const int a_row = wm * 32 + (lid & 15);
    const int b_row = wn * 32 + (lid & 15);
    const int lc = lid >> 4;

    int st = 0;
    for (int c = 0; c < nch; ++c) {
        if (c + 1 < nch) asm volatile("cp.async.wait_group 1;" ::: "memory");
        else             asm volatile("cp.async.wait_group 0;" ::: "memory");
        __syncthreads();

        int st2 = st + 2; if (st2 >= 3) st2 -= 3;
        if (c + 2 < nch) load_stage(st2, c + 2);
        asm volatile("cp.async.commit_group;" ::: "memory");

        const uint32_t smA = sbase + st * STAGE_B;
        const uint32_t smB = smA + 8192;
#pragma unroll
        for (int ks = 0; ks < 2; ++ks) {
            uint32_t aq1[2][4], aq2[2][4], bb[2][4], bb2[2][4];
            const int c1 = ks * 2 + lc;
            const int c2 = 4 + ks * 2 + lc;
            // ---- all ldsm up front (first-needed first) ----
#pragma unroll
            for (int mt = 0; mt < 2; ++mt) {
                int row = a_row + mt * 16;
                ldsm_x4(aq1[mt], smA + row * 128 + ((c1 ^ (row & 7)) << 4));
            }
#pragma unroll
            for (int pp = 0; pp < 2; ++pp) {
                int row = b_row + pp * 16;
                ldsm_x4(bb[pp], smB + row * 128 + ((c1 ^ (row & 7)) << 4));
            }
#pragma unroll
            for (int mt = 0; mt < 2; ++mt) {
                int row = a_row + mt * 16;
                ldsm_x4(aq2[mt], smA + row * 128 + ((c2 ^ (row & 7)) << 4));
            }
#pragma unroll
            for (int pp = 0; pp < 2; ++pp) {
                int row = b_row + pp * 16;
                ldsm_x4(bb2[pp], smB + row * 128 + ((c2 ^ (row & 7)) << 4));
            }
            // ---- mma: q1q1 -> acc1, q2q1 -> accX, q1q2 -> accX ----
#pragma unroll
            for (int mt = 0; mt < 2; ++mt)
#pragma unroll
                for (int pp = 0; pp < 2; ++pp) {
                    mma_s8(acc1[mt][2 * pp],     aq1[mt], bb[pp][0], bb[pp][2]);
                    mma_s8(acc1[mt][2 * pp + 1], aq1[mt], bb[pp][1], bb[pp][3]);
                }
#pragma unroll
            for (int mt = 0; mt < 2; ++mt)
#pragma unroll
                for (int pp = 0; pp < 2; ++pp) {
                    mma_s8(accX[mt][2 * pp],     aq2[mt], bb[pp][0], bb[pp][2]);
                    mma_s8(accX[mt][2 * pp + 1], aq2[mt], bb[pp][1], bb[pp][3]);
                }
#pragma unroll
            for (int mt = 0; mt < 2; ++mt)
#pragma unroll
                for (int pp = 0; pp < 2; ++pp) {
                    mma_s8(accX[mt][2 * pp],     aq1[mt], bb2[pp][0], bb2[pp][2]);
                    mma_s8(accX[mt][2 * pp + 1], aq1[mt], bb2[pp][1], bb2[pp][3]);
                }
        }
        if (++st >= 3) st = 0;
    }

    const int tr = lid >> 2;
    const int tc = (lid & 3) * 2;
    const float ix = 1.0f / 252.0f;
#pragma unroll
    for (int mt = 0; mt < 2; ++mt) {
#pragma unroll
        for (int half = 0; half < 2; ++half) {
            const int m = bm + wm * 32 + mt * 16 + tr + half * 8;
            const size_t rowoff = (size_t)m * N;
            const float sa = sA[m];
#pragma unroll
            for (int nt = 0; nt < 4; ++nt) {
                const int n = bn + wn * 32 + nt * 8 + tc;
                float v0 = (__int2float_rn(acc1[mt][nt][half * 2 + 0]) +
                            __int2float_rn(accX[mt][nt][half * 2 + 0]) * ix) *
                           sa * sB[n];
                float v1 = (__int2float_rn(acc1[mt][nt][half * 2 + 1]) +
                            __int2float_rn(accX[mt][nt][half * 2 + 1]) * ix) *
                           sa * sB[n + 1];
                if (EPI == 4) {
                    // (v0, v1) = (a_c, g_c); write a*gelu(g) at [m, n/2] bf16
                    float prod = v0 * gelu_f(v1);
                    ((bf16*)Cout)[(size_t)m * (N >> 1) + (n >> 1)] =
                        __float2bfloat16(prod);
                    continue;
                }
                const size_t idx = rowoff + n;
                if (EPI == 2) {
                    float f0 = e0[idx], f1 = e0[idx + 1];
                    v0 = gelu_f(fmaf(e1[n], f0, v0)) + f0;
                    v1 = gelu_f(fmaf(e1[n + 1], f1, v1)) + f1;
                } else if (EPI == 3) {
                    v0 += e0[idx];
                    v1 += e0[idx + 1];
                }
                if (OBF) {
                    ((bf162*)Cout)[idx >> 1] = __floats2bfloat162_rn(v0, v1);
                } else {
                    *reinterpret_cast<float2*>((float*)Cout + idx) =
                        make_float2(v0, v1);
                }
            }
        }
    }
}

// ---------------- fp32 SGEMM (encoder only, K=64) ----------------------------
#define TBM 128
#define TBN 128
#define TBK 8
__global__ void __launch_bounds__(256)
sgemm_enc(const float* __restrict__ A, const float* __restrict__ B,
          float* __restrict__ C, int M, int N, int K,
          const float* __restrict__ bias) {
    __shared__ float As[TBK][TBM + 4];
    __shared__ float Bs[TBK][TBN + 4];
    const int tid = threadIdx.x;
    const int bm = blockIdx.y * TBM;
    const int bn = blockIdx.x * TBN;
    const int arow = tid >> 1, akc = (tid & 1) * 4;
    const float* Aptr = A + (size_t)(bm + arow) * K + akc;
    const int br0 = tid >> 5, bc0 = (tid & 31) * 4;
    const float* Bptr = B + (size_t)br0 * N + bn + bc0;

    float acc[8][8];
#pragma unroll
    for (int i = 0; i < 8; i++)
#pragma unroll
        for (int j = 0; j < 8; j++) acc[i][j] = 0.0f;

    float4 aR = *reinterpret_cast<const float4*>(Aptr);
    float4 bR = *reinterpret_cast<const float4*>(Bptr);
    const int tm = tid >> 4, tn = tid & 15;

    for (int k0 = 0;;) {
        As[akc + 0][arow] = aR.x; As[akc + 1][arow] = aR.y;
        As[akc + 2][arow] = aR.z; As[akc + 3][arow] = aR.w;
        Bs[br0][bc0 + 0] = bR.x;  Bs[br0][bc0 + 1] = bR.y;
        Bs[br0][bc0 + 2] = bR.z;  Bs[br0][bc0 + 3] = bR.w;
        __syncthreads();
        k0 += TBK;
        bool more = (k0 < K);
        if (more) {
            aR = *reinterpret_cast<const float4*>(Aptr + k0);
            bR = *reinterpret_cast<const float4*>(Bptr + (size_t)k0 * N);
        }
#pragma unroll
        for (int kk = 0; kk < TBK; kk++) {
            float4 a0 = *reinterpret_cast<const float4*>(&As[kk][tm * 4]);
            float4 a1 = *reinterpret_cast<const float4*>(&As[kk][64 + tm * 4]);
            float4 b0 = *reinterpret_cast<const float4*>(&Bs[kk][tn * 4]);
            float4 b1 = *reinterpret_cast<const float4*>(&Bs[kk][64 + tn * 4]);
            float av[8] = {a0.x, a0.y, a0.z, a0.w, a1.x, a1.y, a1.z, a1.w};
            float bv[8] = {b0.x, b0.y, b0.z, b0.w, b1.x, b1.y, b1.z, b1.w};
#pragma unroll
            for (int i = 0; i < 8; i++)
#pragma unroll
                for (int j = 0; j < 8; j++)
                    acc[i][j] = fmaf(av[i], bv[j], acc[i][j]);
        }
        __syncthreads();
        if (!more) break;
    }
#pragma unroll
    for (int i = 0; i < 8; i++) {
        int r = bm + ((i < 4) ? (tm * 4 + i) : (64 + tm * 4 + i - 4));
        size_t rowoff = (size_t)r * N;
#pragma unroll
        for (int j = 0; j < 8; j++) {
            int c = bn + ((j < 4) ? (tn * 4 + j) : (64 + tn * 4 + j - 4));
            C[rowoff + c] = acc[i][j] + bias[c];
        }
    }
}

// ---------------- per-layer weight prep --------------------------------------
__global__ void __launch_bounds__(256)
prep_W2q_k(const float* __restrict__ b_re, const float* __restrict__ b_im,
           const float* __restrict__ lam_re, const float* __restrict__ lam_im,
           const float* __restrict__ log_step) {
    __shared__ float redA[8], redB[8];
    const int p = blockIdx.x;
    const int tid = threadIdx.x;
    float dt = expf(log_step[p]);
    float lr = lam_re[p], li = lam_im[p];
    float er = expf(lr * dt);
    float lbx = er * cosf(li * dt), lby = er * sinf(li * dt);
    float nr = lbx - 1.0f, ni = lby;
    float den = lr * lr + li * li;
    float2 c2 = make_float2((nr * lr + ni * li) / den, (ni * lr - nr * li) / den);
    if (tid == 0) {
        g_lamb[p] = make_float2(lbx, lby);
        float mag2 = lbx * lbx + lby * lby;
        float s = rsqrtf(fmaxf(1.0f - mag2, 1e-6f));
        s = fminf(fmaxf(s, 1.0f), 1000.0f);
        g_chs[p] = s;
        g_chsi[p] = 1.0f / s;
    }
    float vre[4], vim[4];
    float amr = 0.0f, ami = 0.0f;
#pragma unroll
    for (int k = 0; k < 4; ++k) {
        int h = tid + k * 256;
        float br = b_re[(size_t)p * DM + h];
        float bi = b_im[(size_t)p * DM + h];
        vre[k] = c2.x * br - c2.y * bi;
        vim[k] = c2.x * bi + c2.y * br;
        amr = fmaxf(amr, fabsf(vre[k]));
        ami = fmaxf(ami, fabsf(vim[k]));
    }
#pragma unroll
    for (int o = 16; o > 0; o >>= 1) {
        amr = fmaxf(amr, __shfl_xor_sync(0xffffffffu, amr, o));
        ami = fmaxf(ami, __shfl_xor_sync(0xffffffffu, ami, o));
    }
    if ((tid & 31) == 0) { redA[tid >> 5] = amr; redB[tid >> 5] = ami; }
    __syncthreads();
    amr = redA[0]; ami = redB[0];
#pragma unroll
    for (int i = 1; i < 8; ++i) { amr = fmaxf(amr, redA[i]); ami = fmaxf(ami, redB[i]); }
    float qr = amr > 0 ? 127.0f / amr : 0.0f;
    float qi = ami > 0 ? 127.0f / ami : 0.0f;
#pragma unroll
    for (int k = 0; k < 4; ++k) {
        int h = tid + k * 256;
        int a1, a2;
        quant2i(vre[k], qr, a1, a2);
        g_W2q1[(size_t)(2 * p) * DM + h] = (int8_t)a1;
        g_W2q2[(size_t)(2 * p) * DM + h] = (int8_t)a2;
        quant2i(vim[k], qi, a1, a2);
        g_W2q1[(size_t)(2 * p + 1) * DM + h] = (int8_t)a1;
        g_W2q2[(size_t)(2 * p + 1) * DM + h] = (int8_t)a2;
    }
    if (tid == 0) {
        g_sW2[2 * p]     = amr * (1.0f / 127.0f);
        g_sW2[2 * p + 1] = ami * (1.0f / 127.0f);
    }
}

__global__ void __launch_bounds__(256)
prep_Cwq_k(const float* __restrict__ c_re, const float* __restrict__ c_im) {
    __shared__ float red[8];
    const int h = blockIdx.x;
    const int tid = threadIdx.x;
    float v[8];
    float am = 0.0f;
#pragma unroll
    for (int k = 0; k < 4; ++k) {
        int p = tid + k * 256;
        float re = c_re[(size_t)h * DM + p] * g_chs[p];
        float im = -c_im[(size_t)h * DM + p] * g_chs[p];
        v[2 * k] = re;
        v[2 * k + 1] = im;
        am = fmaxf(am, fmaxf(fabsf(re), fabsf(im)));
    }
#pragma unroll
    for (int o = 16; o > 0; o >>= 1) am = fmaxf(am, __shfl_xor_sync(0xffffffffu, am, o));
    if ((tid & 31) == 0) red[tid >> 5] = am;
    __syncthreads();
    am = red[0];
#pragma unroll
    for (int i = 1; i < 8; ++i) am = fmaxf(am, red[i]);
    float qs = am > 0 ? 127.0f / am : 0.0f;
#pragma unroll
    for (int k = 0; k < 4; ++k) {
        int p = tid + k * 256;
        int a1, a2, b1, b2;
        quant2i(v[2 * k], qs, a1, a2);
        quant2i(v[2 * k + 1], qs, b1, b2);
        uint16_t w1 = (uint16_t)((uint8_t)a1 | ((uint16_t)(uint8_t)b1 << 8));
        uint16_t w2 = (uint16_t)((uint8_t)a2 | ((uint16_t)(uint8_t)b2 << 8));
        *(uint16_t*)(g_Cwq1 + (size_t)h * DM2 + 2 * p) = w1;
        *(uint16_t*)(g_Cwq2 + (size_t)h * DM2 + 2 * p) = w2;
    }
    if (tid == 0) g_sCw[h] = am * (1.0f / 127.0f);
}

// fp32 transpose: in [R][C2] -> out [C2][R]; ILV>0: interleave halves
// (out-row j<ILV -> 2j, j>=ILV -> 2(j-ILV)+1)
__global__ void wtrans_k(const float* __restrict__ in, float* __restrict__ outT,
                         int R, int C2, int ilv) {
    __shared__ float t[32][33];
    int r = blockIdx.y * 32 + threadIdx.y;
    int c = blockIdx.x * 32 + threadIdx.x;
    t[threadIdx.y][threadIdx.x] = in[(size_t)r * C2 + c];
    __syncthreads();
    int orow = blockIdx.x * 32 + threadIdx.y;
    int ocol = blockIdx.y * 32 + threadIdx.x;
    if (ilv) orow = (orow < ilv) ? (2 * orow) : (2 * (orow - ilv) + 1);
    outT[(size_t)orow * R + ocol] = t[threadIdx.x][threadIdx.y];
}

// weight row quantizer (fp32 in, 1024/row, 256 thr x 4 contiguous)
__global__ void __launch_bounds__(256)
rowq_w_k(const float* __restrict__ in, int8_t* __restrict__ q1,
         int8_t* __restrict__ q2, float* __restrict__ sOut) {
    __shared__ float red[8];
    const size_t base = (size_t)blockIdx.x * DM;
    const int tid = threadIdx.x;
    const int c0 = tid * 4;
    float4 vv = *reinterpret_cast<const float4*>(in + base + c0);
    float v[4] = {vv.x, vv.y, vv.z, vv.w};
    float am = 0.0f;
#pragma unroll
    for (int k = 0; k < 4; ++k) am = fmaxf(am, fabsf(v[k]));
#pragma unroll
    for (int o = 16; o > 0; o >>= 1) am = fmaxf(am, __shfl_xor_sync(0xffffffffu, am, o));
    if ((tid & 31) == 0) red[tid >> 5] = am;
    __syncthreads();
    am = red[0];
#pragma unroll
    for (int i = 1; i < 8; ++i) am = fmaxf(am, red[i]);
    float qs = am > 0 ? 127.0f / am : 0.0f;
    int a1[4], a2[4];
#pragma unroll
    for (int k = 0; k < 4; ++k) quant2i(v[k], qs, a1[k], a2[k]);
    *(uint32_t*)(q1 + base + c0) = pack4(a1[0], a1[1], a1[2], a1[3]);
    *(uint32_t*)(q2 + base + c0) = pack4(a2[0], a2[1], a2[2], a2[3]);
    if (tid == 0) sOut[blockIdx.x] = am * (1.0f / 127.0f);
}

// xs row quantizer: bf16 in, 2048/row, channel-flattening. 256 thr x 8 contig.
__global__ void __launch_bounds__(256)
rowq_xs_k(const bf16* __restrict__ in, int8_t* __restrict__ q1,
          int8_t* __restrict__ q2, float* __restrict__ sOut) {
    __shared__ float red[8];
    const size_t base = (size_t)blockIdx.x * DM2;
    const int tid = threadIdx.x;
    const int c0 = tid * 8;
    const bf162* pin = reinterpret_cast<const bf162*>(in + base + c0);
    float v[8];
    float am = 0.0f;
#pragma unroll
    for (int k = 0; k < 4; ++k) {
        float2 f = __bfloat1622float2(pin[k]);
        float sc = g_chsi[(c0 >> 1) + k];
        v[2 * k] = f.x * sc;
        v[2 * k + 1] = f.y * sc;
        am = fmaxf(am, fmaxf(fabsf(v[2 * k]), fabsf(v[2 * k + 1])));
    }
#pragma unroll
    for (int o = 16; o > 0; o >>= 1) am = fmaxf(am, __shfl_xor_sync(0xffffffffu, am, o));
    if ((tid & 31) == 0) red[tid >> 5] = am;
    __syncthreads();
    am = red[0];
#pragma unroll
    for (int i = 1; i < 8; ++i) am = fmaxf(am, red[i]);
    float qs = am > 0 ? 127.0f / am : 0.0f;
    uint2 w1, w2;
    quant8(v, qs, w1, w2);
    *(uint2*)(q1 + base + c0) = w1;
    *(uint2*)(q2 + base + c0) = w2;
    if (tid == 0) sOut[blockIdx.x] = am * (1.0f / 127.0f);
}

// gg row quantizer: bf16 in, 1024/row. 128 thr x 8 contiguous.
__global__ void __launch_bounds__(128)
rowq_gg_k(const bf16* __restrict__ in, int8_t* __restrict__ q1,
          int8_t* __restrict__ q2, float* __restrict__ sOut) {
    __shared__ float redm[4];
    const size_t base = (size_t)blockIdx.x * DM;
    const int t = threadIdx.x;
    const int c0 = t * 8;
    const bf162* pin = reinterpret_cast<const bf162*>(in + base + c0);
    float v[8];
    float am = 0.0f;
#pragma unroll
    for (int k = 0; k < 4; ++k) {
        float2 f = __bfloat1622float2(pin[k]);
        v[2 * k] = f.x;
        v[2 * k + 1] = f.y;
        am = fmaxf(am, fmaxf(fabsf(f.x), fabsf(f.y)));
    }
#pragma unroll
    for (int o = 16; o > 0; o >>= 1) am = fmaxf(am, __shfl_xor_sync(0xffffffffu, am, o));
    if ((t & 31) == 0) redm[t >> 5] = am;
    __syncthreads();
    am = fmaxf(fmaxf(redm[0], redm[1]), fmaxf(redm[2], redm[3]));
    float qs = am > 0 ? 127.0f / am : 0.0f;
    uint2 w1, w2;
    quant8(v, qs, w1, w2);
    *(uint2*)(q1 + base + c0) = w1;
    *(uint2*)(q2 + base + c0) = w2;
    if (t == 0) sOut[blockIdx.x] = am * (1.0f / 127.0f);
}

// ---------------- scan: fp32 recurrence over bf16 data, in-place -------------
__global__ void scan_k(bf162* __restrict__ bu) {
    int idx = blockIdx.x * blockDim.x + threadIdx.x;
    if (idx >= BATCH * DM) return;
    int b = idx >> 10, p = idx & (DM - 1);
    float2 a = g_lamb[p];
    bf162* ptr = bu + (size_t)b * SEQ * DM + p;
    float xr = 0.0f, xi = 0.0f;
    const int U = 8;
    bf162 cur[U], nxt[U];
#pragma unroll
    for (int i = 0; i < U; i++) cur[i] = ptr[(size_t)i * DM];
#pragma unroll
    for (int i = 0; i < U; i++) nxt[i] = __floats2bfloat162_rn(0.f, 0.f);
    for (int l0 = 0; l0 < SEQ; l0 += U) {
        if (l0 + U < SEQ) {
#pragma unroll
            for (int i = 0; i < U; i++) nxt[i] = ptr[(size_t)(l0 + U + i) * DM];
        }
#pragma unroll
        for (int i = 0; i < U; i++) {
            float2 u = __bfloat1622float2(cur[i]);
            float nr = fmaf(a.x, xr, fmaf(-a.y, xi, u.x));
            float ni = fmaf(a.x, xi, fmaf(a.y, xr, u.y));
            xr = nr; xi = ni;
            ptr[(size_t)(l0 + i) * DM] = __floats2bfloat162_rn(xr, xi);
        }
#pragma unroll
        for (int i = 0; i < U; i++) cur[i] = nxt[i];
    }
}

// ---------------- LayerNorm (+optional residual add, +optional int8 quant) ---
__global__ void __launch_bounds__(128)
ln_k(const float* __restrict__ in, const float* __restrict__ add,
     float* __restrict__ out, int8_t* __restrict__ q1, int8_t* __restrict__ q2,
     float* __restrict__ sOut,
     const float* __restrict__ g, const float* __restrict__ bb) {
    __shared__ float red[8];
    __shared__ float redm[4];
    size_t base = (size_t)blockIdx.x * DM;
    int t = threadIdx.x;
    int c0 = t * 8;
    float v[8];
    float4 i0 = *reinterpret_cast<const float4*>(in + base + c0);
    float4 i1 = *reinterpret_cast<const float4*>(in + base + c0 + 4);
    v[0] = i0.x; v[1] = i0.y; v[2] = i0.z; v[3] = i0.w;
    v[4] = i1.x; v[5] = i1.y; v[6] = i1.z; v[7] = i1.w;
    if (add) {
        float4 a0 = *reinterpret_cast<const float4*>(add + base + c0);
        float4 a1 = *reinterpret_cast<const float4*>(add + base + c0 + 4);
        v[0] += a0.x; v[1] += a0.y; v[2] += a0.z; v[3] += a0.w;
        v[4] += a1.x; v[5] += a1.y; v[6] += a1.z; v[7] += a1.w;
    }
    float s = 0.0f;
#pragma unroll
    for (int i = 0; i < 8; i++) s += v[i];
#pragma unroll
    for (int o = 16; o > 0; o >>= 1) s += __shfl_xor_sync(0xffffffffu, s, o);
    if ((t & 31) == 0) red[t >> 5] = s;
    __syncthreads();
    float mean = (red[0] + red[1] + red[2] + red[3]) * (1.0f / DM);
    float s2 = 0.0f;
#pragma unroll
    for (int i = 0; i < 8; i++) { float d = v[i] - mean; s2 += d * d; }
#pragma unroll
    for (int o = 16; o > 0; o >>= 1) s2 += __shfl_xor_sync(0xffffffffu, s2, o);
    if ((t & 31) == 0) red[4 + (t >> 5)] = s2;
    __syncthreads();
    float var = (red[4] + red[5] + red[6] + red[7]) * (1.0f / DM);
    float inv = rsqrtf(var + 1e-5f);
    float4 g0 = *reinterpret_cast<const float4*>(g + c0);
    float4 g1 = *reinterpret_cast<const float4*>(g + c0 + 4);
    float4 b0 = *reinterpret_cast<const float4*>(bb + c0);
    float4 b1 = *reinterpret_cast<const float4*>(bb + c0 + 4);
    float gg[8] = {g0.x, g0.y, g0.z, g0.w, g1.x, g1.y, g1.z, g1.w};
    float bbv[8] = {b0.x, b0.y, b0.z, b0.w, b1.x, b1.y, b1.z, b1.w};
    float y[8];
    float am = 0.0f;
#pragma unroll
    for (int i = 0; i < 8; i++) {
        y[i] = (v[i] - mean) * inv * gg[i] + bbv[i];
        am = fmaxf(am, fabsf(y[i]));
    }
    *reinterpret_cast<float4*>(out + base + c0) =
        make_float4(y[0], y[1], y[2], y[3]);
    *reinterpret_cast<float4*>(out + base + c0 + 4) =
        make_float4(y[4], y[5], y[6], y[7]);
    if (q1) {
#pragma unroll
        for (int o = 16; o > 0; o >>= 1) am = fmaxf(am, __shfl_xor_sync(0xffffffffu, am, o));
        if ((t & 31) == 0) redm[t >> 5] = am;
        __syncthreads();
        am = fmaxf(fmaxf(redm[0], redm[1]), fmaxf(redm[2], redm[3]));
        float qs = am > 0 ? 127.0f / am : 0.0f;
        uint2 w1, w2;
        quant8(y, qs, w1, w2);
        *(uint2*)(q1 + base + c0) = w1;
        *(uint2*)(q2 + base + c0) = w2;
        if (t == 0) sOut[blockIdx.x] = am * (1.0f / 127.0f);
    }
}

// ---------------- fused double-LN at layer boundary ---------------------------
__global__ void __launch_bounds__(128)
ln2_k(const float* __restrict__ z, const float* __restrict__ hprev,
      float* __restrict__ hout, float* __restrict__ fxout,
      int8_t* __restrict__ q1, int8_t* __restrict__ q2,
      float* __restrict__ sOut,
      const float* __restrict__ g1v, const float* __restrict__ b1v,
      const float* __restrict__ g2v, const float* __restrict__ b2v) {
    __shared__ float red[8];
    __shared__ float redm[4];
    size_t base = (size_t)blockIdx.x * DM;
    int t = threadIdx.x;
    int c0 = t * 8;
    float v[8];
    {
        float4 i0 = *reinterpret_cast<const float4*>(z + base + c0);
        float4 i1 = *reinterpret_cast<const float4*>(z + base + c0 + 4);
        float4 a0 = *reinterpret_cast<const float4*>(hprev + base + c0);
        float4 a1 = *reinterpret_cast<const float4*>(hprev + base + c0 + 4);
        v[0] = i0.x + a0.x; v[1] = i0.y + a0.y; v[2] = i0.z + a0.z; v[3] = i0.w + a0.w;
        v[4] = i1.x + a1.x; v[5] = i1.y + a1.y; v[6] = i1.z + a1.z; v[7] = i1.w + a1.w;
    }
    float s = 0.0f;
#pragma unroll
    for (int i = 0; i < 8; i++) s += v[i];
#pragma unroll
    for (int o = 16; o > 0; o >>= 1) s += __shfl_xor_sync(0xffffffffu, s, o);
    if ((t & 31) == 0) red[t >> 5] = s;
    __syncthreads();
    float mean = (red[0] + red[1] + red[2] + red[3]) * (1.0f / DM);
    float s2 = 0.0f;
#pragma unroll
    for (int i = 0; i < 8; i++) { float d = v[i] - mean; s2 += d * d; }
#pragma unroll
    for (int o = 16; o > 0; o >>= 1) s2 += __shfl_xor_sync(0xffffffffu, s2, o);
    if ((t & 31) == 0) red[4 + (t >> 5)] = s2;
    __syncthreads();
    float var = (red[4] + red[5] + red[6] + red[7]) * (1.0f / DM);
    float inv = rsqrtf(var + 1e-5f);
    float y1[8];
    {
        float4 g0 = *reinterpret_cast<const float4*>(g1v + c0);
        float4 g1 = *reinterpret_cast<const float4*>(g1v + c0 + 4);
        float4 b0 = *reinterpret_cast<const float4*>(b1v + c0);
        float4 b1 = *reinterpret_cast<const float4*>(b1v + c0 + 4);
        float gg[8] = {g0.x, g0.y, g0.z, g0.w, g1.x, g1.y, g1.z, g1.w};
        float bb[8] = {b0.x, b0.y, b0.z, b0.w, b1.x, b1.y, b1.z, b1.w};
#pragma unroll
        for (int i = 0; i < 8; i++)
            y1[i] = (v[i] - mean) * inv * gg[i] + bb[i];
    }
    *reinterpret_cast<float4*>(hout + base + c0) =
        make_float4(y1[0], y1[1], y1[2], y1[3]);
    *reinterpret_cast<float4*>(hout + base + c0 + 4) =
        make_float4(y1[4], y1[5], y1[6], y1[7]);
    __syncthreads();
    s = 0.0f;
#pragma unroll
    for (int i = 0; i < 8; i++) s += y1[i];
#pragma unroll
    for (int o = 16; o > 0; o >>= 1) s += __shfl_xor_sync(0xffffffffu, s, o);
    if ((t & 31) == 0) red[t >> 5] = s;
    __syncthreads();
    mean = (red[0] + red[1] + red[2] + red[3]) * (1.0f / DM);
    s2 = 0.0f;
#pragma unroll
    for (int i = 0; i < 8; i++) { float d = y1[i] - mean; s2 += d * d; }
#pragma unroll
    for (int o = 16; o > 0; o >>= 1) s2 += __shfl_xor_sync(0xffffffffu, s2, o);
    if ((t & 31) == 0) red[4 + (t >> 5)] = s2;
    __syncthreads();
    var = (red[4] + red[5] + red[6] + red[7]) * (1.0f / DM);
    inv = rsqrtf(var + 1e-5f);
    float y2[8];
    float am = 0.0f;
    {
        float4 g0 = *reinterpret_cast<const float4*>(g2v + c0);
        float4 g1 = *reinterpret_cast<const float4*>(g2v + c0 + 4);
        float4 b0 = *reinterpret_cast<const float4*>(b2v + c0);
        float4 b1 = *reinterpret_cast<const float4*>(b2v + c0 + 4);
        float gg[8] = {g0.x, g0.y, g0.z, g0.w, g1.x, g1.y, g1.z, g1.w};
        float bb[8] = {b0.x, b0.y, b0.z, b0.w, b1.x, b1.y, b1.z, b1.w};
#pragma unroll
        for (int i = 0; i < 8; i++) {
            y2[i] = (y1[i] - mean) * inv * gg[i] + bb[i];
            am = fmaxf(am, fabsf(y2[i]));
        }
    }
    *reinterpret_cast<float4*>(fxout + base + c0) =
        make_float4(y2[0], y2[1], y2[2], y2[3]);
    *reinterpret_cast<float4*>(fxout + base + c0 + 4) =
        make_float4(y2[4], y2[5], y2[6], y2[7]);
#pragma unroll
    for (int o = 16; o > 0; o >>= 1) am = fmaxf(am, __shfl_xor_sync(0xffffffffu, am, o));
    if ((t & 31) == 0) redm[t >> 5] = am;
    __syncthreads();
    am = fmaxf(fmaxf(redm[0], redm[1]), fmaxf(redm[2], redm[3]));
    float qs = am > 0 ? 127.0f / am : 0.0f;
    uint2 w1, w2;
    quant8(y2, qs, w1, w2);
    *(uint2*)(q1 + base + c0) = w1;
    *(uint2*)(q2 + base + c0) = w2;
    if (t == 0) sOut[blockIdx.x] = am * (1.0f / 127.0f);
}

// ---------------- mean pool + decode -----------------------------------------
__global__ void pool_k(const float* __restrict__ h, float* __restrict__ pooled) {
    int idx = blockIdx.x * blockDim.x + threadIdx.x;
    if (idx >= BATCH * DM) return;
    int b = idx >> 10, d = idx & (DM - 1);
    const float* p = h + (size_t)b * SEQ * DM + d;
    float s = 0.0f;
#pragma unroll 8
    for (int l = 0; l < SEQ; l++) s += p[(size_t)l * DM];
    pooled[idx] = s * (1.0f / SEQ);
}

__global__ void dec_k(const float* __restrict__ pooled,
                      const float* __restrict__ w,
                      const float* __restrict__ b,
                      float* __restrict__ out) {
    __shared__ float red[8];
    int bi = blockIdx.x;
    int t = threadIdx.x;
    float s = 0.0f;
    for (int d = t; d < DM; d += 256) s += pooled[bi * DM + d] * w[d];
#pragma unroll
    for (int o = 16; o > 0; o >>= 1) s += __shfl_xor_sync(0xffffffffu, s, o);
    if ((t & 31) == 0) red[t >> 5] = s;
    __syncthreads();
    if (t == 0) {
        float tot = 0.0f;
#pragma unroll
        for (int i = 0; i < 8; i++) tot += red[i];
        out[bi] = tot + b[0];
    }
}

// ---------------- driver ----------------
extern "C" void kernel_launch(void* const* d_in, const int* in_sizes, int n_in,
                              void* d_out, int out_size) {
    const float* x        = (const float*)d_in[0];
    const float* enc_w    = (const float*)d_in[1];
    const float* enc_b    = (const float*)d_in[2];
    const float* ln1_g    = (const float*)d_in[3];
    const float* ln1_b    = (const float*)d_in[4];
    const float* lam_re   = (const float*)d_in[5];
    const float* lam_im   = (const float*)d_in[6];
    const float* b_re     = (const float*)d_in[7];
    const float* b_im     = (const float*)d_in[8];
    const float* c_re     = (const float*)d_in[9];
    const float* c_im     = (const float*)d_in[10];
    const float* d_skip   = (const float*)d_in[11];
    const float* log_step = (const float*)d_in[12];
    const float* ffn_g    = (const float*)d_in[13];
    const float* ffn_b    = (const float*)d_in[14];
    const float* ff_enc_w = (const float*)d_in[15];
    const float* ff_dec_w = (const float*)d_in[16];
    const float* norm_g   = (const float*)d_in[17];
    const float* norm_b   = (const float*)d_in[18];
    const float* dec_w    = (const float*)d_in[19];
    const float* dec_b    = (const float*)d_in[20];
    float* out = (float*)d_out;

    static int attr_done = 0;
    if (!attr_done) {
        cudaFuncSetAttribute((const void*)imma_gemm<0, true>,
                             cudaFuncAttributeMaxDynamicSharedMemorySize, SMEM_GEMM);
        cudaFuncSetAttribute((const void*)imma_gemm<2, false>,
                             cudaFuncAttributeMaxDynamicSharedMemorySize, SMEM_GEMM);
        cudaFuncSetAttribute((const void*)imma_gemm<3, false>,
                             cudaFuncAttributeMaxDynamicSharedMemorySize, SMEM_GEMM);
        cudaFuncSetAttribute((const void*)imma_gemm<4, false>,
                             cudaFuncAttributeMaxDynamicSharedMemorySize, SMEM_GEMM);
        attr_done = 1;
    }

    float *p_h, *p_fx, *p_fy, *p_z, *p_wtmp, *p_pooled;
    bf16 *p_big;
    int8_t *p_fxq1, *p_fxq2, *p_xsq1, *p_xsq2, *p_fyq1, *p_fyq2, *p_ggq1, *p_ggq2;
    int8_t *p_W2q1, *p_W2q2, *p_Cwq1, *p_Cwq2, *p_feq1, *p_feq2, *p_fdq1, *p_fdq2;
    float *p_sfx, *p_sxs, *p_sfy, *p_sgg, *p_sW2, *p_sCw, *p_sfe, *p_sfd;
    cudaGetSymbolAddress((void**)&p_h, g_h);
    cudaGetSymbolAddress((void**)&p_fx, g_fx);
    cudaGetSymbolAddress((void**)&p_fy, g_fy);
    cudaGetSymbolAddress((void**)&p_z, g_z);
    cudaGetSymbolAddress((void**)&p_big, g_big);
    cudaGetSymbolAddress((void**)&p_wtmp, g_wtmp);
    cudaGetSymbolAddress((void**)&p_pooled, g_pooled);
    cudaGetSymbolAddress((void**)&p_fxq1, g_fxq1);
    cudaGetSymbolAddress((void**)&p_fxq2, g_fxq2);
    cudaGetSymbolAddress((void**)&p_xsq1, g_xsq1);
    cudaGetSymbolAddress((void**)&p_xsq2, g_xsq2);
    cudaGetSymbolAddress((void**)&p_fyq1, g_fyq1);
    cudaGetSymbolAddress((void**)&p_fyq2, g_fyq2);
    cudaGetSymbolAddress((void**)&p_ggq1, g_ggq1);
    cudaGetSymbolAddress((void**)&p_ggq2, g_ggq2);
    cudaGetSymbolAddress((void**)&p_W2q1, g_W2q1);
    cudaGetSymbolAddress((void**)&p_W2q2, g_W2q2);
    cudaGetSymbolAddress((void**)&p_Cwq1, g_Cwq1);
    cudaGetSymbolAddress((void**)&p_Cwq2, g_Cwq2);
    cudaGetSymbolAddress((void**)&p_feq1, g_feq1);
    cudaGetSymbolAddress((void**)&p_feq2, g_feq2);
    cudaGetSymbolAddress((void**)&p_fdq1, g_fdq1);
    cudaGetSymbolAddress((void**)&p_fdq2, g_fdq2);
    cudaGetSymbolAddress((void**)&p_sfx, g_sfx);
    cudaGetSymbolAddress((void**)&p_sxs, g_sxs);
    cudaGetSymbolAddress((void**)&p_sfy, g_sfy);
    cudaGetSymbolAddress((void**)&p_sgg, g_sgg);
    cudaGetSymbolAddress((void**)&p_sW2, g_sW2);
    cudaGetSymbolAddress((void**)&p_sCw, g_sCw);
    cudaGetSymbolAddress((void**)&p_sfe, g_sfe);
    cudaGetSymbolAddress((void**)&p_sfd, g_sfd);

    const int M = MROWS;

    // #1: encoder h = x @ enc_w + enc_b  (fp32, K=64)
    sgemm_enc<<<dim3(DM / TBN, M / TBM), 256>>>(x, enc_w, p_h, M, DM, D_IN, enc_b);
    // #2: layer-0 W2 quant + inline lamb/chs
    prep_W2q_k<<<DM, 256>>>(b_re, b_im, lam_re, lam_im, log_step);
    // #3: layer-0 fx = LN(h) + quant
    ln_k<<<M, 128>>>(p_h, nullptr, p_fx, p_fxq1, p_fxq2, p_sfx, ln1_g, ln1_b);

    for (int i = 0; i < NL; i++) {
        const size_t w1 = (size_t)i * DM;
        const size_t w2 = (size_t)i * DM * DM;
        const size_t w3 = (size_t)i * DM * DM2;

        // #4 (i=0): Bu = fx @ W2^T  [M, 2P] bf16 out  <-- ncu-captured launch
        imma_gemm<0, true><<<dim3(DM2 / 64, M / 64), 128, SMEM_GEMM>>>(
            p_fxq1, p_fxq2, p_W2q1, p_W2q2, p_big, DM2, DM,
            p_sfx, p_sW2, nullptr, nullptr);
        // Cw quant (needs g_chs from this layer's prep_W2q)
        prep_Cwq_k<<<DM, 256>>>(c_re + w2, c_im + w2);
        // sequential complex scan, in place
        scan_k<<<(BATCH * DM) / 128, 128>>>((bf162*)p_big);
        // quantize xs rows (channel-flattened)
        rowq_xs_k<<<M, 256>>>(p_big, p_xsq1, p_xsq2, p_sxs);
        // z = gelu(xs @ Cw^T + d*fx) + fx
        imma_gemm<2, false><<<dim3(DM / 64, M / 64), 128, SMEM_GEMM>>>(
            p_xsq1, p_xsq2, p_Cwq1, p_Cwq2, p_z, DM, DM2,
            p_sxs, p_sCw, p_fx, d_skip + w1);
        // ff_enc^T quant (interleaved a/g rows)
        wtrans_k<<<dim3(DM2 / 32, DM / 32), dim3(32, 32)>>>(
            ff_enc_w + w3, p_wtmp, DM, DM2, DM);
        rowq_w_k<<<DM2, 256>>>(p_wtmp, p_feq1, p_feq2, p_sfe);
        // fy = LN(z) + quant
        ln_k<<<M, 128>>>(p_z, nullptr, p_fy, p_fyq1, p_fyq2, p_sfy,
                         ffn_g + w1, ffn_b + w1);
        // gg = geglu(fy @ ff_enc)  fused epilogue -> bf16 [M, DM] in p_big
        imma_gemm<4, false><<<dim3(DM2 / 64, M / 64), 128, SMEM_GEMM>>>(
            p_fyq1, p_fyq2, p_feq1, p_feq2, p_big, DM2, DM,
            p_sfy, p_sfe, nullptr, nullptr);
        // quantize gg rows
        rowq_gg_k<<<M, 128>>>(p_big, p_ggq1, p_ggq2, p_sgg);
        // ff_dec^T quant
        wtrans_k<<<dim3(DM / 32, DM / 32), dim3(32, 32)>>>(
            ff_dec_w + w2, p_wtmp, DM, DM, 0);
        rowq_w_k<<<DM, 256>>>(p_wtmp, p_fdq1, p_fdq2, p_sfd);
        // z2 = gg @ ff_dec + fy   (into p_z)
        imma_gemm<3, false><<<dim3(DM / 64, M / 64), 128, SMEM_GEMM>>>(
            p_ggq1, p_ggq2, p_fdq1, p_fdq2, p_z, DM, DM,
            p_sgg, p_sfd, p_fy, nullptr);

        if (i + 1 < NL) {
            const size_t nw1 = (size_t)(i + 1) * DM;
            const size_t nw2 = (size_t)(i + 1) * DM * DM;
            prep_W2q_k<<<DM, 256>>>(b_re + nw2, b_im + nw2,
                                    lam_re + nw1, lam_im + nw1, log_step + nw1);
            ln2_k<<<M, 128>>>(p_z, p_h, p_h, p_fx, p_fxq1, p_fxq2, p_sfx,
                              norm_g + w1, norm_b + w1, ln1_g + nw1, ln1_b + nw1);
        } else {
            ln_k<<<M, 128>>>(p_z, p_h, p_h, nullptr, nullptr, nullptr,
                             norm_g + w1, norm_b + w1);
        }
    }

    pool_k<<<(BATCH * DM) / 128, 128>>>(p_h, p_pooled);
    dec_k<<<BATCH, 256>>>(p_pooled, dec_w, dec_b, out);
}

// round 14
// speedup vs baseline: 3.6031x; 1.0619x over previous
#include <cuda_runtime.h>
#include <cuda_bf16.h>
#include <math.h>
#include <stdint.h>

// ---------------- problem constants ----------------
#define BATCH   8
#define SEQ     2048
#define D_IN    64
#define DM      1024
#define DM2     2048
#define NL      4
#define MROWS   (BATCH*SEQ)   // 16384

typedef __nv_bfloat16 bf16;
typedef __nv_bfloat162 bf162;

// ---------------- scratch (device globals) ----------------
__device__ float g_h  [(size_t)MROWS * DM];
__device__ float g_fx [(size_t)MROWS * DM];
__device__ float g_fy [(size_t)MROWS * DM];
__device__ float g_z  [(size_t)MROWS * DM];
__device__ __align__(16) bf16 g_big[(size_t)MROWS * DM2];   // bu->xs; then gg [M,DM]
__device__ float g_wtmp[(size_t)DM2 * DM];                  // transposed weight staging

__device__ __align__(16) int8_t g_fxq1[(size_t)MROWS * DM];
__device__ __align__(16) int8_t g_fxq2[(size_t)MROWS * DM];
__device__ __align__(16) int8_t g_xsq1[(size_t)MROWS * DM2];
__device__ __align__(16) int8_t g_xsq2[(size_t)MROWS * DM2];
__device__ __align__(16) int8_t g_fyq1[(size_t)MROWS * DM];
__device__ __align__(16) int8_t g_fyq2[(size_t)MROWS * DM];
__device__ __align__(16) int8_t g_ggq1[(size_t)MROWS * DM];
__device__ __align__(16) int8_t g_ggq2[(size_t)MROWS * DM];

__device__ __align__(16) int8_t g_W2q1[(size_t)DM2 * DM];
__device__ __align__(16) int8_t g_W2q2[(size_t)DM2 * DM];
__device__ __align__(16) int8_t g_Cwq1[(size_t)DM * DM2];
__device__ __align__(16) int8_t g_Cwq2[(size_t)DM * DM2];
__device__ __align__(16) int8_t g_feq1[(size_t)DM2 * DM];
__device__ __align__(16) int8_t g_feq2[(size_t)DM2 * DM];
__device__ __align__(16) int8_t g_fdq1[(size_t)DM * DM];
__device__ __align__(16) int8_t g_fdq2[(size_t)DM * DM];

__device__ float g_sfx[MROWS], g_sxs[MROWS], g_sfy[MROWS], g_sgg[MROWS];
__device__ float g_sW2[DM2], g_sCw[DM], g_sfe[DM2], g_sfd[DM];

__device__ float2 g_lamb[DM];
__device__ float  g_chs [DM];
__device__ float  g_chsi[DM];
__device__ float  g_pooled[BATCH * DM];

// ---------------- helpers ----------------
__device__ __forceinline__ float gelu_f(float x) {
    return 0.5f * x * (1.0f + erff(x * 0.70710678118654752f));
}
__device__ __forceinline__ uint32_t s2u(const void* p) {
    uint32_t a;
    asm("{ .reg .u64 t; cvta.to.shared.u64 t, %1; cvt.u32.u64 %0, t; }"
        : "=r"(a) : "l"(p));
    return a;
}
__device__ __forceinline__ void cpasync16(uint32_t s, const void* g) {
    asm volatile("cp.async.cg.shared.global [%0], [%1], 16;" :: "r"(s), "l"(g));
}
__device__ __forceinline__ void ldsm_x4(uint32_t* r, uint32_t addr) {
    asm volatile("ldmatrix.sync.aligned.m8n8.x4.shared.b16 {%0,%1,%2,%3}, [%4];"
                 : "=r"(r[0]), "=r"(r[1]), "=r"(r[2]), "=r"(r[3]) : "r"(addr));
}
__device__ __forceinline__ void mma_s8(int* d, const uint32_t* a,
                                       uint32_t b0, uint32_t b1) {
    asm volatile(
        "mma.sync.aligned.m16n8k32.row.col.s32.s8.s8.s32 "
        "{%0,%1,%2,%3}, {%4,%5,%6,%7}, {%8,%9}, {%0,%1,%2,%3};"
        : "+r"(d[0]), "+r"(d[1]), "+r"(d[2]), "+r"(d[3])
        : "r"(a[0]), "r"(a[1]), "r"(a[2]), "r"(a[3]), "r"(b0), "r"(b1));
}
__device__ __forceinline__ void quant2i(float v, float qs, int& o1, int& o2) {
    float t = v * qs;
    o1 = __float2int_rn(t);
    o2 = __float2int_rn((t - (float)o1) * 252.0f);
}
__device__ __forceinline__ uint32_t pack4(int a, int b, int c, int d) {
    return (uint32_t)(uint8_t)a | ((uint32_t)(uint8_t)b << 8) |
           ((uint32_t)(uint8_t)c << 16) | ((uint32_t)(uint8_t)d << 24);
}
__device__ __forceinline__ void quant8(const float* v, float qs,
                                       uint2& w1, uint2& w2) {
    int a1[8], a2[8];
#pragma unroll
    for (int i = 0; i < 8; i++) quant2i(v[i], qs, a1[i], a2[i]);
    w1.x = pack4(a1[0], a1[1], a1[2], a1[3]);
    w1.y = pack4(a1[4], a1[5], a1[6], a1[7]);
    w2.x = pack4(a2[0], a2[1], a2[2], a2[3]);
    w2.y = pack4(a2[4], a2[5], a2[6], a2[7]);
}

// ---------------- IMMA split-int8 GEMM: C[M,N] = sA.sB.(A @ B^T) -------------
// CTA 64x64, 4 warps (2m x 2n, 32x32 each), 4 CTAs/SM, 3-stage, 1 barrier/chunk.
// Fragment prefetch: all 8 ldsm of a ks-step issued before its mma.
// EPI 0: plain  2: gelu(v + e1[n]*e0[m,n]) + e0[m,n]  3: v + e0[m,n]
// EPI 4: geglu pair-fused: out[m, n/2] = bf16( v0 * gelu(v1) )
// OBF: write bf162 pairs instead of float2 (EPI 0 path).
#define STAGE_B   16384
#define NSTAGE    3
#define SMEM_GEMM (NSTAGE * STAGE_B)

template <int EPI, bool OBF>
__global__ void __launch_bounds__(128, 4)
imma_gemm(const int8_t* __restrict__ Aq1, const int8_t* __restrict__ Aq2,
          const int8_t* __restrict__ Bq1, const int8_t* __restrict__ Bq2,
          void* __restrict__ Cout, int N, int K,
          const float* __restrict__ sA, const float* __restrict__ sB,
          const float* __restrict__ e0, const float* __restrict__ e1) {
    extern __shared__ __align__(128) char smem[];
    const int tid = threadIdx.x;
    const int wid = tid >> 5;
    const int lid = tid & 31;
    const int wm = wid & 1;
    const int wn = wid >> 1;
    const int bm = blockIdx.y * 64;
    const int bn = blockIdx.x * 64;
    const uint32_t sbase = s2u(smem);
    const int nch = K >> 6;

    auto load_stage = [&](int st, int c) {
        const int kc = c << 6;
        const uint32_t stb = sbase + st * STAGE_B;
#pragma unroll
        for (int t = 0; t < 8; ++t) {
            int i = tid + t * 128;
            int isB = (i >= 512);
            int ii = i & 511;
            int row = ii >> 3, j = ii & 7;
            const int8_t* src = isB ? ((j < 4) ? Bq1 : Bq2)
                                    : ((j < 4) ? Aq1 : Aq2);
            size_t go = (size_t)((isB ? bn : bm) + row) * K + kc + (j & 3) * 16;
            uint32_t dst = stb + (isB ? 8192u : 0u) + row * 128 +
                           (uint32_t)((j ^ (row & 7)) << 4);
            cpasync16(dst, src + go);
        }
    };

    int acc1[2][4][4], accX[2][4][4];
#pragma unroll
    for (int mt = 0; mt < 2; mt++)
#pragma unroll
        for (int nt = 0; nt < 4; nt++)
#pragma unroll
            for (int q = 0; q < 4; q++) { acc1[mt][nt][q] = 0; accX[mt][nt][q] = 0; }

    load_stage(0, 0); asm volatile("cp.async.commit_group;" ::: "memory");
    load_stage(1, 1); asm volatile("cp.async.commit_group;" ::: "memory");

    const int a_row = wm * 32 + (lid & 15);
    const int b_row = wn * 32 + (lid & 15);
    const int lc = lid >> 4;

    int st = 0;
    for (int c = 0; c < nch; ++c) {
        if (c + 1 < nch) asm volatile("cp.async.wait_group 1;" ::: "memory");
        else             asm volatile("cp.async.wait_group 0;" ::: "memory");
        __syncthreads();

        int st2 = st + 2; if (st2 >= 3) st2 -= 3;
        if (c + 2 < nch) load_stage(st2, c + 2);
        asm volatile("cp.async.commit_group;" ::: "memory");

        const uint32_t smA = sbase + st * STAGE_B;
        const uint32_t smB = smA + 8192;
#pragma unroll
        for (int ks = 0; ks < 2; ++ks) {
            uint32_t aq1[2][4], aq2[2][4], bb[2][4], bb2[2][4];
            const int c1 = ks * 2 + lc;
            const int c2 = 4 + ks * 2 + lc;
#pragma unroll
            for (int mt = 0; mt < 2; ++mt) {
                int row = a_row + mt * 16;
                ldsm_x4(aq1[mt], smA + row * 128 + ((c1 ^ (row & 7)) << 4));
            }
#pragma unroll
            for (int pp = 0; pp < 2; ++pp) {
                int row = b_row + pp * 16;
                ldsm_x4(bb[pp], smB + row * 128 + ((c1 ^ (row & 7)) << 4));
            }
#pragma unroll
            for (int mt = 0; mt < 2; ++mt) {
                int row = a_row + mt * 16;
                ldsm_x4(aq2[mt], smA + row * 128 + ((c2 ^ (row & 7)) << 4));
            }
#pragma unroll
            for (int pp = 0; pp < 2; ++pp) {
                int row = b_row + pp * 16;
                ldsm_x4(bb2[pp], smB + row * 128 + ((c2 ^ (row & 7)) << 4));
            }
#pragma unroll
            for (int mt = 0; mt < 2; ++mt)
#pragma unroll
                for (int pp = 0; pp < 2; ++pp) {
                    mma_s8(acc1[mt][2 * pp],     aq1[mt], bb[pp][0], bb[pp][2]);
                    mma_s8(acc1[mt][2 * pp + 1], aq1[mt], bb[pp][1], bb[pp][3]);
                }
#pragma unroll
            for (int mt = 0; mt < 2; ++mt)
#pragma unroll
                for (int pp = 0; pp < 2; ++pp) {
                    mma_s8(accX[mt][2 * pp],     aq2[mt], bb[pp][0], bb[pp][2]);
                    mma_s8(accX[mt][2 * pp + 1], aq2[mt], bb[pp][1], bb[pp][3]);
                }
#pragma unroll
            for (int mt = 0; mt < 2; ++mt)
#pragma unroll
                for (int pp = 0; pp < 2; ++pp) {
                    mma_s8(accX[mt][2 * pp],     aq1[mt], bb2[pp][0], bb2[pp][2]);
                    mma_s8(accX[mt][2 * pp + 1], aq1[mt], bb2[pp][1], bb2[pp][3]);
                }
        }
        if (++st >= 3) st = 0;
    }

    const int tr = lid >> 2;
    const int tc = (lid & 3) * 2;
    const float ix = 1.0f / 252.0f;
#pragma unroll
    for (int mt = 0; mt < 2; ++mt) {
#pragma unroll
        for (int half = 0; half < 2; ++half) {
            const int m = bm + wm * 32 + mt * 16 + tr + half * 8;
            const size_t rowoff = (size_t)m * N;
            const float sa = sA[m];
#pragma unroll
            for (int nt = 0; nt < 4; ++nt) {
                const int n = bn + wn * 32 + nt * 8 + tc;
                float v0 = (__int2float_rn(acc1[mt][nt][half * 2 + 0]) +
                            __int2float_rn(accX[mt][nt][half * 2 + 0]) * ix) *
                           sa * sB[n];
                float v1 = (__int2float_rn(acc1[mt][nt][half * 2 + 1]) +
                            __int2float_rn(accX[mt][nt][half * 2 + 1]) * ix) *
                           sa * sB[n + 1];
                if (EPI == 4) {
                    float prod = v0 * gelu_f(v1);
                    ((bf16*)Cout)[(size_t)m * (N >> 1) + (n >> 1)] =
                        __float2bfloat16(prod);
                    continue;
                }
                const size_t idx = rowoff + n;
                if (EPI == 2) {
                    float f0 = e0[idx], f1 = e0[idx + 1];
                    v0 = gelu_f(fmaf(e1[n], f0, v0)) + f0;
                    v1 = gelu_f(fmaf(e1[n + 1], f1, v1)) + f1;
                } else if (EPI == 3) {
                    v0 += e0[idx];
                    v1 += e0[idx + 1];
                }
                if (OBF) {
                    ((bf162*)Cout)[idx >> 1] = __floats2bfloat162_rn(v0, v1);
                } else {
                    *reinterpret_cast<float2*>((float*)Cout + idx) =
                        make_float2(v0, v1);
                }
            }
        }
    }
}

// ---------------- fp32 SGEMM (encoder only, K=64) ----------------------------
#define TBM 128
#define TBN 128
#define TBK 8
__global__ void __launch_bounds__(256)
sgemm_enc(const float* __restrict__ A, const float* __restrict__ B,
          float* __restrict__ C, int M, int N, int K,
          const float* __restrict__ bias) {
    __shared__ float As[TBK][TBM + 4];
    __shared__ float Bs[TBK][TBN + 4];
    const int tid = threadIdx.x;
    const int bm = blockIdx.y * TBM;
    const int bn = blockIdx.x * TBN;
    const int arow = tid >> 1, akc = (tid & 1) * 4;
    const float* Aptr = A + (size_t)(bm + arow) * K + akc;
    const int br0 = tid >> 5, bc0 = (tid & 31) * 4;
    const float* Bptr = B + (size_t)br0 * N + bn + bc0;

    float acc[8][8];
#pragma unroll
    for (int i = 0; i < 8; i++)
#pragma unroll
        for (int j = 0; j < 8; j++) acc[i][j] = 0.0f;

    float4 aR = *reinterpret_cast<const float4*>(Aptr);
    float4 bR = *reinterpret_cast<const float4*>(Bptr);
    const int tm = tid >> 4, tn = tid & 15;

    for (int k0 = 0;;) {
        As[akc + 0][arow] = aR.x; As[akc + 1][arow] = aR.y;
        As[akc + 2][arow] = aR.z; As[akc + 3][arow] = aR.w;
        Bs[br0][bc0 + 0] = bR.x;  Bs[br0][bc0 + 1] = bR.y;
        Bs[br0][bc0 + 2] = bR.z;  Bs[br0][bc0 + 3] = bR.w;
        __syncthreads();
        k0 += TBK;
        bool more = (k0 < K);
        if (more) {
            aR = *reinterpret_cast<const float4*>(Aptr + k0);
            bR = *reinterpret_cast<const float4*>(Bptr + (size_t)k0 * N);
        }
#pragma unroll
        for (int kk = 0; kk < TBK; kk++) {
            float4 a0 = *reinterpret_cast<const float4*>(&As[kk][tm * 4]);
            float4 a1 = *reinterpret_cast<const float4*>(&As[kk][64 + tm * 4]);
            float4 b0 = *reinterpret_cast<const float4*>(&Bs[kk][tn * 4]);
            float4 b1 = *reinterpret_cast<const float4*>(&Bs[kk][64 + tn * 4]);
            float av[8] = {a0.x, a0.y, a0.z, a0.w, a1.x, a1.y, a1.z, a1.w};
            float bv[8] = {b0.x, b0.y, b0.z, b0.w, b1.x, b1.y, b1.z, b1.w};
#pragma unroll
            for (int i = 0; i < 8; i++)
#pragma unroll
                for (int j = 0; j < 8; j++)
                    acc[i][j] = fmaf(av[i], bv[j], acc[i][j]);
        }
        __syncthreads();
        if (!more) break;
    }
#pragma unroll
    for (int i = 0; i < 8; i++) {
        int r = bm + ((i < 4) ? (tm * 4 + i) : (64 + tm * 4 + i - 4));
        size_t rowoff = (size_t)r * N;
#pragma unroll
        for (int j = 0; j < 8; j++) {
            int c = bn + ((j < 4) ? (tn * 4 + j) : (64 + tn * 4 + j - 4));
            C[rowoff + c] = acc[i][j] + bias[c];
        }
    }
}

// ---------------- per-layer weight prep --------------------------------------
__global__ void __launch_bounds__(256)
prep_W2q_k(const float* __restrict__ b_re, const float* __restrict__ b_im,
           const float* __restrict__ lam_re, const float* __restrict__ lam_im,
           const float* __restrict__ log_step) {
    __shared__ float redA[8], redB[8];
    const int p = blockIdx.x;
    const int tid = threadIdx.x;
    float dt = expf(log_step[p]);
    float lr = lam_re[p], li = lam_im[p];
    float er = expf(lr * dt);
    float lbx = er * cosf(li * dt), lby = er * sinf(li * dt);
    float nr = lbx - 1.0f, ni = lby;
    float den = lr * lr + li * li;
    float2 c2 = make_float2((nr * lr + ni * li) / den, (ni * lr - nr * li) / den);
    if (tid == 0) {
        g_lamb[p] = make_float2(lbx, lby);
        float mag2 = lbx * lbx + lby * lby;
        float s = rsqrtf(fmaxf(1.0f - mag2, 1e-6f));
        s = fminf(fmaxf(s, 1.0f), 1000.0f);
        g_chs[p] = s;
        g_chsi[p] = 1.0f / s;
    }
    float vre[4], vim[4];
    float amr = 0.0f, ami = 0.0f;
#pragma unroll
    for (int k = 0; k < 4; ++k) {
        int h = tid + k * 256;
        float br = b_re[(size_t)p * DM + h];
        float bi = b_im[(size_t)p * DM + h];
        vre[k] = c2.x * br - c2.y * bi;
        vim[k] = c2.x * bi + c2.y * br;
        amr = fmaxf(amr, fabsf(vre[k]));
        ami = fmaxf(ami, fabsf(vim[k]));
    }
#pragma unroll
    for (int o = 16; o > 0; o >>= 1) {
        amr = fmaxf(amr, __shfl_xor_sync(0xffffffffu, amr, o));
        ami = fmaxf(ami, __shfl_xor_sync(0xffffffffu, ami, o));
    }
    if ((tid & 31) == 0) { redA[tid >> 5] = amr; redB[tid >> 5] = ami; }
    __syncthreads();
    amr = redA[0]; ami = redB[0];
#pragma unroll
    for (int i = 1; i < 8; ++i) { amr = fmaxf(amr, redA[i]); ami = fmaxf(ami, redB[i]); }
    float qr = amr > 0 ? 127.0f / amr : 0.0f;
    float qi = ami > 0 ? 127.0f / ami : 0.0f;
#pragma unroll
    for (int k = 0; k < 4; ++k) {
        int h = tid + k * 256;
        int a1, a2;
        quant2i(vre[k], qr, a1, a2);
        g_W2q1[(size_t)(2 * p) * DM + h] = (int8_t)a1;
        g_W2q2[(size_t)(2 * p) * DM + h] = (int8_t)a2;
        quant2i(vim[k], qi, a1, a2);
        g_W2q1[(size_t)(2 * p + 1) * DM + h] = (int8_t)a1;
        g_W2q2[(size_t)(2 * p + 1) * DM + h] = (int8_t)a2;
    }
    if (tid == 0) {
        g_sW2[2 * p]     = amr * (1.0f / 127.0f);
        g_sW2[2 * p + 1] = ami * (1.0f / 127.0f);
    }
}

__global__ void __launch_bounds__(256)
prep_Cwq_k(const float* __restrict__ c_re, const float* __restrict__ c_im) {
    __shared__ float red[8];
    const int h = blockIdx.x;
    const int tid = threadIdx.x;
    float v[8];
    float am = 0.0f;
#pragma unroll
    for (int k = 0; k < 4; ++k) {
        int p = tid + k * 256;
        float re = c_re[(size_t)h * DM + p] * g_chs[p];
        float im = -c_im[(size_t)h * DM + p] * g_chs[p];
        v[2 * k] = re;
        v[2 * k + 1] = im;
        am = fmaxf(am, fmaxf(fabsf(re), fabsf(im)));
    }
#pragma unroll
    for (int o = 16; o > 0; o >>= 1) am = fmaxf(am, __shfl_xor_sync(0xffffffffu, am, o));
    if ((tid & 31) == 0) red[tid >> 5] = am;
    __syncthreads();
    am = red[0];
#pragma unroll
    for (int i = 1; i < 8; ++i) am = fmaxf(am, red[i]);
    float qs = am > 0 ? 127.0f / am : 0.0f;
#pragma unroll
    for (int k = 0; k < 4; ++k) {
        int p = tid + k * 256;
        int a1, a2, b1, b2;
        quant2i(v[2 * k], qs, a1, a2);
        quant2i(v[2 * k + 1], qs, b1, b2);
        uint16_t w1 = (uint16_t)((uint8_t)a1 | ((uint16_t)(uint8_t)b1 << 8));
        uint16_t w2 = (uint16_t)((uint8_t)a2 | ((uint16_t)(uint8_t)b2 << 8));
        *(uint16_t*)(g_Cwq1 + (size_t)h * DM2 + 2 * p) = w1;
        *(uint16_t*)(g_Cwq2 + (size_t)h * DM2 + 2 * p) = w2;
    }
    if (tid == 0) g_sCw[h] = am * (1.0f / 127.0f);
}

// fp32 transpose: in [R][C2] -> out [C2][R]; ILV>0: interleave halves
__global__ void wtrans_k(const float* __restrict__ in, float* __restrict__ outT,
                         int R, int C2, int ilv) {
    __shared__ float t[32][33];
    int r = blockIdx.y * 32 + threadIdx.y;
    int c = blockIdx.x * 32 + threadIdx.x;
    t[threadIdx.y][threadIdx.x] = in[(size_t)r * C2 + c];
    __syncthreads();
    int orow = blockIdx.x * 32 + threadIdx.y;
    int ocol = blockIdx.y * 32 + threadIdx.x;
    if (ilv) orow = (orow < ilv) ? (2 * orow) : (2 * (orow - ilv) + 1);
    outT[(size_t)orow * R + ocol] = t[threadIdx.x][threadIdx.y];
}

// weight row quantizer (fp32 in, 1024/row, 256 thr x 4 contiguous)
__global__ void __launch_bounds__(256)
rowq_w_k(const float* __restrict__ in, int8_t* __restrict__ q1,
         int8_t* __restrict__ q2, float* __restrict__ sOut) {
    __shared__ float red[8];
    const size_t base = (size_t)blockIdx.x * DM;
    const int tid = threadIdx.x;
    const int c0 = tid * 4;
    float4 vv = *reinterpret_cast<const float4*>(in + base + c0);
    float v[4] = {vv.x, vv.y, vv.z, vv.w};
    float am = 0.0f;
#pragma unroll
    for (int k = 0; k < 4; ++k) am = fmaxf(am, fabsf(v[k]));
#pragma unroll
    for (int o = 16; o > 0; o >>= 1) am = fmaxf(am, __shfl_xor_sync(0xffffffffu, am, o));
    if ((tid & 31) == 0) red[tid >> 5] = am;
    __syncthreads();
    am = red[0];
#pragma unroll
    for (int i = 1; i < 8; ++i) am = fmaxf(am, red[i]);
    float qs = am > 0 ? 127.0f / am : 0.0f;
    int a1[4], a2[4];
#pragma unroll
    for (int k = 0; k < 4; ++k) quant2i(v[k], qs, a1[k], a2[k]);
    *(uint32_t*)(q1 + base + c0) = pack4(a1[0], a1[1], a1[2], a1[3]);
    *(uint32_t*)(q2 + base + c0) = pack4(a2[0], a2[1], a2[2], a2[3]);
    if (tid == 0) sOut[blockIdx.x] = am * (1.0f / 127.0f);
}

// xs row quantizer: bf16 in, 2048/row, channel-flattening. 256 thr x 8 contig.
__global__ void __launch_bounds__(256)
rowq_xs_k(const bf16* __restrict__ in, int8_t* __restrict__ q1,
          int8_t* __restrict__ q2, float* __restrict__ sOut) {
    __shared__ float red[8];
    const size_t base = (size_t)blockIdx.x * DM2;
    const int tid = threadIdx.x;
    const int c0 = tid * 8;
    const bf162* pin = reinterpret_cast<const bf162*>(in + base + c0);
    float v[8];
    float am = 0.0f;
#pragma unroll
    for (int k = 0; k < 4; ++k) {
        float2 f = __bfloat1622float2(pin[k]);
        float sc = g_chsi[(c0 >> 1) + k];
        v[2 * k] = f.x * sc;
        v[2 * k + 1] = f.y * sc;
        am = fmaxf(am, fmaxf(fabsf(v[2 * k]), fabsf(v[2 * k + 1])));
    }
#pragma unroll
    for (int o = 16; o > 0; o >>= 1) am = fmaxf(am, __shfl_xor_sync(0xffffffffu, am, o));
    if ((tid & 31) == 0) red[tid >> 5] = am;
    __syncthreads();
    am = red[0];
#pragma unroll
    for (int i = 1; i < 8; ++i) am = fmaxf(am, red[i]);
    float qs = am > 0 ? 127.0f / am : 0.0f;
    uint2 w1, w2;
    quant8(v, qs, w1, w2);
    *(uint2*)(q1 + base + c0) = w1;
    *(uint2*)(q2 + base + c0) = w2;
    if (tid == 0) sOut[blockIdx.x] = am * (1.0f / 127.0f);
}

// gg row quantizer: bf16 in, 1024/row. 128 thr x 8 contiguous.
__global__ void __launch_bounds__(128)
rowq_gg_k(const bf16* __restrict__ in, int8_t* __restrict__ q1,
          int8_t* __restrict__ q2, float* __restrict__ sOut) {
    __shared__ float redm[4];
    const size_t base = (size_t)blockIdx.x * DM;
    const int t = threadIdx.x;
    const int c0 = t * 8;
    const bf162* pin = reinterpret_cast<const bf162*>(in + base + c0);
    float v[8];
    float am = 0.0f;
#pragma unroll
    for (int k = 0; k < 4; ++k) {
        float2 f = __bfloat1622float2(pin[k]);
        v[2 * k] = f.x;
        v[2 * k + 1] = f.y;
        am = fmaxf(am, fmaxf(fabsf(f.x), fabsf(f.y)));
    }
#pragma unroll
    for (int o = 16; o > 0; o >>= 1) am = fmaxf(am, __shfl_xor_sync(0xffffffffu, am, o));
    if ((t & 31) == 0) redm[t >> 5] = am;
    __syncthreads();
    am = fmaxf(fmaxf(redm[0], redm[1]), fmaxf(redm[2], redm[3]));
    float qs = am > 0 ? 127.0f / am : 0.0f;
    uint2 w1, w2;
    quant8(v, qs, w1, w2);
    *(uint2*)(q1 + base + c0) = w1;
    *(uint2*)(q2 + base + c0) = w2;
    if (t == 0) sOut[blockIdx.x] = am * (1.0f / 127.0f);
}

// ---------------- scan: fp32 recurrence over bf16 data, in-place, U=16 -------
__global__ void scan_k(bf162* __restrict__ bu) {
    int idx = blockIdx.x * blockDim.x + threadIdx.x;
    if (idx >= BATCH * DM) return;
    int b = idx >> 10, p = idx & (DM - 1);
    float2 a = g_lamb[p];
    bf162* ptr = bu + (size_t)b * SEQ * DM + p;
    float xr = 0.0f, xi = 0.0f;
    const int U = 16;
    bf162 cur[U], nxt[U];
#pragma unroll
    for (int i = 0; i < U; i++) cur[i] = ptr[(size_t)i * DM];
#pragma unroll
    for (int i = 0; i < U; i++) nxt[i] = __floats2bfloat162_rn(0.f, 0.f);
    for (int l0 = 0; l0 < SEQ; l0 += U) {
        if (l0 + U < SEQ) {
#pragma unroll
            for (int i = 0; i < U; i++) nxt[i] = ptr[(size_t)(l0 + U + i) * DM];
        }
#pragma unroll
        for (int i = 0; i < U; i++) {
            float2 u = __bfloat1622float2(cur[i]);
            float nr = fmaf(a.x, xr, fmaf(-a.y, xi, u.x));
            float ni = fmaf(a.x, xi, fmaf(a.y, xr, u.y));
            xr = nr; xi = ni;
            ptr[(size_t)(l0 + i) * DM] = __floats2bfloat162_rn(xr, xi);
        }
#pragma unroll
        for (int i = 0; i < U; i++) cur[i] = nxt[i];
    }
}

// ---------------- LayerNorm (+optional residual add, +optional int8 quant) ---
__global__ void __launch_bounds__(128)
ln_k(const float* __restrict__ in, const float* __restrict__ add,
     float* __restrict__ out, int8_t* __restrict__ q1, int8_t* __restrict__ q2,
     float* __restrict__ sOut,
     const float* __restrict__ g, const float* __restrict__ bb) {
    __shared__ float red[8];
    __shared__ float redm[4];
    size_t base = (size_t)blockIdx.x * DM;
    int t = threadIdx.x;
    int c0 = t * 8;
    float v[8];
    float4 i0 = *reinterpret_cast<const float4*>(in + base + c0);
    float4 i1 = *reinterpret_cast<const float4*>(in + base + c0 + 4);
    v[0] = i0.x; v[1] = i0.y; v[2] = i0.z; v[3] = i0.w;
    v[4] = i1.x; v[5] = i1.y; v[6] = i1.z; v[7] = i1.w;
    if (add) {
        float4 a0 = *reinterpret_cast<const float4*>(add + base + c0);
        float4 a1 = *reinterpret_cast<const float4*>(add + base + c0 + 4);
        v[0] += a0.x; v[1] += a0.y; v[2] += a0.z; v[3] += a0.w;
        v[4] += a1.x; v[5] += a1.y; v[6] += a1.z; v[7] += a1.w;
    }
    float s = 0.0f;
#pragma unroll
    for (int i = 0; i < 8; i++) s += v[i];
#pragma unroll
    for (int o = 16; o > 0; o >>= 1) s += __shfl_xor_sync(0xffffffffu, s, o);
    if ((t & 31) == 0) red[t >> 5] = s;
    __syncthreads();
    float mean = (red[0] + red[1] + red[2] + red[3]) * (1.0f / DM);
    float s2 = 0.0f;
#pragma unroll
    for (int i = 0; i < 8; i++) { float d = v[i] - mean; s2 += d * d; }
#pragma unroll
    for (int o = 16; o > 0; o >>= 1) s2 += __shfl_xor_sync(0xffffffffu, s2, o);
    if ((t & 31) == 0) red[4 + (t >> 5)] = s2;
    __syncthreads();
    float var = (red[4] + red[5] + red[6] + red[7]) * (1.0f / DM);
    float inv = rsqrtf(var + 1e-5f);
    float4 g0 = *reinterpret_cast<const float4*>(g + c0);
    float4 g1 = *reinterpret_cast<const float4*>(g + c0 + 4);
    float4 b0 = *reinterpret_cast<const float4*>(bb + c0);
    float4 b1 = *reinterpret_cast<const float4*>(bb + c0 + 4);
    float gg[8] = {g0.x, g0.y, g0.z, g0.w, g1.x, g1.y, g1.z, g1.w};
    float bbv[8] = {b0.x, b0.y, b0.z, b0.w, b1.x, b1.y, b1.z, b1.w};
    float y[8];
    float am = 0.0f;
#pragma unroll
    for (int i = 0; i < 8; i++) {
        y[i] = (v[i] - mean) * inv * gg[i] + bbv[i];
        am = fmaxf(am, fabsf(y[i]));
    }
    *reinterpret_cast<float4*>(out + base + c0) =
        make_float4(y[0], y[1], y[2], y[3]);
    *reinterpret_cast<float4*>(out + base + c0 + 4) =
        make_float4(y[4], y[5], y[6], y[7]);
    if (q1) {
#pragma unroll
        for (int o = 16; o > 0; o >>= 1) am = fmaxf(am, __shfl_xor_sync(0xffffffffu, am, o));
        if ((t & 31) == 0) redm[t >> 5] = am;
        __syncthreads();
        am = fmaxf(fmaxf(redm[0], redm[1]), fmaxf(redm[2], redm[3]));
        float qs = am > 0 ? 127.0f / am : 0.0f;
        uint2 w1, w2;
        quant8(y, qs, w1, w2);
        *(uint2*)(q1 + base + c0) = w1;
        *(uint2*)(q2 + base + c0) = w2;
        if (t == 0) sOut[blockIdx.x] = am * (1.0f / 127.0f);
    }
}

// ---------------- fused double-LN at layer boundary ---------------------------
__global__ void __launch_bounds__(128)
ln2_k(const float* __restrict__ z, const float* __restrict__ hprev,
      float* __restrict__ hout, float* __restrict__ fxout,
      int8_t* __restrict__ q1, int8_t* __restrict__ q2,
      float* __restrict__ sOut,
      const float* __restrict__ g1v, const float* __restrict__ b1v,
      const float* __restrict__ g2v, const float* __restrict__ b2v) {
    __shared__ float red[8];
    __shared__ float redm[4];
    size_t base = (size_t)blockIdx.x * DM;
    int t = threadIdx.x;
    int c0 = t * 8;
    float v[8];
    {
        float4 i0 = *reinterpret_cast<const float4*>(z + base + c0);
        float4 i1 = *reinterpret_cast<const float4*>(z + base + c0 + 4);
        float4 a0 = *reinterpret_cast<const float4*>(hprev + base + c0);
        float4 a1 = *reinterpret_cast<const float4*>(hprev + base + c0 + 4);
        v[0] = i0.x + a0.x; v[1] = i0.y + a0.y; v[2] = i0.z + a0.z; v[3] = i0.w + a0.w;
        v[4] = i1.x + a1.x; v[5] = i1.y + a1.y; v[6] = i1.z + a1.z; v[7] = i1.w + a1.w;
    }
    float s = 0.0f;
#pragma unroll
    for (int i = 0; i < 8; i++) s += v[i];
#pragma unroll
    for (int o = 16; o > 0; o >>= 1) s += __shfl_xor_sync(0xffffffffu, s, o);
    if ((t & 31) == 0) red[t >> 5] = s;
    __syncthreads();
    float mean = (red[0] + red[1] + red[2] + red[3]) * (1.0f / DM);
    float s2 = 0.0f;
#pragma unroll
    for (int i = 0; i < 8; i++) { float d = v[i] - mean; s2 += d * d; }
#pragma unroll
    for (int o = 16; o > 0; o >>= 1) s2 += __shfl_xor_sync(0xffffffffu, s2, o);
    if ((t & 31) == 0) red[4 + (t >> 5)] = s2;
    __syncthreads();
    float var = (red[4] + red[5] + red[6] + red[7]) * (1.0f / DM);
    float inv = rsqrtf(var + 1e-5f);
    float y1[8];
    {
        float4 g0 = *reinterpret_cast<const float4*>(g1v + c0);
        float4 g1 = *reinterpret_cast<const float4*>(g1v + c0 + 4);
        float4 b0 = *reinterpret_cast<const float4*>(b1v + c0);
        float4 b1 = *reinterpret_cast<const float4*>(b1v + c0 + 4);
        float gg[8] = {g0.x, g0.y, g0.z, g0.w, g1.x, g1.y, g1.z, g1.w};
        float bb[8] = {b0.x, b0.y, b0.z, b0.w, b1.x, b1.y, b1.z, b1.w};
#pragma unroll
        for (int i = 0; i < 8; i++)
            y1[i] = (v[i] - mean) * inv * gg[i] + bb[i];
    }
    *reinterpret_cast<float4*>(hout + base + c0) =
        make_float4(y1[0], y1[1], y1[2], y1[3]);
    *reinterpret_cast<float4*>(hout + base + c0 + 4) =
        make_float4(y1[4], y1[5], y1[6], y1[7]);
    __syncthreads();
    s = 0.0f;
#pragma unroll
    for (int i = 0; i < 8; i++) s += y1[i];
#pragma unroll
    for (int o = 16; o > 0; o >>= 1) s += __shfl_xor_sync(0xffffffffu, s, o);
    if ((t & 31) == 0) red[t >> 5] = s;
    __syncthreads();
    mean = (red[0] + red[1] + red[2] + red[3]) * (1.0f / DM);
    s2 = 0.0f;
#pragma unroll
    for (int i = 0; i < 8; i++) { float d = y1[i] - mean; s2 += d * d; }
#pragma unroll
    for (int o = 16; o > 0; o >>= 1) s2 += __shfl_xor_sync(0xffffffffu, s2, o);
    if ((t & 31) == 0) red[4 + (t >> 5)] = s2;
    __syncthreads();
    var = (red[4] + red[5] + red[6] + red[7]) * (1.0f / DM);
    inv = rsqrtf(var + 1e-5f);
    float y2[8];
    float am = 0.0f;
    {
        float4 g0 = *reinterpret_cast<const float4*>(g2v + c0);
        float4 g1 = *reinterpret_cast<const float4*>(g2v + c0 + 4);
        float4 b0 = *reinterpret_cast<const float4*>(b2v + c0);
        float4 b1 = *reinterpret_cast<const float4*>(b2v + c0 + 4);
        float gg[8] = {g0.x, g0.y, g0.z, g0.w, g1.x, g1.y, g1.z, g1.w};
        float bb[8] = {b0.x, b0.y, b0.z, b0.w, b1.x, b1.y, b1.z, b1.w};
#pragma unroll
        for (int i = 0; i < 8; i++) {
            y2[i] = (y1[i] - mean) * inv * gg[i] + bb[i];
            am = fmaxf(am, fabsf(y2[i]));
        }
    }
    *reinterpret_cast<float4*>(fxout + base + c0) =
        make_float4(y2[0], y2[1], y2[2], y2[3]);
    *reinterpret_cast<float4*>(fxout + base + c0 + 4) =
        make_float4(y2[4], y2[5], y2[6], y2[7]);
#pragma unroll
    for (int o = 16; o > 0; o >>= 1) am = fmaxf(am, __shfl_xor_sync(0xffffffffu, am, o));
    if ((t & 31) == 0) redm[t >> 5] = am;
    __syncthreads();
    am = fmaxf(fmaxf(redm[0], redm[1]), fmaxf(redm[2], redm[3]));
    float qs = am > 0 ? 127.0f / am : 0.0f;
    uint2 w1, w2;
    quant8(y2, qs, w1, w2);
    *(uint2*)(q1 + base + c0) = w1;
    *(uint2*)(q2 + base + c0) = w2;
    if (t == 0) sOut[blockIdx.x] = am * (1.0f / 127.0f);
}

// ---------------- mean pool + decode -----------------------------------------
__global__ void pool_k(const float* __restrict__ h, float* __restrict__ pooled) {
    int idx = blockIdx.x * blockDim.x + threadIdx.x;
    if (idx >= BATCH * DM) return;
    int b = idx >> 10, d = idx & (DM - 1);
    const float* p = h + (size_t)b * SEQ * DM + d;
    float s = 0.0f;
#pragma unroll 8
    for (int l = 0; l < SEQ; l++) s += p[(size_t)l * DM];
    pooled[idx] = s * (1.0f / SEQ);
}

__global__ void dec_k(const float* __restrict__ pooled,
                      const float* __restrict__ w,
                      const float* __restrict__ b,
                      float* __restrict__ out) {
    __shared__ float red[8];
    int bi = blockIdx.x;
    int t = threadIdx.x;
    float s = 0.0f;
    for (int d = t; d < DM; d += 256) s += pooled[bi * DM + d] * w[d];
#pragma unroll
    for (int o = 16; o > 0; o >>= 1) s += __shfl_xor_sync(0xffffffffu, s, o);
    if ((t & 31) == 0) red[t >> 5] = s;
    __syncthreads();
    if (t == 0) {
        float tot = 0.0f;
#pragma unroll
        for (int i = 0; i < 8; i++) tot += red[i];
        out[bi] = tot + b[0];
    }
}

// ---------------- driver ----------------
extern "C" void kernel_launch(void* const* d_in, const int* in_sizes, int n_in,
                              void* d_out, int out_size) {
    const float* x        = (const float*)d_in[0];
    const float* enc_w    = (const float*)d_in[1];
    const float* enc_b    = (const float*)d_in[2];
    const float* ln1_g    = (const float*)d_in[3];
    const float* ln1_b    = (const float*)d_in[4];
    const float* lam_re   = (const float*)d_in[5];
    const float* lam_im   = (const float*)d_in[6];
    const float* b_re     = (const float*)d_in[7];
    const float* b_im     = (const float*)d_in[8];
    const float* c_re     = (const float*)d_in[9];
    const float* c_im     = (const float*)d_in[10];
    const float* d_skip   = (const float*)d_in[11];
    const float* log_step = (const float*)d_in[12];
    const float* ffn_g    = (const float*)d_in[13];
    const float* ffn_b    = (const float*)d_in[14];
    const float* ff_enc_w = (const float*)d_in[15];
    const float* ff_dec_w = (const float*)d_in[16];
    const float* norm_g   = (const float*)d_in[17];
    const float* norm_b   = (const float*)d_in[18];
    const float* dec_w    = (const float*)d_in[19];
    const float* dec_b    = (const float*)d_in[20];
    float* out = (float*)d_out;

    static int attr_done = 0;
    static cudaStream_t s_side = nullptr;
    static cudaEvent_t evFork, evSide, evMain, evW2;
    if (!attr_done) {
        cudaFuncSetAttribute((const void*)imma_gemm<0, true>,
                             cudaFuncAttributeMaxDynamicSharedMemorySize, SMEM_GEMM);
        cudaFuncSetAttribute((const void*)imma_gemm<2, false>,
                             cudaFuncAttributeMaxDynamicSharedMemorySize, SMEM_GEMM);
        cudaFuncSetAttribute((const void*)imma_gemm<3, false>,
                             cudaFuncAttributeMaxDynamicSharedMemorySize, SMEM_GEMM);
        cudaFuncSetAttribute((const void*)imma_gemm<4, false>,
                             cudaFuncAttributeMaxDynamicSharedMemorySize, SMEM_GEMM);
        cudaStreamCreateWithFlags(&s_side, cudaStreamNonBlocking);
        cudaEventCreateWithFlags(&evFork, cudaEventDisableTiming);
        cudaEventCreateWithFlags(&evSide, cudaEventDisableTiming);
        cudaEventCreateWithFlags(&evMain, cudaEventDisableTiming);
        cudaEventCreateWithFlags(&evW2, cudaEventDisableTiming);
        attr_done = 1;
    }

    float *p_h, *p_fx, *p_fy, *p_z, *p_wtmp, *p_pooled;
    bf16 *p_big;
    int8_t *p_fxq1, *p_fxq2, *p_xsq1, *p_xsq2, *p_fyq1, *p_fyq2, *p_ggq1, *p_ggq2;
    int8_t *p_W2q1, *p_W2q2, *p_Cwq1, *p_Cwq2, *p_feq1, *p_feq2, *p_fdq1, *p_fdq2;
    float *p_sfx, *p_sxs, *p_sfy, *p_sgg, *p_sW2, *p_sCw, *p_sfe, *p_sfd;
    cudaGetSymbolAddress((void**)&p_h, g_h);
    cudaGetSymbolAddress((void**)&p_fx, g_fx);
    cudaGetSymbolAddress((void**)&p_fy, g_fy);
    cudaGetSymbolAddress((void**)&p_z, g_z);
    cudaGetSymbolAddress((void**)&p_big, g_big);
    cudaGetSymbolAddress((void**)&p_wtmp, g_wtmp);
    cudaGetSymbolAddress((void**)&p_pooled, g_pooled);
    cudaGetSymbolAddress((void**)&p_fxq1, g_fxq1);
    cudaGetSymbolAddress((void**)&p_fxq2, g_fxq2);
    cudaGetSymbolAddress((void**)&p_xsq1, g_xsq1);
    cudaGetSymbolAddress((void**)&p_xsq2, g_xsq2);
    cudaGetSymbolAddress((void**)&p_fyq1, g_fyq1);
    cudaGetSymbolAddress((void**)&p_fyq2, g_fyq2);
    cudaGetSymbolAddress((void**)&p_ggq1, g_ggq1);
    cudaGetSymbolAddress((void**)&p_ggq2, g_ggq2);
    cudaGetSymbolAddress((void**)&p_W2q1, g_W2q1);
    cudaGetSymbolAddress((void**)&p_W2q2, g_W2q2);
    cudaGetSymbolAddress((void**)&p_Cwq1, g_Cwq1);
    cudaGetSymbolAddress((void**)&p_Cwq2, g_Cwq2);
    cudaGetSymbolAddress((void**)&p_feq1, g_feq1);
    cudaGetSymbolAddress((void**)&p_feq2, g_feq2);
    cudaGetSymbolAddress((void**)&p_fdq1, g_fdq1);
    cudaGetSymbolAddress((void**)&p_fdq2, g_fdq2);
    cudaGetSymbolAddress((void**)&p_sfx, g_sfx);
    cudaGetSymbolAddress((void**)&p_sxs, g_sxs);
    cudaGetSymbolAddress((void**)&p_sfy, g_sfy);
    cudaGetSymbolAddress((void**)&p_sgg, g_sgg);
    cudaGetSymbolAddress((void**)&p_sW2, g_sW2);
    cudaGetSymbolAddress((void**)&p_sCw, g_sCw);
    cudaGetSymbolAddress((void**)&p_sfe, g_sfe);
    cudaGetSymbolAddress((void**)&p_sfd, g_sfd);

    const int M = MROWS;

    // #1: encoder h = x @ enc_w + enc_b  (fp32, K=64)
    sgemm_enc<<<dim3(DM / TBN, M / TBM), 256>>>(x, enc_w, p_h, M, DM, D_IN, enc_b);
    // #2: layer-0 W2 quant + inline lamb/chs
    prep_W2q_k<<<DM, 256>>>(b_re, b_im, lam_re, lam_im, log_step);
    // #3: layer-0 fx = LN(h) + quant
    ln_k<<<M, 128>>>(p_h, nullptr, p_fx, p_fxq1, p_fxq2, p_sfx, ln1_g, ln1_b);

    for (int i = 0; i < NL; i++) {
        const size_t w1 = (size_t)i * DM;
        const size_t w2 = (size_t)i * DM * DM;
        const size_t w3 = (size_t)i * DM * DM2;

        if (i > 0) cudaStreamWaitEvent(0, evW2, 0);   // W2q(i) ready
        // #4 (i=0): Bu = fx @ W2^T  [M, 2P] bf16 out  <-- ncu-captured launch
        imma_gemm<0, true><<<dim3(DM2 / 64, M / 64), 128, SMEM_GEMM>>>(
            p_fxq1, p_fxq2, p_W2q1, p_W2q2, p_big, DM2, DM,
            p_sfx, p_sW2, nullptr, nullptr);

        // fork side stream: independent weight prep under the GEMM/scan shadow
        cudaEventRecord(evFork, 0);
        cudaStreamWaitEvent(s_side, evFork, 0);
        prep_Cwq_k<<<DM, 256, 0, s_side>>>(c_re + w2, c_im + w2);
        wtrans_k<<<dim3(DM2 / 32, DM / 32), dim3(32, 32), 0, s_side>>>(
            ff_enc_w + w3, p_wtmp, DM, DM2, DM);
        rowq_w_k<<<DM2, 256, 0, s_side>>>(p_wtmp, p_feq1, p_feq2, p_sfe);
        wtrans_k<<<dim3(DM / 32, DM / 32), dim3(32, 32), 0, s_side>>>(
            ff_dec_w + w2, p_wtmp + (size_t)DM2 * DM / 2, DM, DM, 0);
        rowq_w_k<<<DM, 256, 0, s_side>>>(p_wtmp + (size_t)DM2 * DM / 2,
                                         p_fdq1, p_fdq2, p_sfd);
        cudaEventRecord(evSide, s_side);

        // main: scan + xs quant
        scan_k<<<(BATCH * DM) / 128, 128>>>((bf162*)p_big);
        rowq_xs_k<<<M, 256>>>(p_big, p_xsq1, p_xsq2, p_sxs);
        cudaEventRecord(evMain, 0);   // g_lamb/chsi readers of layer i done

        // side: next layer's W2 prep (overwrites g_lamb/chs/chsi)
        if (i + 1 < NL) {
            const size_t nw1 = (size_t)(i + 1) * DM;
            const size_t nw2 = (size_t)(i + 1) * DM * DM;
            cudaStreamWaitEvent(s_side, evMain, 0);
            prep_W2q_k<<<DM, 256, 0, s_side>>>(
                b_re + nw2, b_im + nw2,
                lam_re + nw1, lam_im + nw1, log_step + nw1);
            cudaEventRecord(evW2, s_side);
        }

        // join: Cw/ffenc/ffdec weights ready
        cudaStreamWaitEvent(0, evSide, 0);
        // z = gelu(xs @ Cw^T + d*fx) + fx
        imma_gemm<2, false><<<dim3(DM / 64, M / 64), 128, SMEM_GEMM>>>(
            p_xsq1, p_xsq2, p_Cwq1, p_Cwq2, p_z, DM, DM2,
            p_sxs, p_sCw, p_fx, d_skip + w1);
        // fy = LN(z) + quant
        ln_k<<<M, 128>>>(p_z, nullptr, p_fy, p_fyq1, p_fyq2, p_sfy,
                         ffn_g + w1, ffn_b + w1);
        // gg = geglu(fy @ ff_enc)  fused epilogue -> bf16 [M, DM] in p_big
        imma_gemm<4, false><<<dim3(DM2 / 64, M / 64), 128, SMEM_GEMM>>>(
            p_fyq1, p_fyq2, p_feq1, p_feq2, p_big, DM2, DM,
            p_sfy, p_sfe, nullptr, nullptr);
        // quantize gg rows
        rowq_gg_k<<<M, 128>>>(p_big, p_ggq1, p_ggq2, p_sgg);
        // z2 = gg @ ff_dec + fy   (into p_z)
        imma_gemm<3, false><<<dim3(DM / 64, M / 64), 128, SMEM_GEMM>>>(
            p_ggq1, p_ggq2, p_fdq1, p_fdq2, p_z, DM, DM,
            p_sgg, p_sfd, p_fy, nullptr);

        if (i + 1 < NL) {
            const size_t nw1 = (size_t)(i + 1) * DM;
            // fused: h = LN(z2+h, norm_i);  fx = LN(h, ln1_{i+1}) + quant
            ln2_k<<<M, 128>>>(p_z, p_h, p_h, p_fx, p_fxq1, p_fxq2, p_sfx,
                              norm_g + w1, norm_b + w1, ln1_g + nw1, ln1_b + nw1);
        } else {
            ln_k<<<M, 128>>>(p_z, p_h, p_h, nullptr, nullptr, nullptr,
                             norm_g + w1, norm_b + w1);
        }
    }

    pool_k<<<(BATCH * DM) / 128, 128>>>(p_h, p_pooled);
    dec_k<<<BATCH, 256>>>(p_pooled, dec_w, dec_b, out);
}